// round 2
// baseline (speedup 1.0000x reference)
#include <cuda_runtime.h>

#define Bb 16
#define Ss 384
#define Dd 768
#define Hh 12
#define FFf 3072
#define DHd 64
#define MM (Bb*Ss)          // 6144
#define RROWS (2*Ss-1)      // 767

// ---------------- scratch (static device allocations) ----------------
__device__ float g_q [MM*Dd];
__device__ float g_k [MM*Dd];
__device__ float g_v [MM*Dd];
__device__ float g_r [RROWS*Dd];
__device__ float g_sc[(size_t)Bb*Hh*Ss*Ss];     // 28,311,552 floats
__device__ float g_attn[MM*Dd];
__device__ float g_o [MM*Dd];
__device__ float g_x1[MM*Dd];
__device__ float g_ff[(size_t)MM*FFf];
__device__ float g_f2[MM*Dd];

// ---------------- generic SGEMM: C = A(MxK) * B(KxN)  (+bias, +relu) --------
// EPI: 0 = none, 1 = bias+relu, 2 = bias
template<int EPI>
__global__ void sgemm_kernel(const float* __restrict__ A,
                             const float* __restrict__ Bm,
                             const float* __restrict__ bias,
                             float* __restrict__ C,
                             int M, int N, int K)
{
    const int BM = 128, BN = 128, BK = 8, TM = 8, TN = 8;
    __shared__ float As[BK][BM];
    __shared__ float Bs[BK][BN];

    int tid  = threadIdx.x;           // 256 threads
    int bcol = blockIdx.x, brow = blockIdx.y;
    int tx = tid & 15, ty = tid >> 4;

    int aRow = tid >> 1;              // 0..127
    int aCol = (tid & 1) * 4;         // 0 or 4
    int bRow = tid >> 5;              // 0..7
    int bCol = (tid & 31) * 4;        // 0..124

    int gARow = brow * BM + aRow;
    const float* Brow0 = Bm + (size_t)bcol * BN + bCol;

    float acc[TM][TN];
    #pragma unroll
    for (int i = 0; i < TM; i++)
        #pragma unroll
        for (int j = 0; j < TN; j++) acc[i][j] = 0.f;

    for (int k0 = 0; k0 < K; k0 += BK) {
        float4 av = make_float4(0.f, 0.f, 0.f, 0.f);
        if (gARow < M)
            av = *(const float4*)(A + (size_t)gARow * K + k0 + aCol);
        As[aCol + 0][aRow] = av.x;
        As[aCol + 1][aRow] = av.y;
        As[aCol + 2][aRow] = av.z;
        As[aCol + 3][aRow] = av.w;

        float4 bv = *(const float4*)(Brow0 + (size_t)(k0 + bRow) * N);
        *(float4*)(&Bs[bRow][bCol]) = bv;
        __syncthreads();

        #pragma unroll
        for (int k = 0; k < BK; k++) {
            float ra[TM], rb[TN];
            *(float4*)(&ra[0]) = *(const float4*)(&As[k][ty * TM]);
            *(float4*)(&ra[4]) = *(const float4*)(&As[k][ty * TM + 4]);
            *(float4*)(&rb[0]) = *(const float4*)(&Bs[k][tx * TN]);
            *(float4*)(&rb[4]) = *(const float4*)(&Bs[k][tx * TN + 4]);
            #pragma unroll
            for (int i = 0; i < TM; i++)
                #pragma unroll
                for (int j = 0; j < TN; j++)
                    acc[i][j] += ra[i] * rb[j];
        }
        __syncthreads();
    }

    #pragma unroll
    for (int i = 0; i < TM; i++) {
        int row = brow * BM + ty * TM + i;
        if (row >= M) continue;
        #pragma unroll
        for (int j = 0; j < TN; j += 4) {
            int col = bcol * BN + tx * TN + j;
            float4 o;
            o.x = acc[i][j + 0]; o.y = acc[i][j + 1];
            o.z = acc[i][j + 2]; o.w = acc[i][j + 3];
            if (EPI >= 1) {
                o.x += bias[col + 0]; o.y += bias[col + 1];
                o.z += bias[col + 2]; o.w += bias[col + 3];
            }
            if (EPI == 1) {
                o.x = fmaxf(o.x, 0.f); o.y = fmaxf(o.y, 0.f);
                o.z = fmaxf(o.z, 0.f); o.w = fmaxf(o.w, 0.f);
            }
            *(float4*)(C + (size_t)row * N + col) = o;
        }
    }
}

// ---------------- relative attention scores ----------------
// scores[b,h,i,j] = ((q_i + u_h)·k_j + (q_i + v_h)·r_{i-j+S-1}) / 8
__global__ void scores_kernel(const float* __restrict__ q,
                              const float* __restrict__ k,
                              const float* __restrict__ r,
                              const float* __restrict__ u,
                              const float* __restrict__ v,
                              float* __restrict__ sc)
{
    int j0 = blockIdx.x * 32;
    int i0 = blockIdx.y * 32;
    int bh = blockIdx.z;
    int b  = bh / Hh, h = bh % Hh;

    __shared__ float qs[32][65];
    __shared__ float ks[32][65];
    __shared__ float rs[63][65];
    __shared__ float us[64], vs[64];

    int tx = threadIdx.x, ty = threadIdx.y;
    int tid = ty * 32 + tx;

    if (tid < 64)       us[tid]      = u[h * 64 + tid];
    else if (tid < 128) vs[tid - 64] = v[h * 64 + (tid - 64)];

    const float* qb = q + ((size_t)b * Ss + i0) * Dd + h * 64;
    qs[ty][tx]      = qb[(size_t)ty * Dd + tx];
    qs[ty][tx + 32] = qb[(size_t)ty * Dd + tx + 32];

    const float* kb = k + ((size_t)b * Ss + j0) * Dd + h * 64;
    ks[ty][tx]      = kb[(size_t)ty * Dd + tx];
    ks[ty][tx + 32] = kb[(size_t)ty * Dd + tx + 32];

    int base = i0 - j0 + Ss - 32;      // first r-row of the 63-row band
    for (int rr = ty; rr < 63; rr += 32) {
        const float* rb = r + (size_t)(base + rr) * Dd + h * 64;
        rs[rr][tx]      = rb[tx];
        rs[rr][tx + 32] = rb[tx + 32];
    }
    __syncthreads();

    float acc = 0.f;
    int rrow = ty - tx + 31;
    #pragma unroll 16
    for (int d = 0; d < 64; d++) {
        float qd = qs[ty][d];
        acc += (qd + us[d]) * ks[tx][d];
        acc += (qd + vs[d]) * rs[rrow][d];
    }
    sc[(((size_t)bh) * Ss + i0 + ty) * Ss + j0 + tx] = acc * 0.125f;
}

// ---------------- softmax over last dim (rows of length 384) -------------
__global__ void softmax_kernel(float* __restrict__ sc)
{
    size_t row = blockIdx.x;
    float* p = sc + row * Ss;
    int t = threadIdx.x;                       // 128 threads

    float v0 = p[t], v1 = p[t + 128], v2 = p[t + 256];
    float m = fmaxf(v0, fmaxf(v1, v2));
    #pragma unroll
    for (int o = 16; o > 0; o >>= 1) m = fmaxf(m, __shfl_xor_sync(~0u, m, o));
    __shared__ float sm[4], ssum[4];
    if ((t & 31) == 0) sm[t >> 5] = m;
    __syncthreads();
    m = fmaxf(fmaxf(sm[0], sm[1]), fmaxf(sm[2], sm[3]));

    float e0 = __expf(v0 - m), e1 = __expf(v1 - m), e2 = __expf(v2 - m);
    float s = e0 + e1 + e2;
    #pragma unroll
    for (int o = 16; o > 0; o >>= 1) s += __shfl_xor_sync(~0u, s, o);
    if ((t & 31) == 0) ssum[t >> 5] = s;
    __syncthreads();
    s = ssum[0] + ssum[1] + ssum[2] + ssum[3];
    float inv = 1.0f / s;
    p[t] = e0 * inv; p[t + 128] = e1 * inv; p[t + 256] = e2 * inv;
}

// ---------------- attn = p @ val  (per b,h) -> (B,S,D) layout -------------
__global__ void attnv_kernel(const float* __restrict__ p,
                             const float* __restrict__ val,
                             float* __restrict__ out)
{
    int i0 = blockIdx.x * 32;
    int h  = blockIdx.y;
    int b  = blockIdx.z;

    __shared__ float ps[32][33];
    __shared__ float vs[32][64];

    int tx = threadIdx.x, ty = threadIdx.y;    // (64,4)
    int tid = ty * 64 + tx;

    float acc[8];
    #pragma unroll
    for (int r2 = 0; r2 < 8; r2++) acc[r2] = 0.f;

    const float* prow = p + (((size_t)b * Hh + h) * Ss + i0) * Ss;

    for (int j0 = 0; j0 < Ss; j0 += 32) {
        #pragma unroll
        for (int l = 0; l < 4; l++) {
            int idx = tid + l * 256;
            int ii = idx >> 5, jj = idx & 31;
            ps[ii][jj] = prow[(size_t)ii * Ss + j0 + jj];
        }
        #pragma unroll
        for (int l = 0; l < 8; l++) {
            int idx = tid + l * 256;
            int rr = idx >> 6, cc = idx & 63;
            vs[rr][cc] = val[((size_t)b * Ss + j0 + rr) * Dd + h * 64 + cc];
        }
        __syncthreads();
        #pragma unroll
        for (int jj = 0; jj < 32; jj++) {
            float vv = vs[jj][tx];
            #pragma unroll
            for (int r2 = 0; r2 < 8; r2++)
                acc[r2] += ps[ty + 4 * r2][jj] * vv;
        }
        __syncthreads();
    }
    #pragma unroll
    for (int r2 = 0; r2 < 8; r2++) {
        int i = i0 + ty + 4 * r2;
        out[((size_t)b * Ss + i) * Dd + h * 64 + tx] = acc[r2];
    }
}

// ---------------- out = LayerNorm(a + b) ----------------
__global__ void add_ln_kernel(const float* __restrict__ a,
                              const float* __restrict__ bsrc,
                              const float* __restrict__ g,
                              const float* __restrict__ be,
                              float* __restrict__ out)
{
    size_t row = blockIdx.x;
    const float* pa = a + row * Dd;
    const float* pb = bsrc + row * Dd;
    int t = threadIdx.x;                       // 256 threads

    float x0 = pa[t] + pb[t];
    float x1 = pa[t + 256] + pb[t + 256];
    float x2 = pa[t + 512] + pb[t + 512];

    float s  = x0 + x1 + x2;
    float s2 = x0 * x0 + x1 * x1 + x2 * x2;
    #pragma unroll
    for (int o = 16; o > 0; o >>= 1) {
        s  += __shfl_xor_sync(~0u, s, o);
        s2 += __shfl_xor_sync(~0u, s2, o);
    }
    __shared__ float r1[8], r2s[8];
    if ((t & 31) == 0) { r1[t >> 5] = s; r2s[t >> 5] = s2; }
    __syncthreads();
    if (t < 32) {
        float a1 = (t < 8) ? r1[t] : 0.f;
        float a2 = (t < 8) ? r2s[t] : 0.f;
        #pragma unroll
        for (int o = 4; o > 0; o >>= 1) {
            a1 += __shfl_xor_sync(~0u, a1, o);
            a2 += __shfl_xor_sync(~0u, a2, o);
        }
        if (t == 0) { r1[0] = a1; r2s[0] = a2; }
    }
    __syncthreads();
    float mean = r1[0] * (1.f / 768.f);
    float var  = r2s[0] * (1.f / 768.f) - mean * mean;
    float inv  = rsqrtf(var + 1e-5f);

    float* po = out + row * Dd;
    po[t]       = (x0 - mean) * inv * g[t]       + be[t];
    po[t + 256] = (x1 - mean) * inv * g[t + 256] + be[t + 256];
    po[t + 512] = (x2 - mean) * inv * g[t + 512] + be[t + 512];
}

// ---------------- launch ----------------
extern "C" void kernel_launch(void* const* d_in, const int* in_sizes, int n_in,
                              void* d_out, int out_size)
{
    const float* x    = (const float*)d_in[0];
    const float* pe   = (const float*)d_in[1];
    const float* Wq   = (const float*)d_in[2];
    const float* Wk   = (const float*)d_in[3];
    const float* Wv   = (const float*)d_in[4];
    const float* Wr   = (const float*)d_in[5];
    const float* u    = (const float*)d_in[6];
    const float* v    = (const float*)d_in[7];
    const float* Wo   = (const float*)d_in[8];
    const float* ln1g = (const float*)d_in[9];
    const float* ln1b = (const float*)d_in[10];
    const float* ln2g = (const float*)d_in[11];
    const float* ln2b = (const float*)d_in[12];
    const float* W1   = (const float*)d_in[13];
    const float* b1   = (const float*)d_in[14];
    const float* W2   = (const float*)d_in[15];
    const float* b2   = (const float*)d_in[16];
    float* out = (float*)d_out;

    float *gq, *gk, *gv, *gr, *gsc, *gattn, *go, *gx1, *gff, *gf2;
    cudaGetSymbolAddress((void**)&gq,   g_q);
    cudaGetSymbolAddress((void**)&gk,   g_k);
    cudaGetSymbolAddress((void**)&gv,   g_v);
    cudaGetSymbolAddress((void**)&gr,   g_r);
    cudaGetSymbolAddress((void**)&gsc,  g_sc);
    cudaGetSymbolAddress((void**)&gattn,g_attn);
    cudaGetSymbolAddress((void**)&go,   g_o);
    cudaGetSymbolAddress((void**)&gx1,  g_x1);
    cudaGetSymbolAddress((void**)&gff,  g_ff);
    cudaGetSymbolAddress((void**)&gf2,  g_f2);

    dim3 gProj(Dd / 128, MM / 128);                    // (6, 48)
    sgemm_kernel<0><<<gProj, 256>>>(x, Wq, nullptr, gq, MM, Dd, Dd);
    sgemm_kernel<0><<<gProj, 256>>>(x, Wk, nullptr, gk, MM, Dd, Dd);
    sgemm_kernel<0><<<gProj, 256>>>(x, Wv, nullptr, gv, MM, Dd, Dd);

    dim3 gR(Dd / 128, (RROWS + 127) / 128);            // (6, 6)
    sgemm_kernel<0><<<gR, 256>>>(pe, Wr, nullptr, gr, RROWS, Dd, Dd);

    dim3 gScores(Ss / 32, Ss / 32, Bb * Hh);           // (12, 12, 192)
    scores_kernel<<<gScores, dim3(32, 32)>>>(gq, gk, gr, u, v, gsc);

    softmax_kernel<<<Bb * Hh * Ss, 128>>>(gsc);

    dim3 gAV(Ss / 32, Hh, Bb);                         // (12, 12, 16)
    attnv_kernel<<<gAV, dim3(64, 4)>>>(gsc, gv, gattn);

    sgemm_kernel<0><<<gProj, 256>>>(gattn, Wo, nullptr, go, MM, Dd, Dd);

    add_ln_kernel<<<MM, 256>>>(x, go, ln1g, ln1b, gx1);

    dim3 gF1(FFf / 128, MM / 128);                     // (24, 48)
    sgemm_kernel<1><<<gF1, 256>>>(gx1, W1, b1, gff, MM, FFf, Dd);

    sgemm_kernel<2><<<gProj, 256>>>(gff, W2, b2, gf2, MM, Dd, FFf);

    add_ln_kernel<<<MM, 256>>>(gx1, gf2, ln2g, ln2b, out);

    (void)in_sizes; (void)n_in; (void)out_size;
}

// round 6
// speedup vs baseline: 1.6688x; 1.6688x over previous
#include <cuda_runtime.h>
#include <cuda_bf16.h>
#include <cstdint>

#define Bb 16
#define Ss 384
#define Dd 768
#define Hh 12
#define FFf 3072
#define MM (Bb*Ss)          // 6144
#define RROWS (2*Ss-1)      // 767
#define K3D (3*Dd)          // 2304
#define K3F (3*FFf)         // 9216

// ---------------- scratch (static device allocations) ----------------
__device__ float g_q [MM*Dd];
__device__ float g_k [MM*Dd];
__device__ float g_v [MM*Dd];
__device__ float g_r [RROWS*Dd];
__device__ float g_sc[(size_t)Bb*Hh*Ss*Ss];
__device__ float g_o [MM*Dd];
__device__ float g_x1[MM*Dd];
__device__ float g_f2[MM*Dd];

__device__ __nv_bfloat16 g_xs  [(size_t)MM*K3D];
__device__ __nv_bfloat16 g_pes [(size_t)768*K3D];   // 767 real rows + 1 zero pad
__device__ __nv_bfloat16 g_attns[(size_t)MM*K3D];
__device__ __nv_bfloat16 g_x1s [(size_t)MM*K3D];
__device__ __nv_bfloat16 g_ffs [(size_t)MM*K3F];
__device__ __nv_bfloat16 g_wqs [(size_t)768*K3D];
__device__ __nv_bfloat16 g_wks [(size_t)768*K3D];
__device__ __nv_bfloat16 g_wvs [(size_t)768*K3D];
__device__ __nv_bfloat16 g_wos [(size_t)768*K3D];
__device__ __nv_bfloat16 g_wrs [(size_t)768*K3D];
__device__ __nv_bfloat16 g_w1s [(size_t)FFf*K3D];
__device__ __nv_bfloat16 g_w2s [(size_t)768*K3F];

// ---------------- PTX helpers (portable: sm_80-class only) ----------------
__device__ __forceinline__ uint32_t smem_u32(const void* p) {
    return (uint32_t)__cvta_generic_to_shared(p);
}
__device__ __forceinline__ void cp16(uint32_t dst, const void* src) {
    asm volatile("cp.async.cg.shared.global [%0], [%1], 16;\n"
                 :: "r"(dst), "l"(__cvta_generic_to_global(src)));
}
__device__ __forceinline__ void cp_commit() { asm volatile("cp.async.commit_group;\n" ::: "memory"); }
__device__ __forceinline__ void cp_wait1()  { asm volatile("cp.async.wait_group 1;\n" ::: "memory"); }
__device__ __forceinline__ void cp_wait0()  { asm volatile("cp.async.wait_group 0;\n" ::: "memory"); }

__device__ __forceinline__ void ldmA(uint32_t* a, uint32_t addr) {
    asm volatile("ldmatrix.sync.aligned.m8n8.x4.shared.b16 {%0,%1,%2,%3}, [%4];"
                 : "=r"(a[0]), "=r"(a[1]), "=r"(a[2]), "=r"(a[3]) : "r"(addr));
}
__device__ __forceinline__ void ldmB(uint32_t* b, uint32_t addr) {
    asm volatile("ldmatrix.sync.aligned.m8n8.x2.shared.b16 {%0,%1}, [%2];"
                 : "=r"(b[0]), "=r"(b[1]) : "r"(addr));
}
__device__ __forceinline__ void mma16816(float* d, const uint32_t* a, const uint32_t* b) {
    asm volatile("mma.sync.aligned.m16n8k16.row.col.f32.bf16.bf16.f32 "
                 "{%0,%1,%2,%3}, {%4,%5,%6,%7}, {%8,%9}, {%0,%1,%2,%3};"
                 : "+f"(d[0]), "+f"(d[1]), "+f"(d[2]), "+f"(d[3])
                 : "r"(a[0]), "r"(a[1]), "r"(a[2]), "r"(a[3]), "r"(b[0]), "r"(b[1]));
}

#define SMEM_SZ 98304     // 3 stages x 32KB; epilogue tile 128x132 fp32 = 67584 fits

// ---------------- HMMA GEMM: C(M,N) = A'(M,K3) * Bt'(N,K3)^T ----------------
// EPI 0: fp32 C    EPI 1: bias+relu -> split bf16 Cs (row stride 3N)    EPI 2: bias -> fp32 C
template<int EPI>
__global__ void __launch_bounds__(256)
hmma_gemm(const __nv_bfloat16* __restrict__ A,
          const __nv_bfloat16* __restrict__ Bt,
          const float* __restrict__ bias,
          float* __restrict__ C,
          __nv_bfloat16* __restrict__ Cs,
          int Mreal, int N, int K3)
{
    extern __shared__ __align__(1024) char smem[];
    uint32_t sb = smem_u32(smem);
    int tid = threadIdx.x;
    int wid = tid >> 5, lane = tid & 31;
    int n0 = blockIdx.x * 128, m0 = blockIdx.y * 128;
    int NC = K3 >> 6;
    int wm = (wid >> 2) * 64;    // warp row offset
    int wn = (wid & 3) * 32;     // warp col offset

    float acc[4][4][4];
    #pragma unroll
    for (int mt = 0; mt < 4; mt++)
        #pragma unroll
        for (int nt = 0; nt < 4; nt++)
            #pragma unroll
            for (int q = 0; q < 4; q++) acc[mt][nt][q] = 0.f;

    const int lr = tid >> 3;          // 0..31
    const int lc = tid & 7;           // 16B chunk 0..7
    auto load_stage = [&](int st, int cc) {
        uint32_t sa = sb + st * 32768;
        const __nv_bfloat16* pa = A  + (size_t)(m0 + lr) * K3 + cc * 64 + lc * 8;
        const __nv_bfloat16* pb = Bt + (size_t)(n0 + lr) * K3 + cc * 64 + lc * 8;
        #pragma unroll
        for (int i = 0; i < 4; i++) {
            int row = lr + i * 32;
            uint32_t off = row * 128 + ((lc ^ (row & 7)) * 16);
            cp16(sa + off,         pa);
            cp16(sa + 16384 + off, pb);
            pa += (size_t)32 * K3;
            pb += (size_t)32 * K3;
        }
        cp_commit();
    };

    load_stage(0, 0);
    load_stage(1, 1);

    for (int cc = 0; cc < NC; cc++) {
        if (cc + 2 < NC) cp_wait1(); else cp_wait0();
        __syncthreads();
        if (cc + 2 < NC) load_stage((cc + 2) % 3, cc + 2);

        uint32_t sa  = sb + (cc % 3) * 32768;
        uint32_t sbb = sa + 16384;
        #pragma unroll
        for (int k16 = 0; k16 < 4; k16++) {
            uint32_t a[4][4], b[4][2];
            #pragma unroll
            for (int mt = 0; mt < 4; mt++) {
                int r  = wm + mt * 16 + (lane & 15);
                int kc = 2 * k16 + ((lane >> 4) & 1);
                ldmA(a[mt], sa + r * 128 + ((kc ^ (r & 7)) * 16));
            }
            #pragma unroll
            for (int nt = 0; nt < 4; nt++) {
                int r  = wn + nt * 8 + (lane & 7);
                int kc = 2 * k16 + ((lane >> 3) & 1);
                ldmB(b[nt], sbb + r * 128 + ((kc ^ (r & 7)) * 16));
            }
            #pragma unroll
            for (int mt = 0; mt < 4; mt++)
                #pragma unroll
                for (int nt = 0; nt < 4; nt++)
                    mma16816(acc[mt][nt], a[mt], b[nt]);
        }
    }
    __syncthreads();

    // stage accumulators through smem for coalesced global stores
    float* tile = (float*)smem;           // [128][132]
    #pragma unroll
    for (int mt = 0; mt < 4; mt++) {
        #pragma unroll
        for (int nt = 0; nt < 4; nt++) {
            int r0  = wm + mt * 16 + (lane >> 2);
            int col = wn + nt * 8 + (lane & 3) * 2;
            tile[r0 * 132 + col]           = acc[mt][nt][0];
            tile[r0 * 132 + col + 1]       = acc[mt][nt][1];
            tile[(r0 + 8) * 132 + col]     = acc[mt][nt][2];
            tile[(r0 + 8) * 132 + col + 1] = acc[mt][nt][3];
        }
    }
    __syncthreads();

    #pragma unroll
    for (int j = 0; j < 16; j++) {
        int idx = tid + j * 256;
        int rr = idx >> 5, c4 = idx & 31;
        float4 v = *(const float4*)(tile + rr * 132 + c4 * 4);
        int grow = m0 + rr;
        int gcol = n0 + c4 * 4;
        if (grow < Mreal) {
            if (EPI >= 1) {
                v.x += bias[gcol]; v.y += bias[gcol + 1];
                v.z += bias[gcol + 2]; v.w += bias[gcol + 3];
            }
            if (EPI == 1) {
                v.x = fmaxf(v.x, 0.f); v.y = fmaxf(v.y, 0.f);
                v.z = fmaxf(v.z, 0.f); v.w = fmaxf(v.w, 0.f);
                // activation split for next GEMM's A side: [hi | lo | hi]
                size_t rb = (size_t)grow * (3 * N) + gcol;
                float f[4] = {v.x, v.y, v.z, v.w};
                __nv_bfloat16 hi[4], lo[4];
                #pragma unroll
                for (int q = 0; q < 4; q++) {
                    hi[q] = __float2bfloat16(f[q]);
                    lo[q] = __float2bfloat16(f[q] - __bfloat162float(hi[q]));
                }
                __nv_bfloat162* p0 = (__nv_bfloat162*)(Cs + rb);
                __nv_bfloat162* p1 = (__nv_bfloat162*)(Cs + rb + N);
                __nv_bfloat162* p2 = (__nv_bfloat162*)(Cs + rb + 2 * N);
                p0[0] = __nv_bfloat162(hi[0], hi[1]); p0[1] = __nv_bfloat162(hi[2], hi[3]);
                p1[0] = __nv_bfloat162(lo[0], lo[1]); p1[1] = __nv_bfloat162(lo[2], lo[3]);
                p2[0] = __nv_bfloat162(hi[0], hi[1]); p2[1] = __nv_bfloat162(hi[2], hi[3]);
            } else {
                *(float4*)(C + (size_t)grow * N + gcol) = v;
            }
        }
    }
}

// ---------------- conversion kernels ----------------
// A': chunks [0,K)=Ah, [K,2K)=Al, [2K,3K)=Ah   pairs with Bt' [Bh|Bh|Bl]
__global__ void split_rows(const float* __restrict__ in, __nv_bfloat16* __restrict__ out,
                           int Mreal, int K)
{
    size_t idx = (size_t)blockIdx.x * 256 + threadIdx.x;
    int rowi = (int)(idx / K);
    int k = (int)(idx % K);
    float vv = (rowi < Mreal) ? in[(size_t)rowi * K + k] : 0.f;
    __nv_bfloat16 hi = __float2bfloat16(vv);
    __nv_bfloat16 lo = __float2bfloat16(vv - __bfloat162float(hi));
    size_t b2 = (size_t)rowi * 3 * K;
    out[b2 + k] = hi;
    out[b2 + K + k] = lo;
    out[b2 + 2 * K + k] = hi;
}

__global__ void tsplit_w(const float* __restrict__ W, __nv_bfloat16* __restrict__ out,
                         int K, int N)
{
    __shared__ float t[32][33];
    int k0 = blockIdx.x * 32, n0 = blockIdx.y * 32;
    int tx = threadIdx.x, ty = threadIdx.y;   // (32, 8)
    for (int i = ty; i < 32; i += 8)
        t[i][tx] = W[(size_t)(k0 + i) * N + n0 + tx];
    __syncthreads();
    for (int i = ty; i < 32; i += 8) {
        float vv = t[tx][i];                  // W[k0+tx][n0+i]
        __nv_bfloat16 hi = __float2bfloat16(vv);
        __nv_bfloat16 lo = __float2bfloat16(vv - __bfloat162float(hi));
        size_t b2 = (size_t)(n0 + i) * 3 * K;
        out[b2 + k0 + tx] = hi;
        out[b2 + K + k0 + tx] = hi;
        out[b2 + 2 * K + k0 + tx] = lo;
    }
}

// ---------------- relative attention scores ----------------
__global__ void scores_kernel(const float* __restrict__ q,
                              const float* __restrict__ k,
                              const float* __restrict__ r,
                              const float* __restrict__ u,
                              const float* __restrict__ v,
                              float* __restrict__ sc)
{
    int j0 = blockIdx.x * 32;
    int i0 = blockIdx.y * 32;
    int bh = blockIdx.z;
    int b  = bh / Hh, h = bh % Hh;

    __shared__ float qs[32][65];
    __shared__ float ks[32][65];
    __shared__ float rs[63][65];
    __shared__ float us[64], vs[64];

    int tx = threadIdx.x, ty = threadIdx.y;
    int tid = ty * 32 + tx;

    if (tid < 64)       us[tid]      = u[h * 64 + tid];
    else if (tid < 128) vs[tid - 64] = v[h * 64 + (tid - 64)];

    const float* qb = q + ((size_t)b * Ss + i0) * Dd + h * 64;
    qs[ty][tx]      = qb[(size_t)ty * Dd + tx];
    qs[ty][tx + 32] = qb[(size_t)ty * Dd + tx + 32];

    const float* kb = k + ((size_t)b * Ss + j0) * Dd + h * 64;
    ks[ty][tx]      = kb[(size_t)ty * Dd + tx];
    ks[ty][tx + 32] = kb[(size_t)ty * Dd + tx + 32];

    int basei = i0 - j0 + Ss - 32;
    for (int rr = ty; rr < 63; rr += 32) {
        const float* rb = r + (size_t)(basei + rr) * Dd + h * 64;
        rs[rr][tx]      = rb[tx];
        rs[rr][tx + 32] = rb[tx + 32];
    }
    __syncthreads();

    float acc = 0.f;
    int rrow = ty - tx + 31;
    #pragma unroll 16
    for (int d = 0; d < 64; d++) {
        float qd = qs[ty][d];
        acc += (qd + us[d]) * ks[tx][d];
        acc += (qd + vs[d]) * rs[rrow][d];
    }
    sc[(((size_t)bh) * Ss + i0 + ty) * Ss + j0 + tx] = acc * 0.125f;
}

// ---------------- softmax ----------------
__global__ void softmax_kernel(float* __restrict__ sc)
{
    size_t rowi = blockIdx.x;
    float* p = sc + rowi * Ss;
    int t = threadIdx.x;

    float v0 = p[t], v1 = p[t + 128], v2 = p[t + 256];
    float m = fmaxf(v0, fmaxf(v1, v2));
    #pragma unroll
    for (int o = 16; o > 0; o >>= 1) m = fmaxf(m, __shfl_xor_sync(~0u, m, o));
    __shared__ float sm[4], ssum[4];
    if ((t & 31) == 0) sm[t >> 5] = m;
    __syncthreads();
    m = fmaxf(fmaxf(sm[0], sm[1]), fmaxf(sm[2], sm[3]));

    float e0 = __expf(v0 - m), e1 = __expf(v1 - m), e2 = __expf(v2 - m);
    float s = e0 + e1 + e2;
    #pragma unroll
    for (int o = 16; o > 0; o >>= 1) s += __shfl_xor_sync(~0u, s, o);
    if ((t & 31) == 0) ssum[t >> 5] = s;
    __syncthreads();
    s = ssum[0] + ssum[1] + ssum[2] + ssum[3];
    float inv = 1.0f / s;
    p[t] = e0 * inv; p[t + 128] = e1 * inv; p[t + 256] = e2 * inv;
}

// ---------------- attn = p @ val, epilogue writes split bf16 ----------------
__global__ void attnv_kernel(const float* __restrict__ p,
                             const float* __restrict__ val,
                             __nv_bfloat16* __restrict__ outs)
{
    int i0 = blockIdx.x * 32;
    int h  = blockIdx.y;
    int b  = blockIdx.z;

    __shared__ float ps[32][33];
    __shared__ float vs[32][64];

    int tx = threadIdx.x, ty = threadIdx.y;    // (64,4)
    int tid = ty * 64 + tx;

    float acc[8];
    #pragma unroll
    for (int r2 = 0; r2 < 8; r2++) acc[r2] = 0.f;

    const float* prow = p + (((size_t)b * Hh + h) * Ss + i0) * Ss;

    for (int j0 = 0; j0 < Ss; j0 += 32) {
        #pragma unroll
        for (int l = 0; l < 4; l++) {
            int idx = tid + l * 256;
            int ii = idx >> 5, jj = idx & 31;
            ps[ii][jj] = prow[(size_t)ii * Ss + j0 + jj];
        }
        #pragma unroll
        for (int l = 0; l < 8; l++) {
            int idx = tid + l * 256;
            int rr = idx >> 6, cc = idx & 63;
            vs[rr][cc] = val[((size_t)b * Ss + j0 + rr) * Dd + h * 64 + cc];
        }
        __syncthreads();
        #pragma unroll
        for (int jj = 0; jj < 32; jj++) {
            float vv = vs[jj][tx];
            #pragma unroll
            for (int r2 = 0; r2 < 8; r2++)
                acc[r2] += ps[ty + 4 * r2][jj] * vv;
        }
        __syncthreads();
    }
    #pragma unroll
    for (int r2 = 0; r2 < 8; r2++) {
        int i = i0 + ty + 4 * r2;
        float a = acc[r2];
        __nv_bfloat16 hi = __float2bfloat16(a);
        __nv_bfloat16 lo = __float2bfloat16(a - __bfloat162float(hi));
        size_t b2 = ((size_t)b * Ss + i) * K3D + h * 64 + tx;
        outs[b2]           = hi;
        outs[b2 + Dd]      = lo;
        outs[b2 + 2 * Dd]  = hi;
    }
}

// ---------------- out = LayerNorm(a + b), optional bf16 split ----------------
template<bool SPLIT>
__global__ void add_ln_kernel(const float* __restrict__ a,
                              const float* __restrict__ bsrc,
                              const float* __restrict__ g,
                              const float* __restrict__ be,
                              float* __restrict__ out,
                              __nv_bfloat16* __restrict__ outs)
{
    size_t rowi = blockIdx.x;
    const float* pa = a + rowi * Dd;
    const float* pb = bsrc + rowi * Dd;
    int t = threadIdx.x;

    float x0 = pa[t] + pb[t];
    float x1 = pa[t + 256] + pb[t + 256];
    float x2 = pa[t + 512] + pb[t + 512];

    float s  = x0 + x1 + x2;
    float s2 = x0 * x0 + x1 * x1 + x2 * x2;
    #pragma unroll
    for (int o = 16; o > 0; o >>= 1) {
        s  += __shfl_xor_sync(~0u, s, o);
        s2 += __shfl_xor_sync(~0u, s2, o);
    }
    __shared__ float r1[8], r2s[8];
    if ((t & 31) == 0) { r1[t >> 5] = s; r2s[t >> 5] = s2; }
    __syncthreads();
    if (t < 32) {
        float a1 = (t < 8) ? r1[t] : 0.f;
        float a2 = (t < 8) ? r2s[t] : 0.f;
        #pragma unroll
        for (int o = 4; o > 0; o >>= 1) {
            a1 += __shfl_xor_sync(~0u, a1, o);
            a2 += __shfl_xor_sync(~0u, a2, o);
        }
        if (t == 0) { r1[0] = a1; r2s[0] = a2; }
    }
    __syncthreads();
    float mean = r1[0] * (1.f / 768.f);
    float var  = r2s[0] * (1.f / 768.f) - mean * mean;
    float inv  = rsqrtf(var + 1e-5f);

    float y0 = (x0 - mean) * inv * g[t]       + be[t];
    float y1 = (x1 - mean) * inv * g[t + 256] + be[t + 256];
    float y2 = (x2 - mean) * inv * g[t + 512] + be[t + 512];

    float* po = out + rowi * Dd;
    po[t] = y0; po[t + 256] = y1; po[t + 512] = y2;

    if (SPLIT) {
        size_t b2 = rowi * K3D;
        float ys[3] = {y0, y1, y2};
        int   cs[3] = {t, t + 256, t + 512};
        #pragma unroll
        for (int q = 0; q < 3; q++) {
            __nv_bfloat16 hi = __float2bfloat16(ys[q]);
            __nv_bfloat16 lo = __float2bfloat16(ys[q] - __bfloat162float(hi));
            outs[b2 + cs[q]]          = hi;
            outs[b2 + Dd + cs[q]]     = lo;
            outs[b2 + 2 * Dd + cs[q]] = hi;
        }
    }
}

// ---------------- launch ----------------
extern "C" void kernel_launch(void* const* d_in, const int* in_sizes, int n_in,
                              void* d_out, int out_size)
{
    const float* x    = (const float*)d_in[0];
    const float* pe   = (const float*)d_in[1];
    const float* Wq   = (const float*)d_in[2];
    const float* Wk   = (const float*)d_in[3];
    const float* Wv   = (const float*)d_in[4];
    const float* Wr   = (const float*)d_in[5];
    const float* u    = (const float*)d_in[6];
    const float* v    = (const float*)d_in[7];
    const float* Wo   = (const float*)d_in[8];
    const float* ln1g = (const float*)d_in[9];
    const float* ln1b = (const float*)d_in[10];
    const float* ln2g = (const float*)d_in[11];
    const float* ln2b = (const float*)d_in[12];
    const float* W1   = (const float*)d_in[13];
    const float* b1   = (const float*)d_in[14];
    const float* W2   = (const float*)d_in[15];
    const float* b2   = (const float*)d_in[16];
    float* out = (float*)d_out;

    float *gq, *gk, *gv, *gr, *gsc, *go, *gx1, *gf2;
    __nv_bfloat16 *gxs, *gpes, *gattns, *gx1s, *gffs;
    __nv_bfloat16 *gwqs, *gwks, *gwvs, *gwos, *gwrs, *gw1s, *gw2s;
    cudaGetSymbolAddress((void**)&gq, g_q);     cudaGetSymbolAddress((void**)&gk, g_k);
    cudaGetSymbolAddress((void**)&gv, g_v);     cudaGetSymbolAddress((void**)&gr, g_r);
    cudaGetSymbolAddress((void**)&gsc, g_sc);   cudaGetSymbolAddress((void**)&go, g_o);
    cudaGetSymbolAddress((void**)&gx1, g_x1);   cudaGetSymbolAddress((void**)&gf2, g_f2);
    cudaGetSymbolAddress((void**)&gxs, g_xs);   cudaGetSymbolAddress((void**)&gpes, g_pes);
    cudaGetSymbolAddress((void**)&gattns, g_attns);
    cudaGetSymbolAddress((void**)&gx1s, g_x1s); cudaGetSymbolAddress((void**)&gffs, g_ffs);
    cudaGetSymbolAddress((void**)&gwqs, g_wqs); cudaGetSymbolAddress((void**)&gwks, g_wks);
    cudaGetSymbolAddress((void**)&gwvs, g_wvs); cudaGetSymbolAddress((void**)&gwos, g_wos);
    cudaGetSymbolAddress((void**)&gwrs, g_wrs);
    cudaGetSymbolAddress((void**)&gw1s, g_w1s); cudaGetSymbolAddress((void**)&gw2s, g_w2s);

    cudaFuncSetAttribute(hmma_gemm<0>, cudaFuncAttributeMaxDynamicSharedMemorySize, SMEM_SZ);
    cudaFuncSetAttribute(hmma_gemm<1>, cudaFuncAttributeMaxDynamicSharedMemorySize, SMEM_SZ);
    cudaFuncSetAttribute(hmma_gemm<2>, cudaFuncAttributeMaxDynamicSharedMemorySize, SMEM_SZ);

    // conversions
    split_rows<<<(MM * Dd) / 256, 256>>>(x, gxs, MM, Dd);
    split_rows<<<(768 * Dd) / 256, 256>>>(pe, gpes, RROWS, Dd);
    dim3 tb(32, 8);
    tsplit_w<<<dim3(24, 24), tb>>>(Wq, gwqs, Dd, Dd);
    tsplit_w<<<dim3(24, 24), tb>>>(Wk, gwks, Dd, Dd);
    tsplit_w<<<dim3(24, 24), tb>>>(Wv, gwvs, Dd, Dd);
    tsplit_w<<<dim3(24, 24), tb>>>(Wr, gwrs, Dd, Dd);
    tsplit_w<<<dim3(24, 24), tb>>>(Wo, gwos, Dd, Dd);
    tsplit_w<<<dim3(24, 96), tb>>>(W1, gw1s, Dd, FFf);
    tsplit_w<<<dim3(96, 24), tb>>>(W2, gw2s, FFf, Dd);

    // projections
    dim3 gProj(6, 48);
    hmma_gemm<0><<<gProj, 256, SMEM_SZ>>>(gxs, gwqs, nullptr, gq, nullptr, MM, Dd, K3D);
    hmma_gemm<0><<<gProj, 256, SMEM_SZ>>>(gxs, gwks, nullptr, gk, nullptr, MM, Dd, K3D);
    hmma_gemm<0><<<gProj, 256, SMEM_SZ>>>(gxs, gwvs, nullptr, gv, nullptr, MM, Dd, K3D);
    hmma_gemm<0><<<dim3(6, 6), 256, SMEM_SZ>>>(gpes, gwrs, nullptr, gr, nullptr, RROWS, Dd, K3D);

    // attention
    scores_kernel<<<dim3(12, 12, Bb * Hh), dim3(32, 32)>>>(gq, gk, gr, u, v, gsc);
    softmax_kernel<<<Bb * Hh * Ss, 128>>>(gsc);
    attnv_kernel<<<dim3(12, Hh, Bb), dim3(64, 4)>>>(gsc, gv, gattns);

    hmma_gemm<0><<<gProj, 256, SMEM_SZ>>>(gattns, gwos, nullptr, go, nullptr, MM, Dd, K3D);

    add_ln_kernel<true><<<MM, 256>>>(x, go, ln1g, ln1b, gx1, gx1s);

    // FFN
    hmma_gemm<1><<<dim3(24, 48), 256, SMEM_SZ>>>(gx1s, gw1s, b1, nullptr, gffs, MM, FFf, K3D);
    hmma_gemm<2><<<gProj, 256, SMEM_SZ>>>(gffs, gw2s, b2, gf2, nullptr, MM, Dd, K3F);

    add_ln_kernel<false><<<MM, 256>>>(gx1, gf2, ln2g, ln2b, out, nullptr);

    (void)in_sizes; (void)n_in; (void)out_size;
}

// round 8
// speedup vs baseline: 3.9764x; 2.3829x over previous
#include <cuda_runtime.h>
#include <cuda_bf16.h>
#include <cstdint>

#define Bb 16
#define Ss 384
#define Dd 768
#define Hh 12
#define FFf 3072
#define MM (Bb*Ss)          // 6144
#define RROWS (2*Ss-1)      // 767

// ---------------- scratch (static device allocations) ----------------
__device__ float g_q [MM*Dd];
__device__ float g_k [MM*Dd];
__device__ float g_v [MM*Dd];
__device__ float g_r [(size_t)768*Dd];
__device__ float g_sc[(size_t)Bb*Hh*Ss*Ss];
__device__ float g_o [MM*Dd];
__device__ float g_x1[MM*Dd];
__device__ float g_x1t[MM*Dd];
__device__ float g_ff[(size_t)MM*FFf];
__device__ float g_f2[MM*Dd];

__device__ __nv_bfloat16 g_xb  [(size_t)MM*Dd];
__device__ __nv_bfloat16 g_peb [(size_t)768*Dd];
__device__ __nv_bfloat16 g_qu  [(size_t)MM*Dd];
__device__ __nv_bfloat16 g_qv  [(size_t)MM*Dd];
__device__ __nv_bfloat16 g_kb  [(size_t)MM*Dd];
__device__ __nv_bfloat16 g_rb  [(size_t)768*Dd];
__device__ __nv_bfloat16 g_attnb[(size_t)MM*Dd];
__device__ __nv_bfloat16 g_wqt [(size_t)Dd*Dd];
__device__ __nv_bfloat16 g_wkt [(size_t)Dd*Dd];
__device__ __nv_bfloat16 g_wvt [(size_t)Dd*Dd];
__device__ __nv_bfloat16 g_wrt [(size_t)Dd*Dd];
__device__ __nv_bfloat16 g_wot [(size_t)Dd*Dd];
__device__ float g_w1t[(size_t)FFf*Dd];
__device__ float g_w2t[(size_t)Dd*FFf];

// ---------------- PTX helpers (portable sm_80-class) ----------------
__device__ __forceinline__ uint32_t smem_u32(const void* p) {
    return (uint32_t)__cvta_generic_to_shared(p);
}
__device__ __forceinline__ void cp16(uint32_t dst, const void* src) {
    asm volatile("cp.async.cg.shared.global [%0], [%1], 16;\n"
                 :: "r"(dst), "l"(__cvta_generic_to_global(src)));
}
__device__ __forceinline__ void cp_commit() { asm volatile("cp.async.commit_group;\n" ::: "memory"); }
__device__ __forceinline__ void cp_wait1()  { asm volatile("cp.async.wait_group 1;\n" ::: "memory"); }
__device__ __forceinline__ void cp_wait0()  { asm volatile("cp.async.wait_group 0;\n" ::: "memory"); }

__device__ __forceinline__ void ldmA(uint32_t* a, uint32_t addr) {
    asm volatile("ldmatrix.sync.aligned.m8n8.x4.shared.b16 {%0,%1,%2,%3}, [%4];"
                 : "=r"(a[0]), "=r"(a[1]), "=r"(a[2]), "=r"(a[3]) : "r"(addr));
}
__device__ __forceinline__ void ldmB(uint32_t* b, uint32_t addr) {
    asm volatile("ldmatrix.sync.aligned.m8n8.x2.shared.b16 {%0,%1}, [%2];"
                 : "=r"(b[0]), "=r"(b[1]) : "r"(addr));
}
__device__ __forceinline__ void mma16816(float* d, const uint32_t* a, const uint32_t* b) {
    asm volatile("mma.sync.aligned.m16n8k16.row.col.f32.bf16.bf16.f32 "
                 "{%0,%1,%2,%3}, {%4,%5,%6,%7}, {%8,%9}, {%0,%1,%2,%3};"
                 : "+f"(d[0]), "+f"(d[1]), "+f"(d[2]), "+f"(d[3])
                 : "r"(a[0]), "r"(a[1]), "r"(a[2]), "r"(a[3]), "r"(b[0]), "r"(b[1]));
}
__device__ __forceinline__ void mma1688t(float* d, const uint32_t* a, const uint32_t* b) {
    asm volatile("mma.sync.aligned.m16n8k8.row.col.f32.tf32.tf32.f32 "
                 "{%0,%1,%2,%3}, {%4,%5,%6,%7}, {%8,%9}, {%0,%1,%2,%3};"
                 : "+f"(d[0]), "+f"(d[1]), "+f"(d[2]), "+f"(d[3])
                 : "r"(a[0]), "r"(a[1]), "r"(a[2]), "r"(a[3]), "r"(b[0]), "r"(b[1]));
}
__device__ __forceinline__ uint32_t lds1(uint32_t addr) {
    uint32_t r; asm volatile("ld.shared.b32 %0, [%1];" : "=r"(r) : "r"(addr)); return r;
}
__device__ __forceinline__ float tf32r(float x) {
    uint32_t r; asm("cvt.rna.tf32.f32 %0, %1;" : "=r"(r) : "f"(x));
    return __uint_as_float(r);
}

#define SMEM_SZ 98304

// ======================= bf16 HMMA GEMM (single precision pass) =============
// C(M,N) = A(M,K) * Bt(N,K)^T   fp32 out
__global__ void __launch_bounds__(256)
hmma_gemm(const __nv_bfloat16* __restrict__ A,
          const __nv_bfloat16* __restrict__ Bt,
          float* __restrict__ C,
          int Mreal, int N, int K)
{
    extern __shared__ __align__(1024) char smem[];
    uint32_t sb = smem_u32(smem);
    int tid = threadIdx.x;
    int wid = tid >> 5, lane = tid & 31;
    int n0 = blockIdx.x * 128, m0 = blockIdx.y * 128;
    int NC = K >> 6;
    int wm = (wid >> 2) * 64;
    int wn = (wid & 3) * 32;

    float acc[4][4][4];
    #pragma unroll
    for (int mt = 0; mt < 4; mt++)
        #pragma unroll
        for (int nt = 0; nt < 4; nt++)
            #pragma unroll
            for (int q = 0; q < 4; q++) acc[mt][nt][q] = 0.f;

    const int lr = tid >> 3;
    const int lc = tid & 7;
    auto load_stage = [&](int st, int cc) {
        uint32_t sa = sb + st * 32768;
        const __nv_bfloat16* pa = A  + (size_t)(m0 + lr) * K + cc * 64 + lc * 8;
        const __nv_bfloat16* pb = Bt + (size_t)(n0 + lr) * K + cc * 64 + lc * 8;
        #pragma unroll
        for (int i = 0; i < 4; i++) {
            int row = lr + i * 32;
            uint32_t off = row * 128 + ((lc ^ (row & 7)) * 16);
            cp16(sa + off,         pa);
            cp16(sa + 16384 + off, pb);
            pa += (size_t)32 * K;
            pb += (size_t)32 * K;
        }
        cp_commit();
    };

    load_stage(0, 0);
    load_stage(1, 1);

    for (int cc = 0; cc < NC; cc++) {
        if (cc + 2 < NC) cp_wait1(); else cp_wait0();
        __syncthreads();
        if (cc + 2 < NC) load_stage((cc + 2) % 3, cc + 2);

        uint32_t sa  = sb + (cc % 3) * 32768;
        uint32_t sbb = sa + 16384;
        #pragma unroll
        for (int k16 = 0; k16 < 4; k16++) {
            uint32_t a[4][4], b[4][2];
            #pragma unroll
            for (int mt = 0; mt < 4; mt++) {
                int r  = wm + mt * 16 + (lane & 15);
                int kc = 2 * k16 + ((lane >> 4) & 1);
                ldmA(a[mt], sa + r * 128 + ((kc ^ (r & 7)) * 16));
            }
            #pragma unroll
            for (int nt = 0; nt < 4; nt++) {
                int r  = wn + nt * 8 + (lane & 7);
                int kc = 2 * k16 + ((lane >> 3) & 1);
                ldmB(b[nt], sbb + r * 128 + ((kc ^ (r & 7)) * 16));
            }
            #pragma unroll
            for (int mt = 0; mt < 4; mt++)
                #pragma unroll
                for (int nt = 0; nt < 4; nt++)
                    mma16816(acc[mt][nt], a[mt], b[nt]);
        }
    }
    __syncthreads();

    float* tile = (float*)smem;
    #pragma unroll
    for (int mt = 0; mt < 4; mt++) {
        #pragma unroll
        for (int nt = 0; nt < 4; nt++) {
            int r0  = wm + mt * 16 + (lane >> 2);
            int col = wn + nt * 8 + (lane & 3) * 2;
            tile[r0 * 132 + col]           = acc[mt][nt][0];
            tile[r0 * 132 + col + 1]       = acc[mt][nt][1];
            tile[(r0 + 8) * 132 + col]     = acc[mt][nt][2];
            tile[(r0 + 8) * 132 + col + 1] = acc[mt][nt][3];
        }
    }
    __syncthreads();

    #pragma unroll
    for (int j = 0; j < 16; j++) {
        int idx = tid + j * 256;
        int rr = idx >> 5, c4 = idx & 31;
        float4 v = *(const float4*)(tile + rr * 132 + c4 * 4);
        int grow = m0 + rr;
        if (grow < Mreal)
            *(float4*)(C + (size_t)grow * N + n0 + c4 * 4) = v;
    }
}

// ======================= tf32 GEMM (FFN) ====================================
// C(M,N) = A(M,K)*Bt(N,K)^T.  A/Bt hold tf32-rounded floats.
// EPI 1: bias+relu -> tf32-rounded floats (Cs).  EPI 2: bias -> fp32 C.
template<int EPI>
__global__ void __launch_bounds__(256)
tf32_gemm(const float* __restrict__ A,
          const float* __restrict__ Bt,
          const float* __restrict__ bias,
          float* __restrict__ C,
          int M, int N, int K)
{
    extern __shared__ __align__(1024) char smem[];
    uint32_t sb = smem_u32(smem);
    int tid = threadIdx.x;
    int wid = tid >> 5, lane = tid & 31;
    int n0 = blockIdx.x * 128, m0 = blockIdx.y * 128;
    int NC = K >> 5;                 // chunks of K=32
    int wm = (wid >> 2) * 64;
    int wn = (wid & 3) * 32;

    float acc[4][4][4];
    #pragma unroll
    for (int mt = 0; mt < 4; mt++)
        #pragma unroll
        for (int nt = 0; nt < 4; nt++)
            #pragma unroll
            for (int q = 0; q < 4; q++) acc[mt][nt][q] = 0.f;

    const int lr = tid >> 3;
    const int lc = tid & 7;
    auto load_stage = [&](int st, int cc) {
        uint32_t sa = sb + st * 32768;
        const float* pa = A  + (size_t)(m0 + lr) * K + cc * 32 + lc * 4;
        const float* pb = Bt + (size_t)(n0 + lr) * K + cc * 32 + lc * 4;
        #pragma unroll
        for (int i = 0; i < 4; i++) {
            int row = lr + i * 32;
            uint32_t off = row * 128 + ((lc ^ (row & 7)) * 16);
            cp16(sa + off,         pa);
            cp16(sa + 16384 + off, pb);
            pa += (size_t)32 * K;
            pb += (size_t)32 * K;
        }
        cp_commit();
    };

    load_stage(0, 0);
    load_stage(1, 1);

    for (int cc = 0; cc < NC; cc++) {
        if (cc + 2 < NC) cp_wait1(); else cp_wait0();
        __syncthreads();
        if (cc + 2 < NC) load_stage((cc + 2) % 3, cc + 2);

        uint32_t sa  = sb + (cc % 3) * 32768;
        uint32_t sbb = sa + 16384;
        #pragma unroll
        for (int k8 = 0; k8 < 4; k8++) {
            uint32_t a[4][4], b[4][2];
            int l4 = (lane & 3) * 4;
            #pragma unroll
            for (int mt = 0; mt < 4; mt++) {
                int r = wm + mt * 16 + (lane >> 2);
                uint32_t base = sa + r * 128;
                uint32_t ad0 = base + (((2 * k8)     ^ (r & 7)) * 16) + l4;
                uint32_t ad2 = base + (((2 * k8 + 1) ^ (r & 7)) * 16) + l4;
                a[mt][0] = lds1(ad0);
                a[mt][1] = lds1(ad0 + 8 * 128);
                a[mt][2] = lds1(ad2);
                a[mt][3] = lds1(ad2 + 8 * 128);
            }
            #pragma unroll
            for (int nt = 0; nt < 4; nt++) {
                int r = wn + nt * 8 + (lane >> 2);
                uint32_t base = sbb + r * 128 + l4;
                b[nt][0] = lds1(base + (((2 * k8)     ^ (r & 7)) * 16));
                b[nt][1] = lds1(base + (((2 * k8 + 1) ^ (r & 7)) * 16));
            }
            #pragma unroll
            for (int mt = 0; mt < 4; mt++)
                #pragma unroll
                for (int nt = 0; nt < 4; nt++)
                    mma1688t(acc[mt][nt], a[mt], b[nt]);
        }
    }
    __syncthreads();

    float* tile = (float*)smem;
    #pragma unroll
    for (int mt = 0; mt < 4; mt++) {
        #pragma unroll
        for (int nt = 0; nt < 4; nt++) {
            int r0  = wm + mt * 16 + (lane >> 2);
            int col = wn + nt * 8 + (lane & 3) * 2;
            tile[r0 * 132 + col]           = acc[mt][nt][0];
            tile[r0 * 132 + col + 1]       = acc[mt][nt][1];
            tile[(r0 + 8) * 132 + col]     = acc[mt][nt][2];
            tile[(r0 + 8) * 132 + col + 1] = acc[mt][nt][3];
        }
    }
    __syncthreads();

    #pragma unroll
    for (int j = 0; j < 16; j++) {
        int idx = tid + j * 256;
        int rr = idx >> 5, c4 = idx & 31;
        float4 v = *(const float4*)(tile + rr * 132 + c4 * 4);
        int grow = m0 + rr;
        int gcol = n0 + c4 * 4;
        v.x += bias[gcol]; v.y += bias[gcol + 1];
        v.z += bias[gcol + 2]; v.w += bias[gcol + 3];
        if (EPI == 1) {
            v.x = tf32r(fmaxf(v.x, 0.f)); v.y = tf32r(fmaxf(v.y, 0.f));
            v.z = tf32r(fmaxf(v.z, 0.f)); v.w = tf32r(fmaxf(v.w, 0.f));
        }
        *(float4*)(C + (size_t)grow * N + gcol) = v;
    }
}

// ======================= scores via bf16 MMA ================================
// Block: (j0=bx*64, i0=by*64, bh).  content = QU·K^T ; rel via banded T=QV·R^T.
__global__ void __launch_bounds__(256)
scores_mma(const __nv_bfloat16* __restrict__ qu,
           const __nv_bfloat16* __restrict__ qv,
           const __nv_bfloat16* __restrict__ kb,
           const __nv_bfloat16* __restrict__ rb,
           float* __restrict__ sc)
{
    extern __shared__ __align__(1024) char smem[];
    uint32_t sb = smem_u32(smem);
    float* Tsm = reinterpret_cast<float*>(smem + 40960);

    int tid = threadIdx.x;
    int wid = tid >> 5, lane = tid & 31;
    int j0 = blockIdx.x * 64, i0 = blockIdx.y * 64;
    int bh = blockIdx.z;
    int b = bh / Hh, h = bh % Hh;
    int cbase = i0 - j0 + 320;

    // ---- load QU(8K) K(8K) QV(8K) R(16K) ----
    #pragma unroll
    for (int t2 = 0; t2 < 2; t2++) {
        int idx = tid * 2 + t2;
        int row = idx >> 3, lcc = idx & 7;
        uint32_t off = row * 128 + ((lcc ^ (row & 7)) * 16);
        const size_t qoff = ((size_t)(b * Ss + i0 + row)) * Dd + h * 64 + lcc * 8;
        cp16(sb + off,         qu + qoff);
        cp16(sb + 8192 + off,  kb + ((size_t)(b * Ss + j0 + row)) * Dd + h * 64 + lcc * 8);
        cp16(sb + 16384 + off, qv + qoff);
    }
    #pragma unroll
    for (int t4 = 0; t4 < 4; t4++) {
        int idx = tid * 4 + t4;
        int row = idx >> 3, lcc = idx & 7;
        int rg = cbase + row; if (rg > 766) rg = 766;
        uint32_t off = row * 128 + ((lcc ^ (row & 7)) * 16);
        cp16(sb + 24576 + off, rb + (size_t)rg * Dd + h * 64 + lcc * 8);
    }
    cp_commit(); cp_wait0();
    __syncthreads();

    int wm = (wid >> 1) * 16;         // 0,16,32,48
    int wn_c = (wid & 1) * 32;        // content cols
    int wn_r = (wid & 1) * 64;        // rel cols

    // ---- content pass: accC warp tile 16x32 ----
    float accC[4][4];
    #pragma unroll
    for (int nt = 0; nt < 4; nt++)
        #pragma unroll
        for (int q = 0; q < 4; q++) accC[nt][q] = 0.f;
    // ---- rel pass accums: warp tile 16x64 over T ----
    float accT[8][4];
    #pragma unroll
    for (int nt = 0; nt < 8; nt++)
        #pragma unroll
        for (int q = 0; q < 4; q++) accT[nt][q] = 0.f;

    #pragma unroll
    for (int k16 = 0; k16 < 4; k16++) {
        uint32_t a[4], b2[2];
        int kcA = 2 * k16 + ((lane >> 4) & 1);
        int rA = wm + (lane & 15);
        ldmA(a, sb + rA * 128 + ((kcA ^ (rA & 7)) * 16));
        #pragma unroll
        for (int nt = 0; nt < 4; nt++) {
            int r = wn_c + nt * 8 + (lane & 7);
            int kc = 2 * k16 + ((lane >> 3) & 1);
            ldmB(b2, sb + 8192 + r * 128 + ((kc ^ (r & 7)) * 16));
            mma16816(accC[nt], a, b2);
        }
        // rel: A from QV
        uint32_t av[4];
        ldmA(av, sb + 16384 + rA * 128 + ((kcA ^ (rA & 7)) * 16));
        #pragma unroll
        for (int nt = 0; nt < 8; nt++) {
            int r = wn_r + nt * 8 + (lane & 7);
            int kc = 2 * k16 + ((lane >> 3) & 1);
            ldmB(b2, sb + 24576 + r * 128 + ((kc ^ (r & 7)) * 16));
            mma16816(accT[nt], av, b2);
        }
    }

    // ---- store T (64 x 127 used, stride 130) ----
    #pragma unroll
    for (int nt = 0; nt < 8; nt++) {
        int row = wm + (lane >> 2);
        int col = wn_r + nt * 8 + (lane & 3) * 2;
        *(float2*)(Tsm + row * 130 + col)       = make_float2(accT[nt][0], accT[nt][1]);
        *(float2*)(Tsm + (row + 8) * 130 + col) = make_float2(accT[nt][2], accT[nt][3]);
    }
    __syncthreads();

    // ---- combine: scores = (content + T[di][di-dj+63]) * 0.125 ----
    #pragma unroll
    for (int nt = 0; nt < 4; nt++) {
        int di0 = wm + (lane >> 2);
        int dj0 = wn_c + nt * 8 + (lane & 3) * 2;
        int c00 = di0 - dj0 + 63;
        float t00 = Tsm[di0 * 130 + c00];
        float t01 = Tsm[di0 * 130 + c00 - 1];
        float t10 = Tsm[(di0 + 8) * 130 + c00 + 8];
        float t11 = Tsm[(di0 + 8) * 130 + c00 + 7];
        size_t r0 = ((size_t)bh * Ss + i0 + di0) * Ss + j0 + dj0;
        size_t r1 = ((size_t)bh * Ss + i0 + di0 + 8) * Ss + j0 + dj0;
        *(float2*)(sc + r0) = make_float2((accC[nt][0] + t00) * 0.125f,
                                          (accC[nt][1] + t01) * 0.125f);
        *(float2*)(sc + r1) = make_float2((accC[nt][2] + t10) * 0.125f,
                                          (accC[nt][3] + t11) * 0.125f);
    }
}

// ======================= conversions / prep ================================
__global__ void conv_bf16(const float* __restrict__ in, __nv_bfloat16* __restrict__ out,
                          int Mreal, int K)
{
    size_t idx = (size_t)blockIdx.x * 256 + threadIdx.x;
    int rowi = (int)(idx / K);
    float vv = (rowi < Mreal) ? in[idx] : 0.f;
    out[idx] = __float2bfloat16(vv);
}

__global__ void wt_bf16(const float* __restrict__ W, __nv_bfloat16* __restrict__ out,
                        int K, int N)
{
    __shared__ float t[32][33];
    int k0 = blockIdx.x * 32, n0 = blockIdx.y * 32;
    int tx = threadIdx.x, ty = threadIdx.y;
    for (int i = ty; i < 32; i += 8)
        t[i][tx] = W[(size_t)(k0 + i) * N + n0 + tx];
    __syncthreads();
    for (int i = ty; i < 32; i += 8)
        out[(size_t)(n0 + i) * K + k0 + tx] = __float2bfloat16(t[tx][i]);
}

__global__ void wt_tf32(const float* __restrict__ W, float* __restrict__ out,
                        int K, int N)
{
    __shared__ float t[32][33];
    int k0 = blockIdx.x * 32, n0 = blockIdx.y * 32;
    int tx = threadIdx.x, ty = threadIdx.y;
    for (int i = ty; i < 32; i += 8)
        t[i][tx] = W[(size_t)(k0 + i) * N + n0 + tx];
    __syncthreads();
    for (int i = ty; i < 32; i += 8)
        out[(size_t)(n0 + i) * K + k0 + tx] = tf32r(t[tx][i]);
}

__global__ void qkv_prep(const float* __restrict__ q, const float* __restrict__ k,
                         const float* __restrict__ u, const float* __restrict__ v,
                         __nv_bfloat16* __restrict__ qu, __nv_bfloat16* __restrict__ qv,
                         __nv_bfloat16* __restrict__ kb)
{
    size_t idx = (size_t)blockIdx.x * 256 + threadIdx.x;
    int col = (int)(idx % Dd);
    float qq = q[idx];
    qu[idx] = __float2bfloat16(qq + u[col]);
    qv[idx] = __float2bfloat16(qq + v[col]);
    kb[idx] = __float2bfloat16(k[idx]);
}

// ======================= softmax ===========================================
__global__ void softmax_kernel(float* __restrict__ sc)
{
    size_t rowi = blockIdx.x;
    float* p = sc + rowi * Ss;
    int t = threadIdx.x;

    float v0 = p[t], v1 = p[t + 128], v2 = p[t + 256];
    float m = fmaxf(v0, fmaxf(v1, v2));
    #pragma unroll
    for (int o = 16; o > 0; o >>= 1) m = fmaxf(m, __shfl_xor_sync(~0u, m, o));
    __shared__ float sm[4], ssum[4];
    if ((t & 31) == 0) sm[t >> 5] = m;
    __syncthreads();
    m = fmaxf(fmaxf(sm[0], sm[1]), fmaxf(sm[2], sm[3]));

    float e0 = __expf(v0 - m), e1 = __expf(v1 - m), e2 = __expf(v2 - m);
    float s = e0 + e1 + e2;
    #pragma unroll
    for (int o = 16; o > 0; o >>= 1) s += __shfl_xor_sync(~0u, s, o);
    if ((t & 31) == 0) ssum[t >> 5] = s;
    __syncthreads();
    s = ssum[0] + ssum[1] + ssum[2] + ssum[3];
    float inv = 1.0f / s;
    p[t] = e0 * inv; p[t + 128] = e1 * inv; p[t + 256] = e2 * inv;
}

// ======================= attn = p @ val -> bf16 ============================
__global__ void attnv_kernel(const float* __restrict__ p,
                             const float* __restrict__ val,
                             __nv_bfloat16* __restrict__ outs)
{
    int i0 = blockIdx.x * 32;
    int h  = blockIdx.y;
    int b  = blockIdx.z;

    __shared__ float ps[32][33];
    __shared__ float vs[32][64];

    int tx = threadIdx.x, ty = threadIdx.y;    // (64,4)
    int tid = ty * 64 + tx;

    float acc[8];
    #pragma unroll
    for (int r2 = 0; r2 < 8; r2++) acc[r2] = 0.f;

    const float* prow = p + (((size_t)b * Hh + h) * Ss + i0) * Ss;

    for (int j0 = 0; j0 < Ss; j0 += 32) {
        #pragma unroll
        for (int l = 0; l < 4; l++) {
            int idx = tid + l * 256;
            int ii = idx >> 5, jj = idx & 31;
            ps[ii][jj] = prow[(size_t)ii * Ss + j0 + jj];
        }
        #pragma unroll
        for (int l = 0; l < 8; l++) {
            int idx = tid + l * 256;
            int rr = idx >> 6, cc = idx & 63;
            vs[rr][cc] = val[((size_t)b * Ss + j0 + rr) * Dd + h * 64 + cc];
        }
        __syncthreads();
        #pragma unroll
        for (int jj = 0; jj < 32; jj++) {
            float vv = vs[jj][tx];
            #pragma unroll
            for (int r2 = 0; r2 < 8; r2++)
                acc[r2] += ps[ty + 4 * r2][jj] * vv;
        }
        __syncthreads();
    }
    #pragma unroll
    for (int r2 = 0; r2 < 8; r2++) {
        int i = i0 + ty + 4 * r2;
        outs[((size_t)b * Ss + i) * Dd + h * 64 + tx] = __float2bfloat16(acc[r2]);
    }
}

// ======================= LayerNorm(a+b) ====================================
template<bool TF32OUT>
__global__ void add_ln_kernel(const float* __restrict__ a,
                              const float* __restrict__ bsrc,
                              const float* __restrict__ g,
                              const float* __restrict__ be,
                              float* __restrict__ out,
                              float* __restrict__ outt)
{
    size_t rowi = blockIdx.x;
    const float* pa = a + rowi * Dd;
    const float* pb = bsrc + rowi * Dd;
    int t = threadIdx.x;

    float x0 = pa[t] + pb[t];
    float x1 = pa[t + 256] + pb[t + 256];
    float x2 = pa[t + 512] + pb[t + 512];

    float s  = x0 + x1 + x2;
    float s2 = x0 * x0 + x1 * x1 + x2 * x2;
    #pragma unroll
    for (int o = 16; o > 0; o >>= 1) {
        s  += __shfl_xor_sync(~0u, s, o);
        s2 += __shfl_xor_sync(~0u, s2, o);
    }
    __shared__ float r1[8], r2s[8];
    if ((t & 31) == 0) { r1[t >> 5] = s; r2s[t >> 5] = s2; }
    __syncthreads();
    if (t < 32) {
        float a1 = (t < 8) ? r1[t] : 0.f;
        float a2 = (t < 8) ? r2s[t] : 0.f;
        #pragma unroll
        for (int o = 4; o > 0; o >>= 1) {
            a1 += __shfl_xor_sync(~0u, a1, o);
            a2 += __shfl_xor_sync(~0u, a2, o);
        }
        if (t == 0) { r1[0] = a1; r2s[0] = a2; }
    }
    __syncthreads();
    float mean = r1[0] * (1.f / 768.f);
    float var  = r2s[0] * (1.f / 768.f) - mean * mean;
    float inv  = rsqrtf(var + 1e-5f);

    float y0 = (x0 - mean) * inv * g[t]       + be[t];
    float y1 = (x1 - mean) * inv * g[t + 256] + be[t + 256];
    float y2 = (x2 - mean) * inv * g[t + 512] + be[t + 512];

    float* po = out + rowi * Dd;
    po[t] = y0; po[t + 256] = y1; po[t + 512] = y2;
    if (TF32OUT) {
        float* pt = outt + rowi * Dd;
        pt[t] = tf32r(y0); pt[t + 256] = tf32r(y1); pt[t + 512] = tf32r(y2);
    }
}

// ======================= launch ============================================
extern "C" void kernel_launch(void* const* d_in, const int* in_sizes, int n_in,
                              void* d_out, int out_size)
{
    const float* x    = (const float*)d_in[0];
    const float* pe   = (const float*)d_in[1];
    const float* Wq   = (const float*)d_in[2];
    const float* Wk   = (const float*)d_in[3];
    const float* Wv   = (const float*)d_in[4];
    const float* Wr   = (const float*)d_in[5];
    const float* u    = (const float*)d_in[6];
    const float* v    = (const float*)d_in[7];
    const float* Wo   = (const float*)d_in[8];
    const float* ln1g = (const float*)d_in[9];
    const float* ln1b = (const float*)d_in[10];
    const float* ln2g = (const float*)d_in[11];
    const float* ln2b = (const float*)d_in[12];
    const float* W1   = (const float*)d_in[13];
    const float* b1   = (const float*)d_in[14];
    const float* W2   = (const float*)d_in[15];
    const float* b2   = (const float*)d_in[16];
    float* out = (float*)d_out;

    float *gq, *gk, *gv, *gr, *gsc, *go, *gx1, *gx1t, *gff, *gf2, *gw1t, *gw2t;
    __nv_bfloat16 *gxb, *gpeb, *gqu, *gqv, *gkb, *grb, *gattnb;
    __nv_bfloat16 *gwqt, *gwkt, *gwvt, *gwrt, *gwot;
    cudaGetSymbolAddress((void**)&gq, g_q);     cudaGetSymbolAddress((void**)&gk, g_k);
    cudaGetSymbolAddress((void**)&gv, g_v);     cudaGetSymbolAddress((void**)&gr, g_r);
    cudaGetSymbolAddress((void**)&gsc, g_sc);   cudaGetSymbolAddress((void**)&go, g_o);
    cudaGetSymbolAddress((void**)&gx1, g_x1);   cudaGetSymbolAddress((void**)&gx1t, g_x1t);
    cudaGetSymbolAddress((void**)&gff, g_ff);   cudaGetSymbolAddress((void**)&gf2, g_f2);
    cudaGetSymbolAddress((void**)&gw1t, g_w1t); cudaGetSymbolAddress((void**)&gw2t, g_w2t);
    cudaGetSymbolAddress((void**)&gxb, g_xb);   cudaGetSymbolAddress((void**)&gpeb, g_peb);
    cudaGetSymbolAddress((void**)&gqu, g_qu);   cudaGetSymbolAddress((void**)&gqv, g_qv);
    cudaGetSymbolAddress((void**)&gkb, g_kb);   cudaGetSymbolAddress((void**)&grb, g_rb);
    cudaGetSymbolAddress((void**)&gattnb, g_attnb);
    cudaGetSymbolAddress((void**)&gwqt, g_wqt); cudaGetSymbolAddress((void**)&gwkt, g_wkt);
    cudaGetSymbolAddress((void**)&gwvt, g_wvt); cudaGetSymbolAddress((void**)&gwrt, g_wrt);
    cudaGetSymbolAddress((void**)&gwot, g_wot);

    cudaFuncSetAttribute(hmma_gemm,   cudaFuncAttributeMaxDynamicSharedMemorySize, SMEM_SZ);
    cudaFuncSetAttribute(tf32_gemm<1>, cudaFuncAttributeMaxDynamicSharedMemorySize, SMEM_SZ);
    cudaFuncSetAttribute(tf32_gemm<2>, cudaFuncAttributeMaxDynamicSharedMemorySize, SMEM_SZ);
    cudaFuncSetAttribute(scores_mma,  cudaFuncAttributeMaxDynamicSharedMemorySize, 74240);

    // conversions
    conv_bf16<<<(MM * Dd) / 256, 256>>>(x, gxb, MM, Dd);
    conv_bf16<<<(768 * Dd) / 256, 256>>>(pe, gpeb, RROWS, Dd);
    dim3 tb(32, 8);
    wt_bf16<<<dim3(24, 24), tb>>>(Wq, gwqt, Dd, Dd);
    wt_bf16<<<dim3(24, 24), tb>>>(Wk, gwkt, Dd, Dd);
    wt_bf16<<<dim3(24, 24), tb>>>(Wv, gwvt, Dd, Dd);
    wt_bf16<<<dim3(24, 24), tb>>>(Wr, gwrt, Dd, Dd);
    wt_bf16<<<dim3(24, 24), tb>>>(Wo, gwot, Dd, Dd);
    wt_tf32<<<dim3(24, 96), tb>>>(W1, gw1t, Dd, FFf);
    wt_tf32<<<dim3(96, 24), tb>>>(W2, gw2t, FFf, Dd);

    // projections (single bf16)
    dim3 gProj(6, 48);
    hmma_gemm<<<gProj, 256, SMEM_SZ>>>(gxb, gwqt, gq, MM, Dd, Dd);
    hmma_gemm<<<gProj, 256, SMEM_SZ>>>(gxb, gwkt, gk, MM, Dd, Dd);
    hmma_gemm<<<gProj, 256, SMEM_SZ>>>(gxb, gwvt, gv, MM, Dd, Dd);
    hmma_gemm<<<dim3(6, 6), 256, SMEM_SZ>>>(gpeb, gwrt, gr, RROWS, Dd, Dd);

    // attention
    qkv_prep<<<(MM * Dd) / 256, 256>>>(gq, gk, u, v, gqu, gqv, gkb);
    conv_bf16<<<(768 * Dd) / 256, 256>>>(gr, grb, RROWS, Dd);
    scores_mma<<<dim3(6, 6, Bb * Hh), 256, 74240>>>(gqu, gqv, gkb, grb, gsc);
    softmax_kernel<<<Bb * Hh * Ss, 128>>>(gsc);
    attnv_kernel<<<dim3(12, Hh, Bb), dim3(64, 4)>>>(gsc, gv, gattnb);
    hmma_gemm<<<gProj, 256, SMEM_SZ>>>(gattnb, gwot, go, MM, Dd, Dd);

    add_ln_kernel<true><<<MM, 256>>>(x, go, ln1g, ln1b, gx1, gx1t);

    // FFN (tf32)
    tf32_gemm<1><<<dim3(24, 48), 256, SMEM_SZ>>>(gx1t, gw1t, b1, gff, MM, FFf, Dd);
    tf32_gemm<2><<<dim3(6, 48), 256, SMEM_SZ>>>(gff, gw2t, b2, gf2, MM, Dd, FFf);

    add_ln_kernel<false><<<MM, 256>>>(gx1, gf2, ln2g, ln2b, out, nullptr);

    (void)in_sizes; (void)n_in; (void)out_size;
}

// round 9
// speedup vs baseline: 5.5738x; 1.4017x over previous
#include <cuda_runtime.h>
#include <cuda_bf16.h>
#include <cstdint>

#define Bb 16
#define Ss 384
#define Dd 768
#define Hh 12
#define FFf 3072
#define MM (Bb*Ss)          // 6144
#define RROWS (2*Ss-1)      // 767

// ---------------- scratch ----------------
__device__ float g_sc[(size_t)Bb*Hh*Ss*Ss];
__device__ float g_o [MM*Dd];
__device__ float g_x1[MM*Dd];
__device__ float g_x1t[MM*Dd];
__device__ float g_ff[(size_t)MM*FFf];
__device__ float g_f2[MM*Dd];

__device__ __nv_bfloat16 g_pb  [(size_t)Bb*Hh*Ss*Ss];
__device__ __nv_bfloat16 g_xb  [(size_t)MM*Dd];
__device__ __nv_bfloat16 g_peb [(size_t)768*Dd];
__device__ __nv_bfloat16 g_qu  [(size_t)MM*Dd];
__device__ __nv_bfloat16 g_qv  [(size_t)MM*Dd];
__device__ __nv_bfloat16 g_kb  [(size_t)MM*Dd];
__device__ __nv_bfloat16 g_vb  [(size_t)MM*Dd];
__device__ __nv_bfloat16 g_rb  [(size_t)768*Dd];
__device__ __nv_bfloat16 g_attnb[(size_t)MM*Dd];
__device__ __nv_bfloat16 g_wqt [(size_t)Dd*Dd];
__device__ __nv_bfloat16 g_wkt [(size_t)Dd*Dd];
__device__ __nv_bfloat16 g_wvt [(size_t)Dd*Dd];
__device__ __nv_bfloat16 g_wrt [(size_t)Dd*Dd];
__device__ __nv_bfloat16 g_wot [(size_t)Dd*Dd];
__device__ float g_w1t[(size_t)FFf*Dd];
__device__ float g_w2t[(size_t)Dd*FFf];

// ---------------- PTX helpers ----------------
__device__ __forceinline__ uint32_t smem_u32(const void* p) {
    return (uint32_t)__cvta_generic_to_shared(p);
}
__device__ __forceinline__ void cp16(uint32_t dst, const void* src) {
    asm volatile("cp.async.cg.shared.global [%0], [%1], 16;\n"
                 :: "r"(dst), "l"(__cvta_generic_to_global(src)));
}
__device__ __forceinline__ void cp_commit() { asm volatile("cp.async.commit_group;\n" ::: "memory"); }
__device__ __forceinline__ void cp_wait1()  { asm volatile("cp.async.wait_group 1;\n" ::: "memory"); }
__device__ __forceinline__ void cp_wait0()  { asm volatile("cp.async.wait_group 0;\n" ::: "memory"); }

__device__ __forceinline__ void ldmA(uint32_t* a, uint32_t addr) {
    asm volatile("ldmatrix.sync.aligned.m8n8.x4.shared.b16 {%0,%1,%2,%3}, [%4];"
                 : "=r"(a[0]), "=r"(a[1]), "=r"(a[2]), "=r"(a[3]) : "r"(addr));
}
__device__ __forceinline__ void ldmB(uint32_t* b, uint32_t addr) {
    asm volatile("ldmatrix.sync.aligned.m8n8.x2.shared.b16 {%0,%1}, [%2];"
                 : "=r"(b[0]), "=r"(b[1]) : "r"(addr));
}
__device__ __forceinline__ void ldmT4(uint32_t* b, uint32_t addr) {
    asm volatile("ldmatrix.sync.aligned.m8n8.x4.trans.shared.b16 {%0,%1,%2,%3}, [%4];"
                 : "=r"(b[0]), "=r"(b[1]), "=r"(b[2]), "=r"(b[3]) : "r"(addr));
}
__device__ __forceinline__ void mma16816(float* d, const uint32_t* a, const uint32_t* b) {
    asm volatile("mma.sync.aligned.m16n8k16.row.col.f32.bf16.bf16.f32 "
                 "{%0,%1,%2,%3}, {%4,%5,%6,%7}, {%8,%9}, {%0,%1,%2,%3};"
                 : "+f"(d[0]), "+f"(d[1]), "+f"(d[2]), "+f"(d[3])
                 : "r"(a[0]), "r"(a[1]), "r"(a[2]), "r"(a[3]), "r"(b[0]), "r"(b[1]));
}
__device__ __forceinline__ void mma1688t(float* d, const uint32_t* a, const uint32_t* b) {
    asm volatile("mma.sync.aligned.m16n8k8.row.col.f32.tf32.tf32.f32 "
                 "{%0,%1,%2,%3}, {%4,%5,%6,%7}, {%8,%9}, {%0,%1,%2,%3};"
                 : "+f"(d[0]), "+f"(d[1]), "+f"(d[2]), "+f"(d[3])
                 : "r"(a[0]), "r"(a[1]), "r"(a[2]), "r"(a[3]), "r"(b[0]), "r"(b[1]));
}
__device__ __forceinline__ uint32_t lds1(uint32_t addr) {
    uint32_t r; asm volatile("ld.shared.b32 %0, [%1];" : "=r"(r) : "r"(addr)); return r;
}
__device__ __forceinline__ float tf32r(float x) {
    uint32_t r; asm("cvt.rna.tf32.f32 %0, %1;" : "=r"(r) : "f"(x));
    return __uint_as_float(r);
}

#define SMEM_SZ 98304

// ======================= bf16 HMMA GEMM =====================================
// C(M,N) = A(M,K)*Bt(N,K)^T.
// EPI 0: fp32 C.   EPI 1: bf16 Cb.   EPI 2: qu=bf16(c+u[col]), qv=bf16(c+v[col]).
template<int EPI>
__global__ void __launch_bounds__(256)
hmma_gemm(const __nv_bfloat16* __restrict__ A,
          const __nv_bfloat16* __restrict__ Bt,
          float* __restrict__ C,
          __nv_bfloat16* __restrict__ Cb,
          __nv_bfloat16* __restrict__ Cb2,
          const float* __restrict__ ub,
          const float* __restrict__ vb,
          int Mreal, int N, int K)
{
    extern __shared__ __align__(1024) char smem[];
    uint32_t sb = smem_u32(smem);
    int tid = threadIdx.x;
    int wid = tid >> 5, lane = tid & 31;
    int n0 = blockIdx.x * 128, m0 = blockIdx.y * 128;
    int NC = K >> 6;
    int wm = (wid >> 2) * 64;
    int wn = (wid & 3) * 32;

    float acc[4][4][4];
    #pragma unroll
    for (int mt = 0; mt < 4; mt++)
        #pragma unroll
        for (int nt = 0; nt < 4; nt++)
            #pragma unroll
            for (int q = 0; q < 4; q++) acc[mt][nt][q] = 0.f;

    const int lr = tid >> 3;
    const int lc = tid & 7;
    auto load_stage = [&](int st, int cc) {
        uint32_t sa = sb + st * 32768;
        const __nv_bfloat16* pa = A  + (size_t)(m0 + lr) * K + cc * 64 + lc * 8;
        const __nv_bfloat16* pb = Bt + (size_t)(n0 + lr) * K + cc * 64 + lc * 8;
        #pragma unroll
        for (int i = 0; i < 4; i++) {
            int row = lr + i * 32;
            uint32_t off = row * 128 + ((lc ^ (row & 7)) * 16);
            cp16(sa + off,         pa);
            cp16(sa + 16384 + off, pb);
            pa += (size_t)32 * K;
            pb += (size_t)32 * K;
        }
        cp_commit();
    };

    load_stage(0, 0);
    load_stage(1, 1);

    for (int cc = 0; cc < NC; cc++) {
        if (cc + 2 < NC) cp_wait1(); else cp_wait0();
        __syncthreads();
        if (cc + 2 < NC) load_stage((cc + 2) % 3, cc + 2);

        uint32_t sa  = sb + (cc % 3) * 32768;
        uint32_t sbb = sa + 16384;
        #pragma unroll
        for (int k16 = 0; k16 < 4; k16++) {
            uint32_t a[4][4], b[4][2];
            #pragma unroll
            for (int mt = 0; mt < 4; mt++) {
                int r  = wm + mt * 16 + (lane & 15);
                int kc = 2 * k16 + ((lane >> 4) & 1);
                ldmA(a[mt], sa + r * 128 + ((kc ^ (r & 7)) * 16));
            }
            #pragma unroll
            for (int nt = 0; nt < 4; nt++) {
                int r  = wn + nt * 8 + (lane & 7);
                int kc = 2 * k16 + ((lane >> 3) & 1);
                ldmB(b[nt], sbb + r * 128 + ((kc ^ (r & 7)) * 16));
            }
            #pragma unroll
            for (int mt = 0; mt < 4; mt++)
                #pragma unroll
                for (int nt = 0; nt < 4; nt++)
                    mma16816(acc[mt][nt], a[mt], b[nt]);
        }
    }
    __syncthreads();

    float* tile = (float*)smem;
    #pragma unroll
    for (int mt = 0; mt < 4; mt++) {
        #pragma unroll
        for (int nt = 0; nt < 4; nt++) {
            int r0  = wm + mt * 16 + (lane >> 2);
            int col = wn + nt * 8 + (lane & 3) * 2;
            tile[r0 * 132 + col]           = acc[mt][nt][0];
            tile[r0 * 132 + col + 1]       = acc[mt][nt][1];
            tile[(r0 + 8) * 132 + col]     = acc[mt][nt][2];
            tile[(r0 + 8) * 132 + col + 1] = acc[mt][nt][3];
        }
    }
    __syncthreads();

    #pragma unroll
    for (int j = 0; j < 16; j++) {
        int idx = tid + j * 256;
        int rr = idx >> 5, c4 = idx & 31;
        float4 v = *(const float4*)(tile + rr * 132 + c4 * 4);
        int grow = m0 + rr;
        int gcol = n0 + c4 * 4;
        if (grow >= Mreal) continue;
        if (EPI == 0) {
            *(float4*)(C + (size_t)grow * N + gcol) = v;
        } else if (EPI == 1) {
            __nv_bfloat162* p = (__nv_bfloat162*)(Cb + (size_t)grow * N + gcol);
            p[0] = __nv_bfloat162(__float2bfloat16(v.x), __float2bfloat16(v.y));
            p[1] = __nv_bfloat162(__float2bfloat16(v.z), __float2bfloat16(v.w));
        } else {
            float u0 = ub[gcol], u1 = ub[gcol + 1], u2 = ub[gcol + 2], u3 = ub[gcol + 3];
            float w0 = vb[gcol], w1 = vb[gcol + 1], w2 = vb[gcol + 2], w3 = vb[gcol + 3];
            __nv_bfloat162* pu = (__nv_bfloat162*)(Cb + (size_t)grow * N + gcol);
            __nv_bfloat162* pv = (__nv_bfloat162*)(Cb2 + (size_t)grow * N + gcol);
            pu[0] = __nv_bfloat162(__float2bfloat16(v.x + u0), __float2bfloat16(v.y + u1));
            pu[1] = __nv_bfloat162(__float2bfloat16(v.z + u2), __float2bfloat16(v.w + u3));
            pv[0] = __nv_bfloat162(__float2bfloat16(v.x + w0), __float2bfloat16(v.y + w1));
            pv[1] = __nv_bfloat162(__float2bfloat16(v.z + w2), __float2bfloat16(v.w + w3));
        }
    }
}

// ======================= tf32 GEMM (FFN) ====================================
template<int EPI>   // 1: bias+relu -> tf32 floats; 2: bias -> fp32
__global__ void __launch_bounds__(256)
tf32_gemm(const float* __restrict__ A,
          const float* __restrict__ Bt,
          const float* __restrict__ bias,
          float* __restrict__ C,
          int M, int N, int K)
{
    extern __shared__ __align__(1024) char smem[];
    uint32_t sb = smem_u32(smem);
    int tid = threadIdx.x;
    int wid = tid >> 5, lane = tid & 31;
    int n0 = blockIdx.x * 128, m0 = blockIdx.y * 128;
    int NC = K >> 5;
    int wm = (wid >> 2) * 64;
    int wn = (wid & 3) * 32;

    float acc[4][4][4];
    #pragma unroll
    for (int mt = 0; mt < 4; mt++)
        #pragma unroll
        for (int nt = 0; nt < 4; nt++)
            #pragma unroll
            for (int q = 0; q < 4; q++) acc[mt][nt][q] = 0.f;

    const int lr = tid >> 3;
    const int lc = tid & 7;
    auto load_stage = [&](int st, int cc) {
        uint32_t sa = sb + st * 32768;
        const float* pa = A  + (size_t)(m0 + lr) * K + cc * 32 + lc * 4;
        const float* pb = Bt + (size_t)(n0 + lr) * K + cc * 32 + lc * 4;
        #pragma unroll
        for (int i = 0; i < 4; i++) {
            int row = lr + i * 32;
            uint32_t off = row * 128 + ((lc ^ (row & 7)) * 16);
            cp16(sa + off,         pa);
            cp16(sa + 16384 + off, pb);
            pa += (size_t)32 * K;
            pb += (size_t)32 * K;
        }
        cp_commit();
    };

    load_stage(0, 0);
    load_stage(1, 1);

    for (int cc = 0; cc < NC; cc++) {
        if (cc + 2 < NC) cp_wait1(); else cp_wait0();
        __syncthreads();
        if (cc + 2 < NC) load_stage((cc + 2) % 3, cc + 2);

        uint32_t sa  = sb + (cc % 3) * 32768;
        uint32_t sbb = sa + 16384;
        #pragma unroll
        for (int k8 = 0; k8 < 4; k8++) {
            uint32_t a[4][4], b[4][2];
            int l4 = (lane & 3) * 4;
            #pragma unroll
            for (int mt = 0; mt < 4; mt++) {
                int r = wm + mt * 16 + (lane >> 2);
                uint32_t base = sa + r * 128;
                uint32_t ad0 = base + (((2 * k8)     ^ (r & 7)) * 16) + l4;
                uint32_t ad2 = base + (((2 * k8 + 1) ^ (r & 7)) * 16) + l4;
                a[mt][0] = lds1(ad0);
                a[mt][1] = lds1(ad0 + 8 * 128);
                a[mt][2] = lds1(ad2);
                a[mt][3] = lds1(ad2 + 8 * 128);
            }
            #pragma unroll
            for (int nt = 0; nt < 4; nt++) {
                int r = wn + nt * 8 + (lane >> 2);
                uint32_t base = sbb + r * 128 + l4;
                b[nt][0] = lds1(base + (((2 * k8)     ^ (r & 7)) * 16));
                b[nt][1] = lds1(base + (((2 * k8 + 1) ^ (r & 7)) * 16));
            }
            #pragma unroll
            for (int mt = 0; mt < 4; mt++)
                #pragma unroll
                for (int nt = 0; nt < 4; nt++)
                    mma1688t(acc[mt][nt], a[mt], b[nt]);
        }
    }
    __syncthreads();

    float* tile = (float*)smem;
    #pragma unroll
    for (int mt = 0; mt < 4; mt++) {
        #pragma unroll
        for (int nt = 0; nt < 4; nt++) {
            int r0  = wm + mt * 16 + (lane >> 2);
            int col = wn + nt * 8 + (lane & 3) * 2;
            tile[r0 * 132 + col]           = acc[mt][nt][0];
            tile[r0 * 132 + col + 1]       = acc[mt][nt][1];
            tile[(r0 + 8) * 132 + col]     = acc[mt][nt][2];
            tile[(r0 + 8) * 132 + col + 1] = acc[mt][nt][3];
        }
    }
    __syncthreads();

    #pragma unroll
    for (int j = 0; j < 16; j++) {
        int idx = tid + j * 256;
        int rr = idx >> 5, c4 = idx & 31;
        float4 v = *(const float4*)(tile + rr * 132 + c4 * 4);
        int grow = m0 + rr;
        int gcol = n0 + c4 * 4;
        v.x += bias[gcol]; v.y += bias[gcol + 1];
        v.z += bias[gcol + 2]; v.w += bias[gcol + 3];
        if (EPI == 1) {
            v.x = tf32r(fmaxf(v.x, 0.f)); v.y = tf32r(fmaxf(v.y, 0.f));
            v.z = tf32r(fmaxf(v.z, 0.f)); v.w = tf32r(fmaxf(v.w, 0.f));
        }
        *(float4*)(C + (size_t)grow * N + gcol) = v;
    }
}

// ======================= scores via bf16 MMA ================================
__global__ void __launch_bounds__(256)
scores_mma(const __nv_bfloat16* __restrict__ qu,
           const __nv_bfloat16* __restrict__ qv,
           const __nv_bfloat16* __restrict__ kb,
           const __nv_bfloat16* __restrict__ rb,
           float* __restrict__ sc)
{
    extern __shared__ __align__(1024) char smem[];
    uint32_t sb = smem_u32(smem);
    float* Tsm = reinterpret_cast<float*>(smem + 40960);

    int tid = threadIdx.x;
    int wid = tid >> 5, lane = tid & 31;
    int j0 = blockIdx.x * 64, i0 = blockIdx.y * 64;
    int bh = blockIdx.z;
    int b = bh / Hh, h = bh % Hh;
    int cbase = i0 - j0 + 320;

    #pragma unroll
    for (int t2 = 0; t2 < 2; t2++) {
        int idx = tid * 2 + t2;
        int row = idx >> 3, lcc = idx & 7;
        uint32_t off = row * 128 + ((lcc ^ (row & 7)) * 16);
        const size_t qoff = ((size_t)(b * Ss + i0 + row)) * Dd + h * 64 + lcc * 8;
        cp16(sb + off,         qu + qoff);
        cp16(sb + 8192 + off,  kb + ((size_t)(b * Ss + j0 + row)) * Dd + h * 64 + lcc * 8);
        cp16(sb + 16384 + off, qv + qoff);
    }
    #pragma unroll
    for (int t4 = 0; t4 < 4; t4++) {
        int idx = tid * 4 + t4;
        int row = idx >> 3, lcc = idx & 7;
        int rg = cbase + row; if (rg > 766) rg = 766;
        uint32_t off = row * 128 + ((lcc ^ (row & 7)) * 16);
        cp16(sb + 24576 + off, rb + (size_t)rg * Dd + h * 64 + lcc * 8);
    }
    cp_commit(); cp_wait0();
    __syncthreads();

    int wm = (wid >> 1) * 16;
    int wn_c = (wid & 1) * 32;
    int wn_r = (wid & 1) * 64;

    float accC[4][4];
    #pragma unroll
    for (int nt = 0; nt < 4; nt++)
        #pragma unroll
        for (int q = 0; q < 4; q++) accC[nt][q] = 0.f;
    float accT[8][4];
    #pragma unroll
    for (int nt = 0; nt < 8; nt++)
        #pragma unroll
        for (int q = 0; q < 4; q++) accT[nt][q] = 0.f;

    #pragma unroll
    for (int k16 = 0; k16 < 4; k16++) {
        uint32_t a[4], b2[2];
        int kcA = 2 * k16 + ((lane >> 4) & 1);
        int rA = wm + (lane & 15);
        ldmA(a, sb + rA * 128 + ((kcA ^ (rA & 7)) * 16));
        #pragma unroll
        for (int nt = 0; nt < 4; nt++) {
            int r = wn_c + nt * 8 + (lane & 7);
            int kc = 2 * k16 + ((lane >> 3) & 1);
            ldmB(b2, sb + 8192 + r * 128 + ((kc ^ (r & 7)) * 16));
            mma16816(accC[nt], a, b2);
        }
        uint32_t av[4];
        ldmA(av, sb + 16384 + rA * 128 + ((kcA ^ (rA & 7)) * 16));
        #pragma unroll
        for (int nt = 0; nt < 8; nt++) {
            int r = wn_r + nt * 8 + (lane & 7);
            int kc = 2 * k16 + ((lane >> 3) & 1);
            ldmB(b2, sb + 24576 + r * 128 + ((kc ^ (r & 7)) * 16));
            mma16816(accT[nt], av, b2);
        }
    }

    #pragma unroll
    for (int nt = 0; nt < 8; nt++) {
        int row = wm + (lane >> 2);
        int col = wn_r + nt * 8 + (lane & 3) * 2;
        *(float2*)(Tsm + row * 130 + col)       = make_float2(accT[nt][0], accT[nt][1]);
        *(float2*)(Tsm + (row + 8) * 130 + col) = make_float2(accT[nt][2], accT[nt][3]);
    }
    __syncthreads();

    #pragma unroll
    for (int nt = 0; nt < 4; nt++) {
        int di0 = wm + (lane >> 2);
        int dj0 = wn_c + nt * 8 + (lane & 3) * 2;
        int c00 = di0 - dj0 + 63;
        float t00 = Tsm[di0 * 130 + c00];
        float t01 = Tsm[di0 * 130 + c00 - 1];
        float t10 = Tsm[(di0 + 8) * 130 + c00 + 8];
        float t11 = Tsm[(di0 + 8) * 130 + c00 + 7];
        size_t r0 = ((size_t)bh * Ss + i0 + di0) * Ss + j0 + dj0;
        size_t r1 = ((size_t)bh * Ss + i0 + di0 + 8) * Ss + j0 + dj0;
        *(float2*)(sc + r0) = make_float2((accC[nt][0] + t00) * 0.125f,
                                          (accC[nt][1] + t01) * 0.125f);
        *(float2*)(sc + r1) = make_float2((accC[nt][2] + t10) * 0.125f,
                                          (accC[nt][3] + t11) * 0.125f);
    }
}

// ======================= attnv via bf16 MMA ================================
// grid (Ss/64, Hh, Bb): out[b, i0+64, h*64..] = p[bh, i, :] @ V[b, :, h*64..]
__global__ void __launch_bounds__(256)
attnv_mma(const __nv_bfloat16* __restrict__ pb,
          const __nv_bfloat16* __restrict__ vb,
          __nv_bfloat16* __restrict__ outb)
{
    extern __shared__ __align__(1024) char smem[];
    uint32_t sb = smem_u32(smem);
    int tid = threadIdx.x;
    int wid = tid >> 5, lane = tid & 31;
    int i0 = blockIdx.x * 64;
    int h = blockIdx.y, b = blockIdx.z;
    int bh = b * Hh + h;

    int wm = (wid >> 1) * 16;
    int wn = (wid & 1) * 32;

    float acc[4][4];
    #pragma unroll
    for (int nf = 0; nf < 4; nf++)
        #pragma unroll
        for (int q = 0; q < 4; q++) acc[nf][q] = 0.f;

    auto load_stage = [&](int st, int kc) {
        uint32_t sp = sb + st * 16384;
        uint32_t sv = sp + 8192;
        #pragma unroll
        for (int t2 = 0; t2 < 2; t2++) {
            int idx = tid * 2 + t2;
            int row = idx >> 3, lcc = idx & 7;
            uint32_t off = row * 128 + ((lcc ^ (row & 7)) * 16);
            cp16(sp + off, pb + ((size_t)bh * Ss + i0 + row) * Ss + kc * 64 + lcc * 8);
            cp16(sv + off, vb + ((size_t)(b * Ss + kc * 64 + row)) * Dd + h * 64 + lcc * 8);
        }
        cp_commit();
    };

    load_stage(0, 0);

    for (int kc = 0; kc < 6; kc++) {
        if (kc + 1 < 6) { load_stage((kc + 1) & 1, kc + 1); cp_wait1(); }
        else cp_wait0();
        __syncthreads();

        uint32_t sp = sb + (kc & 1) * 16384;
        uint32_t sv = sp + 8192;
        #pragma unroll
        for (int k16 = 0; k16 < 4; k16++) {
            uint32_t a[4];
            int rA = wm + (lane & 15);
            int kcA = 2 * k16 + ((lane >> 4) & 1);
            ldmA(a, sp + rA * 128 + ((kcA ^ (rA & 7)) * 16));
            #pragma unroll
            for (int nf2 = 0; nf2 < 2; nf2++) {
                uint32_t bb[4];
                int krow = k16 * 16 + (lane & 15);
                int ncol = wn + nf2 * 16 + ((lane >> 4) * 8);
                ldmT4(bb, sv + krow * 128 + (((ncol >> 3) ^ (krow & 7)) * 16));
                mma16816(acc[nf2 * 2],     a, bb);
                mma16816(acc[nf2 * 2 + 1], a, bb + 2);
            }
        }
        __syncthreads();
    }

    #pragma unroll
    for (int nf = 0; nf < 4; nf++) {
        int row = wm + (lane >> 2);
        int col = wn + nf * 8 + (lane & 3) * 2;
        size_t o0 = ((size_t)(b * Ss + i0 + row)) * Dd + h * 64 + col;
        size_t o1 = ((size_t)(b * Ss + i0 + row + 8)) * Dd + h * 64 + col;
        *(__nv_bfloat162*)(outb + o0) =
            __nv_bfloat162(__float2bfloat16(acc[nf][0]), __float2bfloat16(acc[nf][1]));
        *(__nv_bfloat162*)(outb + o1) =
            __nv_bfloat162(__float2bfloat16(acc[nf][2]), __float2bfloat16(acc[nf][3]));
    }
}

// ======================= conversions =======================================
__global__ void conv_bf16(const float* __restrict__ in, __nv_bfloat16* __restrict__ out,
                          int Mreal, int K)
{
    size_t idx = (size_t)blockIdx.x * 256 + threadIdx.x;
    int rowi = (int)(idx / K);
    float vv = (rowi < Mreal) ? in[idx] : 0.f;
    out[idx] = __float2bfloat16(vv);
}

__global__ void wt5_bf16(const float* __restrict__ W0, const float* __restrict__ W1,
                         const float* __restrict__ W2, const float* __restrict__ W3,
                         const float* __restrict__ W4,
                         __nv_bfloat16* __restrict__ O0, __nv_bfloat16* __restrict__ O1,
                         __nv_bfloat16* __restrict__ O2, __nv_bfloat16* __restrict__ O3,
                         __nv_bfloat16* __restrict__ O4)
{
    const float* W; __nv_bfloat16* O;
    switch (blockIdx.z) {
        case 0: W = W0; O = O0; break;
        case 1: W = W1; O = O1; break;
        case 2: W = W2; O = O2; break;
        case 3: W = W3; O = O3; break;
        default: W = W4; O = O4; break;
    }
    __shared__ float t[32][33];
    int k0 = blockIdx.x * 32, n0 = blockIdx.y * 32;
    int tx = threadIdx.x, ty = threadIdx.y;
    for (int i = ty; i < 32; i += 8)
        t[i][tx] = W[(size_t)(k0 + i) * Dd + n0 + tx];
    __syncthreads();
    for (int i = ty; i < 32; i += 8)
        O[(size_t)(n0 + i) * Dd + k0 + tx] = __float2bfloat16(t[tx][i]);
}

__global__ void wt_tf32(const float* __restrict__ W, float* __restrict__ out,
                        int K, int N)
{
    __shared__ float t[32][33];
    int k0 = blockIdx.x * 32, n0 = blockIdx.y * 32;
    int tx = threadIdx.x, ty = threadIdx.y;
    for (int i = ty; i < 32; i += 8)
        t[i][tx] = W[(size_t)(k0 + i) * N + n0 + tx];
    __syncthreads();
    for (int i = ty; i < 32; i += 8)
        out[(size_t)(n0 + i) * K + k0 + tx] = tf32r(t[tx][i]);
}

// ======================= softmax -> bf16 p =================================
__global__ void softmax_kernel(const float* __restrict__ sc, __nv_bfloat16* __restrict__ pb)
{
    size_t rowi = blockIdx.x;
    const float* p = sc + rowi * Ss;
    int t = threadIdx.x;

    float v0 = p[t], v1 = p[t + 128], v2 = p[t + 256];
    float m = fmaxf(v0, fmaxf(v1, v2));
    #pragma unroll
    for (int o = 16; o > 0; o >>= 1) m = fmaxf(m, __shfl_xor_sync(~0u, m, o));
    __shared__ float sm[4], ssum[4];
    if ((t & 31) == 0) sm[t >> 5] = m;
    __syncthreads();
    m = fmaxf(fmaxf(sm[0], sm[1]), fmaxf(sm[2], sm[3]));

    float e0 = __expf(v0 - m), e1 = __expf(v1 - m), e2 = __expf(v2 - m);
    float s = e0 + e1 + e2;
    #pragma unroll
    for (int o = 16; o > 0; o >>= 1) s += __shfl_xor_sync(~0u, s, o);
    if ((t & 31) == 0) ssum[t >> 5] = s;
    __syncthreads();
    s = ssum[0] + ssum[1] + ssum[2] + ssum[3];
    float inv = 1.0f / s;
    __nv_bfloat16* po = pb + rowi * Ss;
    po[t]       = __float2bfloat16(e0 * inv);
    po[t + 128] = __float2bfloat16(e1 * inv);
    po[t + 256] = __float2bfloat16(e2 * inv);
}

// ======================= LayerNorm(a+b) ====================================
template<bool TF32OUT>
__global__ void add_ln_kernel(const float* __restrict__ a,
                              const float* __restrict__ bsrc,
                              const float* __restrict__ g,
                              const float* __restrict__ be,
                              float* __restrict__ out,
                              float* __restrict__ outt)
{
    size_t rowi = blockIdx.x;
    const float* pa = a + rowi * Dd;
    const float* pb = bsrc + rowi * Dd;
    int t = threadIdx.x;

    float x0 = pa[t] + pb[t];
    float x1 = pa[t + 256] + pb[t + 256];
    float x2 = pa[t + 512] + pb[t + 512];

    float s  = x0 + x1 + x2;
    float s2 = x0 * x0 + x1 * x1 + x2 * x2;
    #pragma unroll
    for (int o = 16; o > 0; o >>= 1) {
        s  += __shfl_xor_sync(~0u, s, o);
        s2 += __shfl_xor_sync(~0u, s2, o);
    }
    __shared__ float r1[8], r2s[8];
    if ((t & 31) == 0) { r1[t >> 5] = s; r2s[t >> 5] = s2; }
    __syncthreads();
    if (t < 32) {
        float a1 = (t < 8) ? r1[t] : 0.f;
        float a2 = (t < 8) ? r2s[t] : 0.f;
        #pragma unroll
        for (int o = 4; o > 0; o >>= 1) {
            a1 += __shfl_xor_sync(~0u, a1, o);
            a2 += __shfl_xor_sync(~0u, a2, o);
        }
        if (t == 0) { r1[0] = a1; r2s[0] = a2; }
    }
    __syncthreads();
    float mean = r1[0] * (1.f / 768.f);
    float var  = r2s[0] * (1.f / 768.f) - mean * mean;
    float inv  = rsqrtf(var + 1e-5f);

    float y0 = (x0 - mean) * inv * g[t]       + be[t];
    float y1 = (x1 - mean) * inv * g[t + 256] + be[t + 256];
    float y2 = (x2 - mean) * inv * g[t + 512] + be[t + 512];

    float* po = out + rowi * Dd;
    po[t] = y0; po[t + 256] = y1; po[t + 512] = y2;
    if (TF32OUT) {
        float* pt = outt + rowi * Dd;
        pt[t] = tf32r(y0); pt[t + 256] = tf32r(y1); pt[t + 512] = tf32r(y2);
    }
}

// ======================= launch ============================================
extern "C" void kernel_launch(void* const* d_in, const int* in_sizes, int n_in,
                              void* d_out, int out_size)
{
    const float* x    = (const float*)d_in[0];
    const float* pe   = (const float*)d_in[1];
    const float* Wq   = (const float*)d_in[2];
    const float* Wk   = (const float*)d_in[3];
    const float* Wv   = (const float*)d_in[4];
    const float* Wr   = (const float*)d_in[5];
    const float* u    = (const float*)d_in[6];
    const float* v    = (const float*)d_in[7];
    const float* Wo   = (const float*)d_in[8];
    const float* ln1g = (const float*)d_in[9];
    const float* ln1b = (const float*)d_in[10];
    const float* ln2g = (const float*)d_in[11];
    const float* ln2b = (const float*)d_in[12];
    const float* W1   = (const float*)d_in[13];
    const float* b1   = (const float*)d_in[14];
    const float* W2   = (const float*)d_in[15];
    const float* b2   = (const float*)d_in[16];
    float* out = (float*)d_out;

    float *gsc, *go, *gx1, *gx1t, *gff, *gf2, *gw1t, *gw2t;
    __nv_bfloat16 *gpb, *gxb, *gpeb, *gqu, *gqv, *gkb, *gvb, *grb, *gattnb;
    __nv_bfloat16 *gwqt, *gwkt, *gwvt, *gwrt, *gwot;
    cudaGetSymbolAddress((void**)&gsc, g_sc);   cudaGetSymbolAddress((void**)&go, g_o);
    cudaGetSymbolAddress((void**)&gx1, g_x1);   cudaGetSymbolAddress((void**)&gx1t, g_x1t);
    cudaGetSymbolAddress((void**)&gff, g_ff);   cudaGetSymbolAddress((void**)&gf2, g_f2);
    cudaGetSymbolAddress((void**)&gw1t, g_w1t); cudaGetSymbolAddress((void**)&gw2t, g_w2t);
    cudaGetSymbolAddress((void**)&gpb, g_pb);
    cudaGetSymbolAddress((void**)&gxb, g_xb);   cudaGetSymbolAddress((void**)&gpeb, g_peb);
    cudaGetSymbolAddress((void**)&gqu, g_qu);   cudaGetSymbolAddress((void**)&gqv, g_qv);
    cudaGetSymbolAddress((void**)&gkb, g_kb);   cudaGetSymbolAddress((void**)&gvb, g_vb);
    cudaGetSymbolAddress((void**)&grb, g_rb);
    cudaGetSymbolAddress((void**)&gattnb, g_attnb);
    cudaGetSymbolAddress((void**)&gwqt, g_wqt); cudaGetSymbolAddress((void**)&gwkt, g_wkt);
    cudaGetSymbolAddress((void**)&gwvt, g_wvt); cudaGetSymbolAddress((void**)&gwrt, g_wrt);
    cudaGetSymbolAddress((void**)&gwot, g_wot);

    cudaFuncSetAttribute(hmma_gemm<0>, cudaFuncAttributeMaxDynamicSharedMemorySize, SMEM_SZ);
    cudaFuncSetAttribute(hmma_gemm<1>, cudaFuncAttributeMaxDynamicSharedMemorySize, SMEM_SZ);
    cudaFuncSetAttribute(hmma_gemm<2>, cudaFuncAttributeMaxDynamicSharedMemorySize, SMEM_SZ);
    cudaFuncSetAttribute(tf32_gemm<1>, cudaFuncAttributeMaxDynamicSharedMemorySize, SMEM_SZ);
    cudaFuncSetAttribute(tf32_gemm<2>, cudaFuncAttributeMaxDynamicSharedMemorySize, SMEM_SZ);
    cudaFuncSetAttribute(scores_mma,  cudaFuncAttributeMaxDynamicSharedMemorySize, 74240);
    cudaFuncSetAttribute(attnv_mma,   cudaFuncAttributeMaxDynamicSharedMemorySize, 32768);

    // conversions
    conv_bf16<<<(MM * Dd) / 256, 256>>>(x, gxb, MM, Dd);
    conv_bf16<<<(768 * Dd) / 256, 256>>>(pe, gpeb, RROWS, Dd);
    dim3 tb(32, 8);
    wt5_bf16<<<dim3(24, 24, 5), tb>>>(Wq, Wk, Wv, Wr, Wo, gwqt, gwkt, gwvt, gwrt, gwot);
    wt_tf32<<<dim3(24, 96), tb>>>(W1, gw1t, Dd, FFf);
    wt_tf32<<<dim3(96, 24), tb>>>(W2, gw2t, FFf, Dd);

    // projections with fused epilogues
    dim3 gProj(6, 48);
    hmma_gemm<2><<<gProj, 256, SMEM_SZ>>>(gxb, gwqt, nullptr, gqu, gqv, u, v, MM, Dd, Dd);
    hmma_gemm<1><<<gProj, 256, SMEM_SZ>>>(gxb, gwkt, nullptr, gkb, nullptr, nullptr, nullptr, MM, Dd, Dd);
    hmma_gemm<1><<<gProj, 256, SMEM_SZ>>>(gxb, gwvt, nullptr, gvb, nullptr, nullptr, nullptr, MM, Dd, Dd);
    hmma_gemm<1><<<dim3(6, 6), 256, SMEM_SZ>>>(gpeb, gwrt, nullptr, grb, nullptr, nullptr, nullptr, RROWS, Dd, Dd);

    // attention
    scores_mma<<<dim3(6, 6, Bb * Hh), 256, 74240>>>(gqu, gqv, gkb, grb, gsc);
    softmax_kernel<<<Bb * Hh * Ss, 128>>>(gsc, gpb);
    attnv_mma<<<dim3(6, Hh, Bb), 256, 32768>>>(gpb, gvb, gattnb);
    hmma_gemm<0><<<gProj, 256, SMEM_SZ>>>(gattnb, gwot, go, nullptr, nullptr, nullptr, nullptr, MM, Dd, Dd);

    add_ln_kernel<true><<<MM, 256>>>(x, go, ln1g, ln1b, gx1, gx1t);

    // FFN (tf32)
    tf32_gemm<1><<<dim3(24, 48), 256, SMEM_SZ>>>(gx1t, gw1t, b1, gff, MM, FFf, Dd);
    tf32_gemm<2><<<dim3(6, 48), 256, SMEM_SZ>>>(gff, gw2t, b2, gf2, MM, Dd, FFf);

    add_ln_kernel<false><<<MM, 256>>>(gx1, gf2, ln2g, ln2b, out, nullptr);

    (void)in_sizes; (void)n_in; (void)out_size;
}

// round 14
// speedup vs baseline: 7.2132x; 1.2941x over previous
#include <cuda_runtime.h>
#include <cuda_fp16.h>
#include <cstdint>

#define Bb 16
#define Ss 384
#define Dd 768
#define Hh 12
#define FFf 3072
#define MM (Bb*Ss)          // 6144
#define RROWS (2*Ss-1)      // 767

// ---------------- scratch ----------------
__device__ float g_sc[(size_t)Bb*Hh*Ss*Ss];
__device__ float g_o [MM*Dd];
__device__ float g_x1[MM*Dd];
__device__ float g_f2[MM*Dd];

__device__ __half g_pb  [(size_t)Bb*Hh*Ss*Ss];
__device__ __half g_xh  [(size_t)MM*Dd];
__device__ __half g_peh [(size_t)768*Dd];
__device__ __half g_qu  [(size_t)MM*Dd];
__device__ __half g_qv  [(size_t)MM*Dd];
__device__ __half g_kh  [(size_t)MM*Dd];
__device__ __half g_vh  [(size_t)MM*Dd];
__device__ __half g_rh  [(size_t)768*Dd];
__device__ __half g_attnh[(size_t)MM*Dd];
__device__ __half g_x1h [(size_t)MM*Dd];
__device__ __half g_ffh [(size_t)MM*FFf];
__device__ __half g_wqt [(size_t)Dd*Dd];
__device__ __half g_wkt [(size_t)Dd*Dd];
__device__ __half g_wvt [(size_t)Dd*Dd];
__device__ __half g_wrt [(size_t)Dd*Dd];
__device__ __half g_wot [(size_t)Dd*Dd];
__device__ __half g_w1t [(size_t)FFf*Dd];
__device__ __half g_w2t [(size_t)Dd*FFf];

// ---------------- PTX helpers ----------------
__device__ __forceinline__ uint32_t smem_u32(const void* p) {
    return (uint32_t)__cvta_generic_to_shared(p);
}
__device__ __forceinline__ void cp16(uint32_t dst, const void* src) {
    asm volatile("cp.async.cg.shared.global [%0], [%1], 16;\n"
                 :: "r"(dst), "l"(__cvta_generic_to_global(src)));
}
__device__ __forceinline__ void cp_commit() { asm volatile("cp.async.commit_group;\n" ::: "memory"); }
__device__ __forceinline__ void cp_wait1()  { asm volatile("cp.async.wait_group 1;\n" ::: "memory"); }
__device__ __forceinline__ void cp_wait0()  { asm volatile("cp.async.wait_group 0;\n" ::: "memory"); }

__device__ __forceinline__ void ldmA(uint32_t* a, uint32_t addr) {
    asm volatile("ldmatrix.sync.aligned.m8n8.x4.shared.b16 {%0,%1,%2,%3}, [%4];"
                 : "=r"(a[0]), "=r"(a[1]), "=r"(a[2]), "=r"(a[3]) : "r"(addr));
}
__device__ __forceinline__ void ldmB(uint32_t* b, uint32_t addr) {
    asm volatile("ldmatrix.sync.aligned.m8n8.x2.shared.b16 {%0,%1}, [%2];"
                 : "=r"(b[0]), "=r"(b[1]) : "r"(addr));
}
__device__ __forceinline__ void ldmT4(uint32_t* b, uint32_t addr) {
    asm volatile("ldmatrix.sync.aligned.m8n8.x4.trans.shared.b16 {%0,%1,%2,%3}, [%4];"
                 : "=r"(b[0]), "=r"(b[1]), "=r"(b[2]), "=r"(b[3]) : "r"(addr));
}
__device__ __forceinline__ void mmaF16(float* d, const uint32_t* a, const uint32_t* b) {
    asm volatile("mma.sync.aligned.m16n8k16.row.col.f32.f16.f16.f32 "
                 "{%0,%1,%2,%3}, {%4,%5,%6,%7}, {%8,%9}, {%0,%1,%2,%3};"
                 : "+f"(d[0]), "+f"(d[1]), "+f"(d[2]), "+f"(d[3])
                 : "r"(a[0]), "r"(a[1]), "r"(a[2]), "r"(a[3]), "r"(b[0]), "r"(b[1]));
}

#define SMEM_SZ 98304

// ======================= fp16 HMMA GEMM =====================================
// C(M,N) = A(M,K)*Bt(N,K)^T.
// EPI 0: fp32 C           EPI 1: half Cb
// EPI 2: qu=h(c+u), qv=h(c+v)
// EPI 3: bias+relu -> half Cb          EPI 4: bias -> fp32 C
template<int EPI>
__global__ void __launch_bounds__(256)
hmma_gemm(const __half* __restrict__ A,
          const __half* __restrict__ Bt,
          float* __restrict__ C,
          __half* __restrict__ Cb,
          __half* __restrict__ Cb2,
          const float* __restrict__ ub,
          const float* __restrict__ vb,
          const float* __restrict__ bias,
          int Mreal, int N, int K)
{
    extern __shared__ __align__(1024) char smem[];
    uint32_t sb = smem_u32(smem);
    int tid = threadIdx.x;
    int wid = tid >> 5, lane = tid & 31;
    int n0 = blockIdx.x * 128, m0 = blockIdx.y * 128;
    int NC = K >> 6;
    int wm = (wid >> 2) * 64;
    int wn = (wid & 3) * 32;

    float acc[4][4][4];
    #pragma unroll
    for (int mt = 0; mt < 4; mt++)
        #pragma unroll
        for (int nt = 0; nt < 4; nt++)
            #pragma unroll
            for (int q = 0; q < 4; q++) acc[mt][nt][q] = 0.f;

    const int lr = tid >> 3;
    const int lc = tid & 7;
    auto load_stage = [&](int st, int cc) {
        uint32_t sa = sb + st * 32768;
        const __half* pa = A  + (size_t)(m0 + lr) * K + cc * 64 + lc * 8;
        const __half* pb = Bt + (size_t)(n0 + lr) * K + cc * 64 + lc * 8;
        #pragma unroll
        for (int i = 0; i < 4; i++) {
            int row = lr + i * 32;
            uint32_t off = row * 128 + ((lc ^ (row & 7)) * 16);
            cp16(sa + off,         pa);
            cp16(sa + 16384 + off, pb);
            pa += (size_t)32 * K;
            pb += (size_t)32 * K;
        }
        cp_commit();
    };

    load_stage(0, 0);
    load_stage(1, 1);

    for (int cc = 0; cc < NC; cc++) {
        if (cc + 2 < NC) cp_wait1(); else cp_wait0();
        __syncthreads();
        if (cc + 2 < NC) load_stage((cc + 2) % 3, cc + 2);

        uint32_t sa  = sb + (cc % 3) * 32768;
        uint32_t sbb = sa + 16384;
        #pragma unroll
        for (int k16 = 0; k16 < 4; k16++) {
            uint32_t a[4][4], b[4][2];
            #pragma unroll
            for (int mt = 0; mt < 4; mt++) {
                int r  = wm + mt * 16 + (lane & 15);
                int kc = 2 * k16 + ((lane >> 4) & 1);
                ldmA(a[mt], sa + r * 128 + ((kc ^ (r & 7)) * 16));
            }
            #pragma unroll
            for (int nt = 0; nt < 4; nt++) {
                int r  = wn + nt * 8 + (lane & 7);
                int kc = 2 * k16 + ((lane >> 3) & 1);
                ldmB(b[nt], sbb + r * 128 + ((kc ^ (r & 7)) * 16));
            }
            #pragma unroll
            for (int mt = 0; mt < 4; mt++)
                #pragma unroll
                for (int nt = 0; nt < 4; nt++)
                    mmaF16(acc[mt][nt], a[mt], b[nt]);
        }
    }
    __syncthreads();

    float* tile = (float*)smem;
    #pragma unroll
    for (int mt = 0; mt < 4; mt++) {
        #pragma unroll
        for (int nt = 0; nt < 4; nt++) {
            int r0  = wm + mt * 16 + (lane >> 2);
            int col = wn + nt * 8 + (lane & 3) * 2;
            tile[r0 * 132 + col]           = acc[mt][nt][0];
            tile[r0 * 132 + col + 1]       = acc[mt][nt][1];
            tile[(r0 + 8) * 132 + col]     = acc[mt][nt][2];
            tile[(r0 + 8) * 132 + col + 1] = acc[mt][nt][3];
        }
    }
    __syncthreads();

    #pragma unroll
    for (int j = 0; j < 16; j++) {
        int idx = tid + j * 256;
        int rr = idx >> 5, c4 = idx & 31;
        float4 v = *(const float4*)(tile + rr * 132 + c4 * 4);
        int grow = m0 + rr;
        int gcol = n0 + c4 * 4;
        if (grow >= Mreal) continue;
        if (EPI == 0) {
            *(float4*)(C + (size_t)grow * N + gcol) = v;
        } else if (EPI == 1) {
            __half2* p = (__half2*)(Cb + (size_t)grow * N + gcol);
            p[0] = __halves2half2(__float2half_rn(v.x), __float2half_rn(v.y));
            p[1] = __halves2half2(__float2half_rn(v.z), __float2half_rn(v.w));
        } else if (EPI == 2) {
            float u0 = ub[gcol], u1 = ub[gcol + 1], u2 = ub[gcol + 2], u3 = ub[gcol + 3];
            float w0 = vb[gcol], w1 = vb[gcol + 1], w2 = vb[gcol + 2], w3 = vb[gcol + 3];
            __half2* pu = (__half2*)(Cb + (size_t)grow * N + gcol);
            __half2* pv = (__half2*)(Cb2 + (size_t)grow * N + gcol);
            pu[0] = __halves2half2(__float2half_rn(v.x + u0), __float2half_rn(v.y + u1));
            pu[1] = __halves2half2(__float2half_rn(v.z + u2), __float2half_rn(v.w + u3));
            pv[0] = __halves2half2(__float2half_rn(v.x + w0), __float2half_rn(v.y + w1));
            pv[1] = __halves2half2(__float2half_rn(v.z + w2), __float2half_rn(v.w + w3));
        } else if (EPI == 3) {
            v.x = fmaxf(v.x + bias[gcol], 0.f);     v.y = fmaxf(v.y + bias[gcol + 1], 0.f);
            v.z = fmaxf(v.z + bias[gcol + 2], 0.f); v.w = fmaxf(v.w + bias[gcol + 3], 0.f);
            __half2* p = (__half2*)(Cb + (size_t)grow * N + gcol);
            p[0] = __halves2half2(__float2half_rn(v.x), __float2half_rn(v.y));
            p[1] = __halves2half2(__float2half_rn(v.z), __float2half_rn(v.w));
        } else {
            v.x += bias[gcol]; v.y += bias[gcol + 1];
            v.z += bias[gcol + 2]; v.w += bias[gcol + 3];
            *(float4*)(C + (size_t)grow * N + gcol) = v;
        }
    }
}

// ======================= scores via fp16 MMA ================================
__global__ void __launch_bounds__(256)
scores_mma(const __half* __restrict__ qu,
           const __half* __restrict__ qv,
           const __half* __restrict__ kb,
           const __half* __restrict__ rb,
           float* __restrict__ sc)
{
    extern __shared__ __align__(1024) char smem[];
    uint32_t sb = smem_u32(smem);
    float* Tsm = reinterpret_cast<float*>(smem + 40960);

    int tid = threadIdx.x;
    int wid = tid >> 5, lane = tid & 31;
    int j0 = blockIdx.x * 64, i0 = blockIdx.y * 64;
    int bh = blockIdx.z;
    int b = bh / Hh, h = bh % Hh;
    int cbase = i0 - j0 + 320;

    #pragma unroll
    for (int t2 = 0; t2 < 2; t2++) {
        int idx = tid * 2 + t2;
        int row = idx >> 3, lcc = idx & 7;
        uint32_t off = row * 128 + ((lcc ^ (row & 7)) * 16);
        const size_t qoff = ((size_t)(b * Ss + i0 + row)) * Dd + h * 64 + lcc * 8;
        cp16(sb + off,         qu + qoff);
        cp16(sb + 8192 + off,  kb + ((size_t)(b * Ss + j0 + row)) * Dd + h * 64 + lcc * 8);
        cp16(sb + 16384 + off, qv + qoff);
    }
    #pragma unroll
    for (int t4 = 0; t4 < 4; t4++) {
        int idx = tid * 4 + t4;
        int row = idx >> 3, lcc = idx & 7;
        int rg = cbase + row; if (rg > 766) rg = 766;
        uint32_t off = row * 128 + ((lcc ^ (row & 7)) * 16);
        cp16(sb + 24576 + off, rb + (size_t)rg * Dd + h * 64 + lcc * 8);
    }
    cp_commit(); cp_wait0();
    __syncthreads();

    int wm = (wid >> 1) * 16;
    int wn_c = (wid & 1) * 32;
    int wn_r = (wid & 1) * 64;

    float accC[4][4];
    #pragma unroll
    for (int nt = 0; nt < 4; nt++)
        #pragma unroll
        for (int q = 0; q < 4; q++) accC[nt][q] = 0.f;
    float accT[8][4];
    #pragma unroll
    for (int nt = 0; nt < 8; nt++)
        #pragma unroll
        for (int q = 0; q < 4; q++) accT[nt][q] = 0.f;

    #pragma unroll
    for (int k16 = 0; k16 < 4; k16++) {
        uint32_t a[4], b2[2];
        int kcA = 2 * k16 + ((lane >> 4) & 1);
        int rA = wm + (lane & 15);
        ldmA(a, sb + rA * 128 + ((kcA ^ (rA & 7)) * 16));
        #pragma unroll
        for (int nt = 0; nt < 4; nt++) {
            int r = wn_c + nt * 8 + (lane & 7);
            int kc = 2 * k16 + ((lane >> 3) & 1);
            ldmB(b2, sb + 8192 + r * 128 + ((kc ^ (r & 7)) * 16));
            mmaF16(accC[nt], a, b2);
        }
        uint32_t av[4];
        ldmA(av, sb + 16384 + rA * 128 + ((kcA ^ (rA & 7)) * 16));
        #pragma unroll
        for (int nt = 0; nt < 8; nt++) {
            int r = wn_r + nt * 8 + (lane & 7);
            int kc = 2 * k16 + ((lane >> 3) & 1);
            ldmB(b2, sb + 24576 + r * 128 + ((kc ^ (r & 7)) * 16));
            mmaF16(accT[nt], av, b2);
        }
    }

    #pragma unroll
    for (int nt = 0; nt < 8; nt++) {
        int row = wm + (lane >> 2);
        int col = wn_r + nt * 8 + (lane & 3) * 2;
        *(float2*)(Tsm + row * 130 + col)       = make_float2(accT[nt][0], accT[nt][1]);
        *(float2*)(Tsm + (row + 8) * 130 + col) = make_float2(accT[nt][2], accT[nt][3]);
    }
    __syncthreads();

    #pragma unroll
    for (int nt = 0; nt < 4; nt++) {
        int di0 = wm + (lane >> 2);
        int dj0 = wn_c + nt * 8 + (lane & 3) * 2;
        int c00 = di0 - dj0 + 63;
        float t00 = Tsm[di0 * 130 + c00];
        float t01 = Tsm[di0 * 130 + c00 - 1];
        float t10 = Tsm[(di0 + 8) * 130 + c00 + 8];
        float t11 = Tsm[(di0 + 8) * 130 + c00 + 7];
        size_t r0 = ((size_t)bh * Ss + i0 + di0) * Ss + j0 + dj0;
        size_t r1 = ((size_t)bh * Ss + i0 + di0 + 8) * Ss + j0 + dj0;
        *(float2*)(sc + r0) = make_float2((accC[nt][0] + t00) * 0.125f,
                                          (accC[nt][1] + t01) * 0.125f);
        *(float2*)(sc + r1) = make_float2((accC[nt][2] + t10) * 0.125f,
                                          (accC[nt][3] + t11) * 0.125f);
    }
}

// ======================= attnv via fp16 MMA ================================
__global__ void __launch_bounds__(256)
attnv_mma(const __half* __restrict__ pb,
          const __half* __restrict__ vb,
          __half* __restrict__ outb)
{
    extern __shared__ __align__(1024) char smem[];
    uint32_t sb = smem_u32(smem);
    int tid = threadIdx.x;
    int wid = tid >> 5, lane = tid & 31;
    int i0 = blockIdx.x * 64;
    int h = blockIdx.y, b = blockIdx.z;
    int bh = b * Hh + h;

    int wm = (wid >> 1) * 16;
    int wn = (wid & 1) * 32;

    float acc[4][4];
    #pragma unroll
    for (int nf = 0; nf < 4; nf++)
        #pragma unroll
        for (int q = 0; q < 4; q++) acc[nf][q] = 0.f;

    auto load_stage = [&](int st, int kc) {
        uint32_t sp = sb + st * 16384;
        uint32_t sv = sp + 8192;
        #pragma unroll
        for (int t2 = 0; t2 < 2; t2++) {
            int idx = tid * 2 + t2;
            int row = idx >> 3, lcc = idx & 7;
            uint32_t off = row * 128 + ((lcc ^ (row & 7)) * 16);
            cp16(sp + off, pb + ((size_t)bh * Ss + i0 + row) * Ss + kc * 64 + lcc * 8);
            cp16(sv + off, vb + ((size_t)(b * Ss + kc * 64 + row)) * Dd + h * 64 + lcc * 8);
        }
        cp_commit();
    };

    load_stage(0, 0);

    for (int kc = 0; kc < 6; kc++) {
        if (kc + 1 < 6) { load_stage((kc + 1) & 1, kc + 1); cp_wait1(); }
        else cp_wait0();
        __syncthreads();

        uint32_t sp = sb + (kc & 1) * 16384;
        uint32_t sv = sp + 8192;
        #pragma unroll
        for (int k16 = 0; k16 < 4; k16++) {
            uint32_t a[4];
            int rA = wm + (lane & 15);
            int kcA = 2 * k16 + ((lane >> 4) & 1);
            ldmA(a, sp + rA * 128 + ((kcA ^ (rA & 7)) * 16));
            #pragma unroll
            for (int nf2 = 0; nf2 < 2; nf2++) {
                uint32_t bb[4];
                int krow = k16 * 16 + (lane & 15);
                int ncol = wn + nf2 * 16 + ((lane >> 4) * 8);
                ldmT4(bb, sv + krow * 128 + (((ncol >> 3) ^ (krow & 7)) * 16));
                mmaF16(acc[nf2 * 2],     a, bb);
                mmaF16(acc[nf2 * 2 + 1], a, bb + 2);
            }
        }
        __syncthreads();
    }

    #pragma unroll
    for (int nf = 0; nf < 4; nf++) {
        int row = wm + (lane >> 2);
        int col = wn + nf * 8 + (lane & 3) * 2;
        size_t o0 = ((size_t)(b * Ss + i0 + row)) * Dd + h * 64 + col;
        size_t o1 = ((size_t)(b * Ss + i0 + row + 8)) * Dd + h * 64 + col;
        *(__half2*)(outb + o0) =
            __halves2half2(__float2half_rn(acc[nf][0]), __float2half_rn(acc[nf][1]));
        *(__half2*)(outb + o1) =
            __halves2half2(__float2half_rn(acc[nf][2]), __float2half_rn(acc[nf][3]));
    }
}

// ======================= conversions =======================================
__global__ void conv_f16(const float* __restrict__ in, __half* __restrict__ out,
                         int Mreal, int K)
{
    size_t idx = (size_t)blockIdx.x * 256 + threadIdx.x;
    int rowi = (int)(idx / K);
    float vv = (rowi < Mreal) ? in[idx] : 0.f;
    out[idx] = __float2half_rn(vv);
}

__global__ void wt5_f16(const float* __restrict__ W0, const float* __restrict__ W1,
                        const float* __restrict__ W2, const float* __restrict__ W3,
                        const float* __restrict__ W4,
                        __half* __restrict__ O0, __half* __restrict__ O1,
                        __half* __restrict__ O2, __half* __restrict__ O3,
                        __half* __restrict__ O4)
{
    const float* W; __half* O;
    switch (blockIdx.z) {
        case 0: W = W0; O = O0; break;
        case 1: W = W1; O = O1; break;
        case 2: W = W2; O = O2; break;
        case 3: W = W3; O = O3; break;
        default: W = W4; O = O4; break;
    }
    __shared__ float t[32][33];
    int k0 = blockIdx.x * 32, n0 = blockIdx.y * 32;
    int tx = threadIdx.x, ty = threadIdx.y;
    for (int i = ty; i < 32; i += 8)
        t[i][tx] = W[(size_t)(k0 + i) * Dd + n0 + tx];
    __syncthreads();
    for (int i = ty; i < 32; i += 8)
        O[(size_t)(n0 + i) * Dd + k0 + tx] = __float2half_rn(t[tx][i]);
}

__global__ void wt_f16(const float* __restrict__ W, __half* __restrict__ out,
                       int K, int N)
{
    __shared__ float t[32][33];
    int k0 = blockIdx.x * 32, n0 = blockIdx.y * 32;
    int tx = threadIdx.x, ty = threadIdx.y;
    for (int i = ty; i < 32; i += 8)
        t[i][tx] = W[(size_t)(k0 + i) * N + n0 + tx];
    __syncthreads();
    for (int i = ty; i < 32; i += 8)
        out[(size_t)(n0 + i) * K + k0 + tx] = __float2half_rn(t[tx][i]);
}

// ======================= softmax -> fp16 p =================================
__global__ void softmax_kernel(const float* __restrict__ sc, __half* __restrict__ pb)
{
    size_t rowi = blockIdx.x;
    const float* p = sc + rowi * Ss;
    int t = threadIdx.x;

    float v0 = p[t], v1 = p[t + 128], v2 = p[t + 256];
    float m = fmaxf(v0, fmaxf(v1, v2));
    #pragma unroll
    for (int o = 16; o > 0; o >>= 1) m = fmaxf(m, __shfl_xor_sync(~0u, m, o));
    __shared__ float sm[4], ssum[4];
    if ((t & 31) == 0) sm[t >> 5] = m;
    __syncthreads();
    m = fmaxf(fmaxf(sm[0], sm[1]), fmaxf(sm[2], sm[3]));

    float e0 = __expf(v0 - m), e1 = __expf(v1 - m), e2 = __expf(v2 - m);
    float s = e0 + e1 + e2;
    #pragma unroll
    for (int o = 16; o > 0; o >>= 1) s += __shfl_xor_sync(~0u, s, o);
    if ((t & 31) == 0) ssum[t >> 5] = s;
    __syncthreads();
    s = ssum[0] + ssum[1] + ssum[2] + ssum[3];
    float inv = 1.0f / s;
    __half* po = pb + rowi * Ss;
    po[t]       = __float2half_rn(e0 * inv);
    po[t + 128] = __float2half_rn(e1 * inv);
    po[t + 256] = __float2half_rn(e2 * inv);
}

// ======================= LayerNorm(a+b) ====================================
template<bool H16OUT>
__global__ void add_ln_kernel(const float* __restrict__ a,
                              const float* __restrict__ bsrc,
                              const float* __restrict__ g,
                              const float* __restrict__ be,
                              float* __restrict__ out,
                              __half* __restrict__ outh)
{
    size_t rowi = blockIdx.x;
    const float* pa = a + rowi * Dd;
    const float* pb = bsrc + rowi * Dd;
    int t = threadIdx.x;

    float x0 = pa[t] + pb[t];
    float x1 = pa[t + 256] + pb[t + 256];
    float x2 = pa[t + 512] + pb[t + 512];

    float s  = x0 + x1 + x2;
    float s2 = x0 * x0 + x1 * x1 + x2 * x2;
    #pragma unroll
    for (int o = 16; o > 0; o >>= 1) {
        s  += __shfl_xor_sync(~0u, s, o);
        s2 += __shfl_xor_sync(~0u, s2, o);
    }
    __shared__ float r1[8], r2s[8];
    if ((t & 31) == 0) { r1[t >> 5] = s; r2s[t >> 5] = s2; }
    __syncthreads();
    if (t < 32) {
        float a1 = (t < 8) ? r1[t] : 0.f;
        float a2 = (t < 8) ? r2s[t] : 0.f;
        #pragma unroll
        for (int o = 4; o > 0; o >>= 1) {
            a1 += __shfl_xor_sync(~0u, a1, o);
            a2 += __shfl_xor_sync(~0u, a2, o);
        }
        if (t == 0) { r1[0] = a1; r2s[0] = a2; }
    }
    __syncthreads();
    float mean = r1[0] * (1.f / 768.f);
    float var  = r2s[0] * (1.f / 768.f) - mean * mean;
    float inv  = rsqrtf(var + 1e-5f);

    float y0 = (x0 - mean) * inv * g[t]       + be[t];
    float y1 = (x1 - mean) * inv * g[t + 256] + be[t + 256];
    float y2 = (x2 - mean) * inv * g[t + 512] + be[t + 512];

    float* po = out + rowi * Dd;
    po[t] = y0; po[t + 256] = y1; po[t + 512] = y2;
    if (H16OUT) {
        __half* ph = outh + rowi * Dd;
        ph[t]       = __float2half_rn(y0);
        ph[t + 256] = __float2half_rn(y1);
        ph[t + 512] = __float2half_rn(y2);
    }
}

// ======================= launch ============================================
extern "C" void kernel_launch(void* const* d_in, const int* in_sizes, int n_in,
                              void* d_out, int out_size)
{
    const float* x    = (const float*)d_in[0];
    const float* pe   = (const float*)d_in[1];
    const float* Wq   = (const float*)d_in[2];
    const float* Wk   = (const float*)d_in[3];
    const float* Wv   = (const float*)d_in[4];
    const float* Wr   = (const float*)d_in[5];
    const float* u    = (const float*)d_in[6];
    const float* v    = (const float*)d_in[7];
    const float* Wo   = (const float*)d_in[8];
    const float* ln1g = (const float*)d_in[9];
    const float* ln1b = (const float*)d_in[10];
    const float* ln2g = (const float*)d_in[11];
    const float* ln2b = (const float*)d_in[12];
    const float* W1   = (const float*)d_in[13];
    const float* b1   = (const float*)d_in[14];
    const float* W2   = (const float*)d_in[15];
    const float* b2   = (const float*)d_in[16];
    float* out = (float*)d_out;

    float *gsc, *go, *gx1, *gf2;
    __half *gpb, *gxh, *gpeh, *gqu, *gqv, *gkh, *gvh, *grh, *gattnh, *gx1h, *gffh;
    __half *gwqt, *gwkt, *gwvt, *gwrt, *gwot, *gw1t, *gw2t;
    cudaGetSymbolAddress((void**)&gsc, g_sc);   cudaGetSymbolAddress((void**)&go, g_o);
    cudaGetSymbolAddress((void**)&gx1, g_x1);   cudaGetSymbolAddress((void**)&gf2, g_f2);
    cudaGetSymbolAddress((void**)&gpb, g_pb);
    cudaGetSymbolAddress((void**)&gxh, g_xh);   cudaGetSymbolAddress((void**)&gpeh, g_peh);
    cudaGetSymbolAddress((void**)&gqu, g_qu);   cudaGetSymbolAddress((void**)&gqv, g_qv);
    cudaGetSymbolAddress((void**)&gkh, g_kh);   cudaGetSymbolAddress((void**)&gvh, g_vh);
    cudaGetSymbolAddress((void**)&grh, g_rh);
    cudaGetSymbolAddress((void**)&gattnh, g_attnh);
    cudaGetSymbolAddress((void**)&gx1h, g_x1h); cudaGetSymbolAddress((void**)&gffh, g_ffh);
    cudaGetSymbolAddress((void**)&gwqt, g_wqt); cudaGetSymbolAddress((void**)&gwkt, g_wkt);
    cudaGetSymbolAddress((void**)&gwvt, g_wvt); cudaGetSymbolAddress((void**)&gwrt, g_wrt);
    cudaGetSymbolAddress((void**)&gwot, g_wot);
    cudaGetSymbolAddress((void**)&gw1t, g_w1t); cudaGetSymbolAddress((void**)&gw2t, g_w2t);

    cudaFuncSetAttribute(hmma_gemm<0>, cudaFuncAttributeMaxDynamicSharedMemorySize, SMEM_SZ);
    cudaFuncSetAttribute(hmma_gemm<1>, cudaFuncAttributeMaxDynamicSharedMemorySize, SMEM_SZ);
    cudaFuncSetAttribute(hmma_gemm<2>, cudaFuncAttributeMaxDynamicSharedMemorySize, SMEM_SZ);
    cudaFuncSetAttribute(hmma_gemm<3>, cudaFuncAttributeMaxDynamicSharedMemorySize, SMEM_SZ);
    cudaFuncSetAttribute(hmma_gemm<4>, cudaFuncAttributeMaxDynamicSharedMemorySize, SMEM_SZ);
    cudaFuncSetAttribute(scores_mma,  cudaFuncAttributeMaxDynamicSharedMemorySize, 74240);
    cudaFuncSetAttribute(attnv_mma,   cudaFuncAttributeMaxDynamicSharedMemorySize, 32768);

    // conversions
    conv_f16<<<(MM * Dd) / 256, 256>>>(x, gxh, MM, Dd);
    conv_f16<<<(768 * Dd) / 256, 256>>>(pe, gpeh, RROWS, Dd);
    dim3 tb(32, 8);
    wt5_f16<<<dim3(24, 24, 5), tb>>>(Wq, Wk, Wv, Wr, Wo, gwqt, gwkt, gwvt, gwrt, gwot);
    wt_f16<<<dim3(24, 96), tb>>>(W1, gw1t, Dd, FFf);
    wt_f16<<<dim3(96, 24), tb>>>(W2, gw2t, FFf, Dd);

    // projections with fused epilogues
    dim3 gProj(6, 48);
    hmma_gemm<2><<<gProj, 256, SMEM_SZ>>>(gxh, gwqt, nullptr, gqu, gqv, u, v, nullptr, MM, Dd, Dd);
    hmma_gemm<1><<<gProj, 256, SMEM_SZ>>>(gxh, gwkt, nullptr, gkh, nullptr, nullptr, nullptr, nullptr, MM, Dd, Dd);
    hmma_gemm<1><<<gProj, 256, SMEM_SZ>>>(gxh, gwvt, nullptr, gvh, nullptr, nullptr, nullptr, nullptr, MM, Dd, Dd);
    hmma_gemm<1><<<dim3(6, 6), 256, SMEM_SZ>>>(gpeh, gwrt, nullptr, grh, nullptr, nullptr, nullptr, nullptr, RROWS, Dd, Dd);

    // attention
    scores_mma<<<dim3(6, 6, Bb * Hh), 256, 74240>>>(gqu, gqv, gkh, grh, gsc);
    softmax_kernel<<<Bb * Hh * Ss, 128>>>(gsc, gpb);
    attnv_mma<<<dim3(6, Hh, Bb), 256, 32768>>>(gpb, gvh, gattnh);
    hmma_gemm<0><<<gProj, 256, SMEM_SZ>>>(gattnh, gwot, go, nullptr, nullptr, nullptr, nullptr, nullptr, MM, Dd, Dd);

    add_ln_kernel<true><<<MM, 256>>>(x, go, ln1g, ln1b, gx1, gx1h);

    // FFN (fp16, fp32 accum)
    hmma_gemm<3><<<dim3(24, 48), 256, SMEM_SZ>>>(gx1h, gw1t, nullptr, gffh, nullptr, nullptr, nullptr, b1, MM, FFf, Dd);
    hmma_gemm<4><<<dim3(6, 48), 256, SMEM_SZ>>>(gffh, gw2t, gf2, nullptr, nullptr, nullptr, nullptr, b2, MM, Dd, FFf);

    add_ln_kernel<false><<<MM, 256>>>(gx1, gf2, ln2g, ln2b, out, nullptr);

    (void)in_sizes; (void)n_in; (void)out_size;
}

// round 15
// speedup vs baseline: 8.7723x; 1.2161x over previous
#include <cuda_runtime.h>
#include <cuda_fp16.h>
#include <cstdint>

#define Bb 16
#define Ss 384
#define Dd 768
#define Hh 12
#define FFf 3072
#define MM (Bb*Ss)          // 6144
#define RROWS (2*Ss-1)      // 767

// ---------------- scratch ----------------
__device__ float g_o [MM*Dd];
__device__ float g_x1[MM*Dd];
__device__ float g_f2[MM*Dd];

__device__ __half g_xh  [(size_t)MM*Dd];
__device__ __half g_peh [(size_t)768*Dd];
__device__ __half g_qu  [(size_t)MM*Dd];
__device__ __half g_qv  [(size_t)MM*Dd];
__device__ __half g_kh  [(size_t)MM*Dd];
__device__ __half g_vh  [(size_t)MM*Dd];
__device__ __half g_rh  [(size_t)768*Dd];
__device__ __half g_attnh[(size_t)MM*Dd];
__device__ __half g_x1h [(size_t)MM*Dd];
__device__ __half g_ffh [(size_t)MM*FFf];
__device__ __half g_wqt [(size_t)Dd*Dd];
__device__ __half g_wkt [(size_t)Dd*Dd];
__device__ __half g_wvt [(size_t)Dd*Dd];
__device__ __half g_wrt [(size_t)Dd*Dd];
__device__ __half g_wot [(size_t)Dd*Dd];
__device__ __half g_w1t [(size_t)FFf*Dd];
__device__ __half g_w2t [(size_t)Dd*FFf];

// ---------------- PTX helpers ----------------
__device__ __forceinline__ uint32_t smem_u32(const void* p) {
    return (uint32_t)__cvta_generic_to_shared(p);
}
__device__ __forceinline__ void cp16(uint32_t dst, const void* src) {
    asm volatile("cp.async.cg.shared.global [%0], [%1], 16;\n"
                 :: "r"(dst), "l"(__cvta_generic_to_global(src)));
}
__device__ __forceinline__ void cp_commit() { asm volatile("cp.async.commit_group;\n" ::: "memory"); }
__device__ __forceinline__ void cp_wait1()  { asm volatile("cp.async.wait_group 1;\n" ::: "memory"); }
__device__ __forceinline__ void cp_wait0()  { asm volatile("cp.async.wait_group 0;\n" ::: "memory"); }

__device__ __forceinline__ void ldmA(uint32_t* a, uint32_t addr) {
    asm volatile("ldmatrix.sync.aligned.m8n8.x4.shared.b16 {%0,%1,%2,%3}, [%4];"
                 : "=r"(a[0]), "=r"(a[1]), "=r"(a[2]), "=r"(a[3]) : "r"(addr));
}
__device__ __forceinline__ void ldmB(uint32_t* b, uint32_t addr) {
    asm volatile("ldmatrix.sync.aligned.m8n8.x2.shared.b16 {%0,%1}, [%2];"
                 : "=r"(b[0]), "=r"(b[1]) : "r"(addr));
}
__device__ __forceinline__ void ldmT4(uint32_t* b, uint32_t addr) {
    asm volatile("ldmatrix.sync.aligned.m8n8.x4.trans.shared.b16 {%0,%1,%2,%3}, [%4];"
                 : "=r"(b[0]), "=r"(b[1]), "=r"(b[2]), "=r"(b[3]) : "r"(addr));
}
__device__ __forceinline__ void mmaF16(float* d, const uint32_t* a, const uint32_t* b) {
    asm volatile("mma.sync.aligned.m16n8k16.row.col.f32.f16.f16.f32 "
                 "{%0,%1,%2,%3}, {%4,%5,%6,%7}, {%8,%9}, {%0,%1,%2,%3};"
                 : "+f"(d[0]), "+f"(d[1]), "+f"(d[2]), "+f"(d[3])
                 : "r"(a[0]), "r"(a[1]), "r"(a[2]), "r"(a[3]), "r"(b[0]), "r"(b[1]));
}
__device__ __forceinline__ void stsh(uint32_t addr, float v) {
    unsigned short h = __half_as_ushort(__float2half_rn(v));
    asm volatile("st.shared.u16 [%0], %1;" :: "r"(addr), "h"(h));
}
__device__ __forceinline__ float ldsh(uint32_t addr) {
    unsigned short h;
    asm volatile("ld.shared.u16 %0, [%1];" : "=h"(h) : "r"(addr));
    return __half2float(__ushort_as_half(h));
}

#define SMEM_SZ 98304

// ======================= fp16 HMMA GEMM =====================================
// EPI 0: fp32 C           EPI 1: half Cb
// EPI 2: qu=h((c+u)*0.125), qv=h((c+v)*0.125)   (scale folded for attention)
// EPI 3: bias+relu -> half Cb          EPI 4: bias -> fp32 C
template<int EPI>
__global__ void __launch_bounds__(256)
hmma_gemm(const __half* __restrict__ A,
          const __half* __restrict__ Bt,
          float* __restrict__ C,
          __half* __restrict__ Cb,
          __half* __restrict__ Cb2,
          const float* __restrict__ ub,
          const float* __restrict__ vb,
          const float* __restrict__ bias,
          int Mreal, int N, int K)
{
    extern __shared__ __align__(1024) char smem[];
    uint32_t sb = smem_u32(smem);
    int tid = threadIdx.x;
    int wid = tid >> 5, lane = tid & 31;
    int n0 = blockIdx.x * 128, m0 = blockIdx.y * 128;
    int NC = K >> 6;
    int wm = (wid >> 2) * 64;
    int wn = (wid & 3) * 32;

    float acc[4][4][4];
    #pragma unroll
    for (int mt = 0; mt < 4; mt++)
        #pragma unroll
        for (int nt = 0; nt < 4; nt++)
            #pragma unroll
            for (int q = 0; q < 4; q++) acc[mt][nt][q] = 0.f;

    const int lr = tid >> 3;
    const int lc = tid & 7;
    auto load_stage = [&](int st, int cc) {
        uint32_t sa = sb + st * 32768;
        const __half* pa = A  + (size_t)(m0 + lr) * K + cc * 64 + lc * 8;
        const __half* pb = Bt + (size_t)(n0 + lr) * K + cc * 64 + lc * 8;
        #pragma unroll
        for (int i = 0; i < 4; i++) {
            int row = lr + i * 32;
            uint32_t off = row * 128 + ((lc ^ (row & 7)) * 16);
            cp16(sa + off,         pa);
            cp16(sa + 16384 + off, pb);
            pa += (size_t)32 * K;
            pb += (size_t)32 * K;
        }
        cp_commit();
    };

    load_stage(0, 0);
    load_stage(1, 1);

    for (int cc = 0; cc < NC; cc++) {
        if (cc + 2 < NC) cp_wait1(); else cp_wait0();
        __syncthreads();
        if (cc + 2 < NC) load_stage((cc + 2) % 3, cc + 2);

        uint32_t sa  = sb + (cc % 3) * 32768;
        uint32_t sbb = sa + 16384;
        #pragma unroll
        for (int k16 = 0; k16 < 4; k16++) {
            uint32_t a[4][4], b[4][2];
            #pragma unroll
            for (int mt = 0; mt < 4; mt++) {
                int r  = wm + mt * 16 + (lane & 15);
                int kc = 2 * k16 + ((lane >> 4) & 1);
                ldmA(a[mt], sa + r * 128 + ((kc ^ (r & 7)) * 16));
            }
            #pragma unroll
            for (int nt = 0; nt < 4; nt++) {
                int r  = wn + nt * 8 + (lane & 7);
                int kc = 2 * k16 + ((lane >> 3) & 1);
                ldmB(b[nt], sbb + r * 128 + ((kc ^ (r & 7)) * 16));
            }
            #pragma unroll
            for (int mt = 0; mt < 4; mt++)
                #pragma unroll
                for (int nt = 0; nt < 4; nt++)
                    mmaF16(acc[mt][nt], a[mt], b[nt]);
        }
    }
    __syncthreads();

    float* tile = (float*)smem;
    #pragma unroll
    for (int mt = 0; mt < 4; mt++) {
        #pragma unroll
        for (int nt = 0; nt < 4; nt++) {
            int r0  = wm + mt * 16 + (lane >> 2);
            int col = wn + nt * 8 + (lane & 3) * 2;
            tile[r0 * 132 + col]           = acc[mt][nt][0];
            tile[r0 * 132 + col + 1]       = acc[mt][nt][1];
            tile[(r0 + 8) * 132 + col]     = acc[mt][nt][2];
            tile[(r0 + 8) * 132 + col + 1] = acc[mt][nt][3];
        }
    }
    __syncthreads();

    #pragma unroll
    for (int j = 0; j < 16; j++) {
        int idx = tid + j * 256;
        int rr = idx >> 5, c4 = idx & 31;
        float4 v = *(const float4*)(tile + rr * 132 + c4 * 4);
        int grow = m0 + rr;
        int gcol = n0 + c4 * 4;
        if (grow >= Mreal) continue;
        if (EPI == 0) {
            *(float4*)(C + (size_t)grow * N + gcol) = v;
        } else if (EPI == 1) {
            __half2* p = (__half2*)(Cb + (size_t)grow * N + gcol);
            p[0] = __halves2half2(__float2half_rn(v.x), __float2half_rn(v.y));
            p[1] = __halves2half2(__float2half_rn(v.z), __float2half_rn(v.w));
        } else if (EPI == 2) {
            float u0 = ub[gcol], u1 = ub[gcol + 1], u2 = ub[gcol + 2], u3 = ub[gcol + 3];
            float w0 = vb[gcol], w1 = vb[gcol + 1], w2 = vb[gcol + 2], w3 = vb[gcol + 3];
            __half2* pu = (__half2*)(Cb + (size_t)grow * N + gcol);
            __half2* pv = (__half2*)(Cb2 + (size_t)grow * N + gcol);
            pu[0] = __halves2half2(__float2half_rn((v.x + u0) * 0.125f), __float2half_rn((v.y + u1) * 0.125f));
            pu[1] = __halves2half2(__float2half_rn((v.z + u2) * 0.125f), __float2half_rn((v.w + u3) * 0.125f));
            pv[0] = __halves2half2(__float2half_rn((v.x + w0) * 0.125f), __float2half_rn((v.y + w1) * 0.125f));
            pv[1] = __halves2half2(__float2half_rn((v.z + w2) * 0.125f), __float2half_rn((v.w + w3) * 0.125f));
        } else if (EPI == 3) {
            v.x = fmaxf(v.x + bias[gcol], 0.f);     v.y = fmaxf(v.y + bias[gcol + 1], 0.f);
            v.z = fmaxf(v.z + bias[gcol + 2], 0.f); v.w = fmaxf(v.w + bias[gcol + 3], 0.f);
            __half2* p = (__half2*)(Cb + (size_t)grow * N + gcol);
            p[0] = __halves2half2(__float2half_rn(v.x), __float2half_rn(v.y));
            p[1] = __halves2half2(__float2half_rn(v.z), __float2half_rn(v.w));
        } else {
            v.x += bias[gcol]; v.y += bias[gcol + 1];
            v.z += bias[gcol + 2]; v.w += bias[gcol + 3];
            *(float4*)(C + (size_t)grow * N + gcol) = v;
        }
    }
}

// ======================= fused flash attention ==============================
// Block: 128 threads (4 warps), one (i-tile of 64 rows, b, h).
// smem: [0, 57344)   R band 448 rows x 128B  ->  overwritten in place by T^T
//       [57344)      QU tile 64x128B
//       [65536)      QV tile 64x128B
//       [73728)      KV stage0 (K 8KB, V 8KB)
//       [90112)      KV stage1
#define FA_BAND 0
#define FA_QU   57344
#define FA_QV   65536
#define FA_KV   73728
#define FA_SMEM 106496

__global__ void __launch_bounds__(128)
flash_attn(const __half* __restrict__ qu,
           const __half* __restrict__ qv,
           const __half* __restrict__ kh,
           const __half* __restrict__ vh,
           const __half* __restrict__ rh,
           __half* __restrict__ outh)
{
    extern __shared__ __align__(1024) char smem[];
    uint32_t sb = smem_u32(smem);
    int tid = threadIdx.x;
    int wid = tid >> 5, lane = tid & 31;
    int i0 = blockIdx.x * 64;
    int h = blockIdx.y, b = blockIdx.z;
    int wm = wid * 16;

    // ---- async loads: KV(0), KV(1), then R band + QU + QV (3 groups) ----
    auto load_kv = [&](int st, int jt) {
        uint32_t sk = sb + FA_KV + st * 16384;
        #pragma unroll
        for (int t4 = 0; t4 < 4; t4++) {
            int idx = tid * 4 + t4;             // 512 chunks per tile
            int row = idx >> 3, lc = idx & 7;
            uint32_t off = row * 128 + ((lc ^ (row & 7)) * 16);
            size_t g = ((size_t)(b * Ss + jt * 64 + row)) * Dd + h * 64 + lc * 8;
            cp16(sk + off,        kh + g);
            cp16(sk + 8192 + off, vh + g);
        }
        cp_commit();
    };
    load_kv(0, 0);
    load_kv(1, 1);
    {
        // R band: rows i0 .. i0+446 (447 rows, 3576 chunks)
        for (int idx = tid; idx < 3576; idx += 128) {
            int row = idx >> 3, lc = idx & 7;
            uint32_t off = row * 128 + ((lc ^ (row & 7)) * 16);
            cp16(sb + FA_BAND + off, rh + (size_t)(i0 + row) * Dd + h * 64 + lc * 8);
        }
        #pragma unroll
        for (int t4 = 0; t4 < 4; t4++) {
            int idx = tid * 4 + t4;
            int row = idx >> 3, lc = idx & 7;
            uint32_t off = row * 128 + ((lc ^ (row & 7)) * 16);
            size_t g = ((size_t)(b * Ss + i0 + row)) * Dd + h * 64 + lc * 8;
            cp16(sb + FA_QU + off, qu + g);
            cp16(sb + FA_QV + off, qv + g);
        }
        cp_commit();
    }
    cp_wait0();
    __syncthreads();

    // ---- hoist QU / QV A-fragments ----
    uint32_t qa[4][4], va[4][4];
    #pragma unroll
    for (int k16 = 0; k16 < 4; k16++) {
        int rA = wm + (lane & 15);
        int kcA = 2 * k16 + ((lane >> 4) & 1);
        ldmA(qa[k16], sb + FA_QU + rA * 128 + ((kcA ^ (rA & 7)) * 16));
        ldmA(va[k16], sb + FA_QV + rA * 128 + ((kcA ^ (rA & 7)) * 16));
    }

    // ---- T = QV @ Rband^T, stored transposed in place over the band ----
    // T(di, tc) lives at band (row tc, col di) as fp16.
    for (int c = 0; c < 7; c++) {
        float tacc[8][4];
        #pragma unroll
        for (int nt = 0; nt < 8; nt++)
            #pragma unroll
            for (int q = 0; q < 4; q++) tacc[nt][q] = 0.f;
        #pragma unroll
        for (int k16 = 0; k16 < 4; k16++) {
            #pragma unroll
            for (int nt = 0; nt < 8; nt++) {
                uint32_t b2[2];
                int r  = c * 64 + nt * 8 + (lane & 7);
                int kc = 2 * k16 + ((lane >> 3) & 1);
                ldmB(b2, sb + FA_BAND + r * 128 + ((kc ^ (r & 7)) * 16));
                mmaF16(tacc[nt], va[k16], b2);
            }
        }
        __syncthreads();
        int di0 = wm + (lane >> 2);
        int di1 = di0 + 8;
        #pragma unroll
        for (int nt = 0; nt < 8; nt++) {
            int tc = c * 64 + nt * 8 + (lane & 3) * 2;
            stsh(sb + FA_BAND + tc * 128       + (((di0 >> 3) ^ (tc & 7)) * 16)       + (di0 & 7) * 2, tacc[nt][0]);
            stsh(sb + FA_BAND + (tc + 1) * 128 + (((di0 >> 3) ^ ((tc + 1) & 7)) * 16) + (di0 & 7) * 2, tacc[nt][1]);
            stsh(sb + FA_BAND + tc * 128       + (((di1 >> 3) ^ (tc & 7)) * 16)       + (di1 & 7) * 2, tacc[nt][2]);
            stsh(sb + FA_BAND + (tc + 1) * 128 + (((di1 >> 3) ^ ((tc + 1) & 7)) * 16) + (di1 & 7) * 2, tacc[nt][3]);
        }
        __syncthreads();
    }

    // ---- online-softmax flash loop over 6 j-tiles ----
    float m0 = -1e30f, m1 = -1e30f, l0 = 0.f, l1 = 0.f;
    float accO[8][4];
    #pragma unroll
    for (int nf = 0; nf < 8; nf++)
        #pragma unroll
        for (int q = 0; q < 4; q++) accO[nf][q] = 0.f;

    int di0 = wm + (lane >> 2);
    int di1 = di0 + 8;

    for (int jt = 0; jt < 6; jt++) {
        if (jt > 0) {
            if (jt < 5) cp_wait1(); else cp_wait0();
            __syncthreads();
        }
        uint32_t sk = sb + FA_KV + (jt & 1) * 16384;
        uint32_t sv = sk + 8192;

        // content scores: QU @ K^T
        float s[8][4];
        #pragma unroll
        for (int nt = 0; nt < 8; nt++)
            #pragma unroll
            for (int q = 0; q < 4; q++) s[nt][q] = 0.f;
        #pragma unroll
        for (int k16 = 0; k16 < 4; k16++) {
            #pragma unroll
            for (int nt = 0; nt < 8; nt++) {
                uint32_t b2[2];
                int r  = nt * 8 + (lane & 7);
                int kc = 2 * k16 + ((lane >> 3) & 1);
                ldmB(b2, sk + r * 128 + ((kc ^ (r & 7)) * 16));
                mmaF16(s[nt], qa[k16], b2);
            }
        }
        // + relative term gathered from T (band rows)
        #pragma unroll
        for (int nt = 0; nt < 8; nt++) {
            int dj = jt * 64 + nt * 8 + (lane & 3) * 2;
            int t0 = di0 - dj + 383;
            int t1 = t0 + 8;                      // row di1
            s[nt][0] += ldsh(sb + FA_BAND + t0 * 128       + (((di0 >> 3) ^ (t0 & 7)) * 16)       + (di0 & 7) * 2);
            s[nt][1] += ldsh(sb + FA_BAND + (t0 - 1) * 128 + (((di0 >> 3) ^ ((t0 - 1) & 7)) * 16) + (di0 & 7) * 2);
            s[nt][2] += ldsh(sb + FA_BAND + t1 * 128       + (((di1 >> 3) ^ (t1 & 7)) * 16)       + (di1 & 7) * 2);
            s[nt][3] += ldsh(sb + FA_BAND + (t1 - 1) * 128 + (((di1 >> 3) ^ ((t1 - 1) & 7)) * 16) + (di1 & 7) * 2);
        }

        // online softmax
        float mx0 = -1e30f, mx1 = -1e30f;
        #pragma unroll
        for (int nt = 0; nt < 8; nt++) {
            mx0 = fmaxf(mx0, fmaxf(s[nt][0], s[nt][1]));
            mx1 = fmaxf(mx1, fmaxf(s[nt][2], s[nt][3]));
        }
        mx0 = fmaxf(mx0, __shfl_xor_sync(~0u, mx0, 1));
        mx0 = fmaxf(mx0, __shfl_xor_sync(~0u, mx0, 2));
        mx1 = fmaxf(mx1, __shfl_xor_sync(~0u, mx1, 1));
        mx1 = fmaxf(mx1, __shfl_xor_sync(~0u, mx1, 2));
        float m0n = fmaxf(m0, mx0), m1n = fmaxf(m1, mx1);
        float c0 = __expf(m0 - m0n), c1 = __expf(m1 - m1n);
        m0 = m0n; m1 = m1n;

        float rs0 = 0.f, rs1 = 0.f;
        #pragma unroll
        for (int nt = 0; nt < 8; nt++) {
            s[nt][0] = __expf(s[nt][0] - m0); s[nt][1] = __expf(s[nt][1] - m0);
            s[nt][2] = __expf(s[nt][2] - m1); s[nt][3] = __expf(s[nt][3] - m1);
            rs0 += s[nt][0] + s[nt][1];
            rs1 += s[nt][2] + s[nt][3];
        }
        rs0 += __shfl_xor_sync(~0u, rs0, 1); rs0 += __shfl_xor_sync(~0u, rs0, 2);
        rs1 += __shfl_xor_sync(~0u, rs1, 1); rs1 += __shfl_xor_sync(~0u, rs1, 2);
        l0 = l0 * c0 + rs0;
        l1 = l1 * c1 + rs1;
        #pragma unroll
        for (int nf = 0; nf < 8; nf++) {
            accO[nf][0] *= c0; accO[nf][1] *= c0;
            accO[nf][2] *= c1; accO[nf][3] *= c1;
        }

        // p -> A fragments
        uint32_t pa_[4][4];
        #pragma unroll
        for (int kc = 0; kc < 4; kc++) {
            __half2 h0 = __halves2half2(__float2half_rn(s[2*kc][0]),   __float2half_rn(s[2*kc][1]));
            __half2 h1 = __halves2half2(__float2half_rn(s[2*kc][2]),   __float2half_rn(s[2*kc][3]));
            __half2 h2 = __halves2half2(__float2half_rn(s[2*kc+1][0]), __float2half_rn(s[2*kc+1][1]));
            __half2 h3 = __halves2half2(__float2half_rn(s[2*kc+1][2]), __float2half_rn(s[2*kc+1][3]));
            pa_[kc][0] = *(uint32_t*)&h0; pa_[kc][1] = *(uint32_t*)&h1;
            pa_[kc][2] = *(uint32_t*)&h2; pa_[kc][3] = *(uint32_t*)&h3;
        }
        // accO += p @ V
        #pragma unroll
        for (int kc = 0; kc < 4; kc++) {
            #pragma unroll
            for (int nf2 = 0; nf2 < 4; nf2++) {
                uint32_t bb[4];
                int krow = kc * 16 + (lane & 15);
                int ncol = nf2 * 16 + ((lane >> 4) * 8);
                ldmT4(bb, sv + krow * 128 + (((ncol >> 3) ^ (krow & 7)) * 16));
                mmaF16(accO[nf2 * 2],     pa_[kc], bb);
                mmaF16(accO[nf2 * 2 + 1], pa_[kc], bb + 2);
            }
        }
        __syncthreads();
        if (jt + 2 < 6) load_kv(jt & 1, jt + 2);
    }

    // ---- epilogue: normalize, write fp16 ----
    float inv0 = 1.f / l0, inv1 = 1.f / l1;
    #pragma unroll
    for (int nf = 0; nf < 8; nf++) {
        int col = nf * 8 + (lane & 3) * 2;
        size_t o0 = ((size_t)(b * Ss + i0 + di0)) * Dd + h * 64 + col;
        size_t o1 = ((size_t)(b * Ss + i0 + di1)) * Dd + h * 64 + col;
        *(__half2*)(outh + o0) =
            __halves2half2(__float2half_rn(accO[nf][0] * inv0), __float2half_rn(accO[nf][1] * inv0));
        *(__half2*)(outh + o1) =
            __halves2half2(__float2half_rn(accO[nf][2] * inv1), __float2half_rn(accO[nf][3] * inv1));
    }
}

// ======================= conversions =======================================
__global__ void conv_f16(const float* __restrict__ in, __half* __restrict__ out,
                         int Mreal, int K)
{
    size_t idx = (size_t)blockIdx.x * 256 + threadIdx.x;
    int rowi = (int)(idx / K);
    float vv = (rowi < Mreal) ? in[idx] : 0.f;
    out[idx] = __float2half_rn(vv);
}

__global__ void wt5_f16(const float* __restrict__ W0, const float* __restrict__ W1,
                        const float* __restrict__ W2, const float* __restrict__ W3,
                        const float* __restrict__ W4,
                        __half* __restrict__ O0, __half* __restrict__ O1,
                        __half* __restrict__ O2, __half* __restrict__ O3,
                        __half* __restrict__ O4)
{
    const float* W; __half* O;
    switch (blockIdx.z) {
        case 0: W = W0; O = O0; break;
        case 1: W = W1; O = O1; break;
        case 2: W = W2; O = O2; break;
        case 3: W = W3; O = O3; break;
        default: W = W4; O = O4; break;
    }
    __shared__ float t[32][33];
    int k0 = blockIdx.x * 32, n0 = blockIdx.y * 32;
    int tx = threadIdx.x, ty = threadIdx.y;
    for (int i = ty; i < 32; i += 8)
        t[i][tx] = W[(size_t)(k0 + i) * Dd + n0 + tx];
    __syncthreads();
    for (int i = ty; i < 32; i += 8)
        O[(size_t)(n0 + i) * Dd + k0 + tx] = __float2half_rn(t[tx][i]);
}

__global__ void wt_f16(const float* __restrict__ W, __half* __restrict__ out,
                       int K, int N)
{
    __shared__ float t[32][33];
    int k0 = blockIdx.x * 32, n0 = blockIdx.y * 32;
    int tx = threadIdx.x, ty = threadIdx.y;
    for (int i = ty; i < 32; i += 8)
        t[i][tx] = W[(size_t)(k0 + i) * N + n0 + tx];
    __syncthreads();
    for (int i = ty; i < 32; i += 8)
        out[(size_t)(n0 + i) * K + k0 + tx] = __float2half_rn(t[tx][i]);
}

// ======================= LayerNorm(a+b) ====================================
template<bool H16OUT>
__global__ void add_ln_kernel(const float* __restrict__ a,
                              const float* __restrict__ bsrc,
                              const float* __restrict__ g,
                              const float* __restrict__ be,
                              float* __restrict__ out,
                              __half* __restrict__ outh)
{
    size_t rowi = blockIdx.x;
    const float* pa = a + rowi * Dd;
    const float* pb = bsrc + rowi * Dd;
    int t = threadIdx.x;

    float x0 = pa[t] + pb[t];
    float x1 = pa[t + 256] + pb[t + 256];
    float x2 = pa[t + 512] + pb[t + 512];

    float s  = x0 + x1 + x2;
    float s2 = x0 * x0 + x1 * x1 + x2 * x2;
    #pragma unroll
    for (int o = 16; o > 0; o >>= 1) {
        s  += __shfl_xor_sync(~0u, s, o);
        s2 += __shfl_xor_sync(~0u, s2, o);
    }
    __shared__ float r1[8], r2s[8];
    if ((t & 31) == 0) { r1[t >> 5] = s; r2s[t >> 5] = s2; }
    __syncthreads();
    if (t < 32) {
        float a1 = (t < 8) ? r1[t] : 0.f;
        float a2 = (t < 8) ? r2s[t] : 0.f;
        #pragma unroll
        for (int o = 4; o > 0; o >>= 1) {
            a1 += __shfl_xor_sync(~0u, a1, o);
            a2 += __shfl_xor_sync(~0u, a2, o);
        }
        if (t == 0) { r1[0] = a1; r2s[0] = a2; }
    }
    __syncthreads();
    float mean = r1[0] * (1.f / 768.f);
    float var  = r2s[0] * (1.f / 768.f) - mean * mean;
    float inv  = rsqrtf(var + 1e-5f);

    float y0 = (x0 - mean) * inv * g[t]       + be[t];
    float y1 = (x1 - mean) * inv * g[t + 256] + be[t + 256];
    float y2 = (x2 - mean) * inv * g[t + 512] + be[t + 512];

    float* po = out + rowi * Dd;
    po[t] = y0; po[t + 256] = y1; po[t + 512] = y2;
    if (H16OUT) {
        __half* ph = outh + rowi * Dd;
        ph[t]       = __float2half_rn(y0);
        ph[t + 256] = __float2half_rn(y1);
        ph[t + 512] = __float2half_rn(y2);
    }
}

// ======================= launch ============================================
extern "C" void kernel_launch(void* const* d_in, const int* in_sizes, int n_in,
                              void* d_out, int out_size)
{
    const float* x    = (const float*)d_in[0];
    const float* pe   = (const float*)d_in[1];
    const float* Wq   = (const float*)d_in[2];
    const float* Wk   = (const float*)d_in[3];
    const float* Wv   = (const float*)d_in[4];
    const float* Wr   = (const float*)d_in[5];
    const float* u    = (const float*)d_in[6];
    const float* v    = (const float*)d_in[7];
    const float* Wo   = (const float*)d_in[8];
    const float* ln1g = (const float*)d_in[9];
    const float* ln1b = (const float*)d_in[10];
    const float* ln2g = (const float*)d_in[11];
    const float* ln2b = (const float*)d_in[12];
    const float* W1   = (const float*)d_in[13];
    const float* b1   = (const float*)d_in[14];
    const float* W2   = (const float*)d_in[15];
    const float* b2   = (const float*)d_in[16];
    float* out = (float*)d_out;

    float *go, *gx1, *gf2;
    __half *gxh, *gpeh, *gqu, *gqv, *gkh, *gvh, *grh, *gattnh, *gx1h, *gffh;
    __half *gwqt, *gwkt, *gwvt, *gwrt, *gwot, *gw1t, *gw2t;
    cudaGetSymbolAddress((void**)&go, g_o);
    cudaGetSymbolAddress((void**)&gx1, g_x1);   cudaGetSymbolAddress((void**)&gf2, g_f2);
    cudaGetSymbolAddress((void**)&gxh, g_xh);   cudaGetSymbolAddress((void**)&gpeh, g_peh);
    cudaGetSymbolAddress((void**)&gqu, g_qu);   cudaGetSymbolAddress((void**)&gqv, g_qv);
    cudaGetSymbolAddress((void**)&gkh, g_kh);   cudaGetSymbolAddress((void**)&gvh, g_vh);
    cudaGetSymbolAddress((void**)&grh, g_rh);
    cudaGetSymbolAddress((void**)&gattnh, g_attnh);
    cudaGetSymbolAddress((void**)&gx1h, g_x1h); cudaGetSymbolAddress((void**)&gffh, g_ffh);
    cudaGetSymbolAddress((void**)&gwqt, g_wqt); cudaGetSymbolAddress((void**)&gwkt, g_wkt);
    cudaGetSymbolAddress((void**)&gwvt, g_wvt); cudaGetSymbolAddress((void**)&gwrt, g_wrt);
    cudaGetSymbolAddress((void**)&gwot, g_wot);
    cudaGetSymbolAddress((void**)&gw1t, g_w1t); cudaGetSymbolAddress((void**)&gw2t, g_w2t);

    cudaFuncSetAttribute(hmma_gemm<0>, cudaFuncAttributeMaxDynamicSharedMemorySize, SMEM_SZ);
    cudaFuncSetAttribute(hmma_gemm<1>, cudaFuncAttributeMaxDynamicSharedMemorySize, SMEM_SZ);
    cudaFuncSetAttribute(hmma_gemm<2>, cudaFuncAttributeMaxDynamicSharedMemorySize, SMEM_SZ);
    cudaFuncSetAttribute(hmma_gemm<3>, cudaFuncAttributeMaxDynamicSharedMemorySize, SMEM_SZ);
    cudaFuncSetAttribute(hmma_gemm<4>, cudaFuncAttributeMaxDynamicSharedMemorySize, SMEM_SZ);
    cudaFuncSetAttribute(flash_attn,   cudaFuncAttributeMaxDynamicSharedMemorySize, FA_SMEM);

    // conversions
    conv_f16<<<(MM * Dd) / 256, 256>>>(x, gxh, MM, Dd);
    conv_f16<<<(768 * Dd) / 256, 256>>>(pe, gpeh, RROWS, Dd);
    dim3 tb(32, 8);
    wt5_f16<<<dim3(24, 24, 5), tb>>>(Wq, Wk, Wv, Wr, Wo, gwqt, gwkt, gwvt, gwrt, gwot);
    wt_f16<<<dim3(24, 96), tb>>>(W1, gw1t, Dd, FFf);
    wt_f16<<<dim3(96, 24), tb>>>(W2, gw2t, FFf, Dd);

    // projections (Q epilogue folds +u/+v and the 1/8 score scale)
    dim3 gProj(6, 48);
    hmma_gemm<2><<<gProj, 256, SMEM_SZ>>>(gxh, gwqt, nullptr, gqu, gqv, u, v, nullptr, MM, Dd, Dd);
    hmma_gemm<1><<<gProj, 256, SMEM_SZ>>>(gxh, gwkt, nullptr, gkh, nullptr, nullptr, nullptr, nullptr, MM, Dd, Dd);
    hmma_gemm<1><<<gProj, 256, SMEM_SZ>>>(gxh, gwvt, nullptr, gvh, nullptr, nullptr, nullptr, nullptr, MM, Dd, Dd);
    hmma_gemm<1><<<dim3(6, 6), 256, SMEM_SZ>>>(gpeh, gwrt, nullptr, grh, nullptr, nullptr, nullptr, nullptr, RROWS, Dd, Dd);

    // fused attention (scores + softmax + p@V)
    flash_attn<<<dim3(6, Hh, Bb), 128, FA_SMEM>>>(gqu, gqv, gkh, gvh, grh, gattnh);

    hmma_gemm<0><<<gProj, 256, SMEM_SZ>>>(gattnh, gwot, go, nullptr, nullptr, nullptr, nullptr, nullptr, MM, Dd, Dd);

    add_ln_kernel<true><<<MM, 256>>>(x, go, ln1g, ln1b, gx1, gx1h);

    // FFN (fp16, fp32 accum)
    hmma_gemm<3><<<dim3(24, 48), 256, SMEM_SZ>>>(gx1h, gw1t, nullptr, gffh, nullptr, nullptr, nullptr, b1, MM, FFf, Dd);
    hmma_gemm<4><<<dim3(6, 48), 256, SMEM_SZ>>>(gffh, gw2t, gf2, nullptr, nullptr, nullptr, nullptr, b2, MM, Dd, FFf);

    add_ln_kernel<false><<<MM, 256>>>(gx1, gf2, ln2g, ln2b, out, nullptr);

    (void)in_sizes; (void)n_in; (void)out_size;
}

// round 16
// speedup vs baseline: 9.7337x; 1.1096x over previous
#include <cuda_runtime.h>
#include <cuda_fp16.h>
#include <cstdint>

#define Bb 16
#define Ss 384
#define Dd 768
#define Hh 12
#define FFf 3072
#define MM (Bb*Ss)          // 6144
#define RROWS (2*Ss-1)      // 767

// ---------------- scratch ----------------
__device__ float g_o [MM*Dd];
__device__ float g_x1[MM*Dd];
__device__ float g_f2[MM*Dd];

__device__ __half g_xh  [(size_t)MM*Dd];
__device__ __half g_peh [(size_t)768*Dd];
__device__ __half g_qu  [(size_t)MM*Dd];
__device__ __half g_qv  [(size_t)MM*Dd];
__device__ __half g_kh  [(size_t)MM*Dd];
__device__ __half g_vh  [(size_t)MM*Dd];
__device__ __half g_rh  [(size_t)768*Dd];
__device__ __half g_attnh[(size_t)MM*Dd];
__device__ __half g_x1h [(size_t)MM*Dd];
__device__ __half g_ffh [(size_t)MM*FFf];
__device__ __half g_wqt [(size_t)Dd*Dd];
__device__ __half g_wkt [(size_t)Dd*Dd];
__device__ __half g_wvt [(size_t)Dd*Dd];
__device__ __half g_wrt [(size_t)Dd*Dd];
__device__ __half g_wot [(size_t)Dd*Dd];
__device__ __half g_w1t [(size_t)FFf*Dd];
__device__ __half g_w2t [(size_t)Dd*FFf];

// ---------------- PTX helpers ----------------
__device__ __forceinline__ uint32_t smem_u32(const void* p) {
    return (uint32_t)__cvta_generic_to_shared(p);
}
__device__ __forceinline__ void cp16(uint32_t dst, const void* src) {
    asm volatile("cp.async.cg.shared.global [%0], [%1], 16;\n"
                 :: "r"(dst), "l"(__cvta_generic_to_global(src)));
}
__device__ __forceinline__ void cp_commit() { asm volatile("cp.async.commit_group;\n" ::: "memory"); }
__device__ __forceinline__ void cp_wait1()  { asm volatile("cp.async.wait_group 1;\n" ::: "memory"); }
__device__ __forceinline__ void cp_wait0()  { asm volatile("cp.async.wait_group 0;\n" ::: "memory"); }

__device__ __forceinline__ void ldmA(uint32_t* a, uint32_t addr) {
    asm volatile("ldmatrix.sync.aligned.m8n8.x4.shared.b16 {%0,%1,%2,%3}, [%4];"
                 : "=r"(a[0]), "=r"(a[1]), "=r"(a[2]), "=r"(a[3]) : "r"(addr));
}
__device__ __forceinline__ void ldmB(uint32_t* b, uint32_t addr) {
    asm volatile("ldmatrix.sync.aligned.m8n8.x2.shared.b16 {%0,%1}, [%2];"
                 : "=r"(b[0]), "=r"(b[1]) : "r"(addr));
}
__device__ __forceinline__ void ldmT4(uint32_t* b, uint32_t addr) {
    asm volatile("ldmatrix.sync.aligned.m8n8.x4.trans.shared.b16 {%0,%1,%2,%3}, [%4];"
                 : "=r"(b[0]), "=r"(b[1]), "=r"(b[2]), "=r"(b[3]) : "r"(addr));
}
__device__ __forceinline__ void mmaF16(float* d, const uint32_t* a, const uint32_t* b) {
    asm volatile("mma.sync.aligned.m16n8k16.row.col.f32.f16.f16.f32 "
                 "{%0,%1,%2,%3}, {%4,%5,%6,%7}, {%8,%9}, {%0,%1,%2,%3};"
                 : "+f"(d[0]), "+f"(d[1]), "+f"(d[2]), "+f"(d[3])
                 : "r"(a[0]), "r"(a[1]), "r"(a[2]), "r"(a[3]), "r"(b[0]), "r"(b[1]));
}
__device__ __forceinline__ void stsh(uint32_t addr, float v) {
    unsigned short h = __half_as_ushort(__float2half_rn(v));
    asm volatile("st.shared.u16 [%0], %1;" :: "r"(addr), "h"(h));
}
__device__ __forceinline__ float ldsh(uint32_t addr) {
    unsigned short h;
    asm volatile("ld.shared.u16 %0, [%1];" : "=h"(h) : "r"(addr));
    return __half2float(__ushort_as_half(h));
}

#define SMEM_SZ 98304

// ======================= GEMM mainloop (shared macro-ish inline) ============
// Computes 128x128 fp32 acc for C = A(Mx K)*Bt(N x K)^T; tile staged to smem.
__device__ __forceinline__ void gemm_core(uint32_t sb, const __half* A, const __half* Bt,
                                          int m0, int n0, int K, int tid, int wid, int lane,
                                          float acc[4][4][4])
{
    int NC = K >> 6;
    int wm = (wid >> 2) * 64;
    int wn = (wid & 3) * 32;
    const int lr = tid >> 3;
    const int lc = tid & 7;

    auto load_stage = [&](int st, int cc) {
        uint32_t sa = sb + st * 32768;
        const __half* pa = A  + (size_t)(m0 + lr) * K + cc * 64 + lc * 8;
        const __half* pb = Bt + (size_t)(n0 + lr) * K + cc * 64 + lc * 8;
        #pragma unroll
        for (int i = 0; i < 4; i++) {
            int row = lr + i * 32;
            uint32_t off = row * 128 + ((lc ^ (row & 7)) * 16);
            cp16(sa + off,         pa);
            cp16(sa + 16384 + off, pb);
            pa += (size_t)32 * K;
            pb += (size_t)32 * K;
        }
        cp_commit();
    };

    load_stage(0, 0);
    load_stage(1, 1);

    for (int cc = 0; cc < NC; cc++) {
        if (cc + 2 < NC) cp_wait1(); else cp_wait0();
        __syncthreads();
        if (cc + 2 < NC) load_stage((cc + 2) % 3, cc + 2);

        uint32_t sa  = sb + (cc % 3) * 32768;
        uint32_t sbb = sa + 16384;
        #pragma unroll
        for (int k16 = 0; k16 < 4; k16++) {
            uint32_t a[4][4], b[4][2];
            #pragma unroll
            for (int mt = 0; mt < 4; mt++) {
                int r  = wm + mt * 16 + (lane & 15);
                int kc = 2 * k16 + ((lane >> 4) & 1);
                ldmA(a[mt], sa + r * 128 + ((kc ^ (r & 7)) * 16));
            }
            #pragma unroll
            for (int nt = 0; nt < 4; nt++) {
                int r  = wn + nt * 8 + (lane & 7);
                int kc = 2 * k16 + ((lane >> 3) & 1);
                ldmB(b[nt], sbb + r * 128 + ((kc ^ (r & 7)) * 16));
            }
            #pragma unroll
            for (int mt = 0; mt < 4; mt++)
                #pragma unroll
                for (int nt = 0; nt < 4; nt++)
                    mmaF16(acc[mt][nt], a[mt], b[nt]);
        }
    }
    __syncthreads();
}

__device__ __forceinline__ void acc_to_tile(char* smem, int wid, int lane, float acc[4][4][4])
{
    float* tile = (float*)smem;
    int wm = (wid >> 2) * 64;
    int wn = (wid & 3) * 32;
    #pragma unroll
    for (int mt = 0; mt < 4; mt++) {
        #pragma unroll
        for (int nt = 0; nt < 4; nt++) {
            int r0  = wm + mt * 16 + (lane >> 2);
            int col = wn + nt * 8 + (lane & 3) * 2;
            tile[r0 * 132 + col]           = acc[mt][nt][0];
            tile[r0 * 132 + col + 1]       = acc[mt][nt][1];
            tile[(r0 + 8) * 132 + col]     = acc[mt][nt][2];
            tile[(r0 + 8) * 132 + col + 1] = acc[mt][nt][3];
        }
    }
    __syncthreads();
}

// ======================= batched projection GEMM ============================
// z=0: xh@Wq -> qu=h((c+u)/8), qv=h((c+v)/8);  z=1: xh@Wk -> kh;
// z=2: xh@Wv -> vh;  z=3: peh@Wr -> rh (M=767)
__global__ void __launch_bounds__(256)
proj_gemm(const __half* __restrict__ xh, const __half* __restrict__ peh,
          const __half* __restrict__ wq, const __half* __restrict__ wk,
          const __half* __restrict__ wv, const __half* __restrict__ wr,
          __half* __restrict__ qu, __half* __restrict__ qv,
          __half* __restrict__ kh, __half* __restrict__ vh,
          __half* __restrict__ rh,
          const float* __restrict__ ub, const float* __restrict__ vb)
{
    extern __shared__ __align__(1024) char smem[];
    int z = blockIdx.z;
    int m0 = blockIdx.y * 128, n0 = blockIdx.x * 128;
    int Mreal = (z == 3) ? RROWS : MM;
    if (m0 >= Mreal) return;

    const __half* A  = (z == 3) ? peh : xh;
    const __half* Bt = (z == 0) ? wq : (z == 1) ? wk : (z == 2) ? wv : wr;

    uint32_t sb = smem_u32(smem);
    int tid = threadIdx.x;
    int wid = tid >> 5, lane = tid & 31;

    float acc[4][4][4];
    #pragma unroll
    for (int mt = 0; mt < 4; mt++)
        #pragma unroll
        for (int nt = 0; nt < 4; nt++)
            #pragma unroll
            for (int q = 0; q < 4; q++) acc[mt][nt][q] = 0.f;

    gemm_core(sb, A, Bt, m0, n0, Dd, tid, wid, lane, acc);
    acc_to_tile(smem, wid, lane, acc);

    float* tile = (float*)smem;
    #pragma unroll
    for (int j = 0; j < 16; j++) {
        int idx = tid + j * 256;
        int rr = idx >> 5, c4 = idx & 31;
        float4 v = *(const float4*)(tile + rr * 132 + c4 * 4);
        int grow = m0 + rr;
        int gcol = n0 + c4 * 4;
        if (grow >= Mreal) continue;
        if (z == 0) {
            float u0 = ub[gcol], u1 = ub[gcol + 1], u2 = ub[gcol + 2], u3 = ub[gcol + 3];
            float w0 = vb[gcol], w1 = vb[gcol + 1], w2 = vb[gcol + 2], w3 = vb[gcol + 3];
            __half2* pu = (__half2*)(qu + (size_t)grow * Dd + gcol);
            __half2* pv = (__half2*)(qv + (size_t)grow * Dd + gcol);
            pu[0] = __halves2half2(__float2half_rn((v.x + u0) * 0.125f), __float2half_rn((v.y + u1) * 0.125f));
            pu[1] = __halves2half2(__float2half_rn((v.z + u2) * 0.125f), __float2half_rn((v.w + u3) * 0.125f));
            pv[0] = __halves2half2(__float2half_rn((v.x + w0) * 0.125f), __float2half_rn((v.y + w1) * 0.125f));
            pv[1] = __halves2half2(__float2half_rn((v.z + w2) * 0.125f), __float2half_rn((v.w + w3) * 0.125f));
        } else {
            __half* dst = (z == 1) ? kh : (z == 2) ? vh : rh;
            __half2* p = (__half2*)(dst + (size_t)grow * Dd + gcol);
            p[0] = __halves2half2(__float2half_rn(v.x), __float2half_rn(v.y));
            p[1] = __halves2half2(__float2half_rn(v.z), __float2half_rn(v.w));
        }
    }
}

// ======================= fp16 HMMA GEMM (Wo / FFN) ==========================
// EPI 0: fp32 C    EPI 3: bias+relu -> half Cb    EPI 4: bias -> fp32 C
template<int EPI>
__global__ void __launch_bounds__(256)
hmma_gemm(const __half* __restrict__ A,
          const __half* __restrict__ Bt,
          float* __restrict__ C,
          __half* __restrict__ Cb,
          const float* __restrict__ bias,
          int Mreal, int N, int K)
{
    extern __shared__ __align__(1024) char smem[];
    uint32_t sb = smem_u32(smem);
    int tid = threadIdx.x;
    int wid = tid >> 5, lane = tid & 31;
    int n0 = blockIdx.x * 128, m0 = blockIdx.y * 128;

    float acc[4][4][4];
    #pragma unroll
    for (int mt = 0; mt < 4; mt++)
        #pragma unroll
        for (int nt = 0; nt < 4; nt++)
            #pragma unroll
            for (int q = 0; q < 4; q++) acc[mt][nt][q] = 0.f;

    gemm_core(sb, A, Bt, m0, n0, K, tid, wid, lane, acc);
    acc_to_tile(smem, wid, lane, acc);

    float* tile = (float*)smem;
    #pragma unroll
    for (int j = 0; j < 16; j++) {
        int idx = tid + j * 256;
        int rr = idx >> 5, c4 = idx & 31;
        float4 v = *(const float4*)(tile + rr * 132 + c4 * 4);
        int grow = m0 + rr;
        int gcol = n0 + c4 * 4;
        if (grow >= Mreal) continue;
        if (EPI == 0) {
            *(float4*)(C + (size_t)grow * N + gcol) = v;
        } else if (EPI == 3) {
            v.x = fmaxf(v.x + bias[gcol], 0.f);     v.y = fmaxf(v.y + bias[gcol + 1], 0.f);
            v.z = fmaxf(v.z + bias[gcol + 2], 0.f); v.w = fmaxf(v.w + bias[gcol + 3], 0.f);
            __half2* p = (__half2*)(Cb + (size_t)grow * N + gcol);
            p[0] = __halves2half2(__float2half_rn(v.x), __float2half_rn(v.y));
            p[1] = __halves2half2(__float2half_rn(v.z), __float2half_rn(v.w));
        } else {
            v.x += bias[gcol]; v.y += bias[gcol + 1];
            v.z += bias[gcol + 2]; v.w += bias[gcol + 3];
            *(float4*)(C + (size_t)grow * N + gcol) = v;
        }
    }
}

// ======================= fused flash attention ==============================
#define FA_BAND 0
#define FA_QU   57344
#define FA_QV   65536
#define FA_KV   73728
#define FA_SMEM 106496

__global__ void __launch_bounds__(128)
flash_attn(const __half* __restrict__ qu,
           const __half* __restrict__ qv,
           const __half* __restrict__ kh,
           const __half* __restrict__ vh,
           const __half* __restrict__ rh,
           __half* __restrict__ outh)
{
    extern __shared__ __align__(1024) char smem[];
    uint32_t sb = smem_u32(smem);
    int tid = threadIdx.x;
    int wid = tid >> 5, lane = tid & 31;
    int i0 = blockIdx.x * 64;
    int h = blockIdx.y, b = blockIdx.z;
    int wm = wid * 16;

    auto load_kv = [&](int st, int jt) {
        uint32_t sk = sb + FA_KV + st * 16384;
        #pragma unroll
        for (int t4 = 0; t4 < 4; t4++) {
            int idx = tid * 4 + t4;
            int row = idx >> 3, lc = idx & 7;
            uint32_t off = row * 128 + ((lc ^ (row & 7)) * 16);
            size_t g = ((size_t)(b * Ss + jt * 64 + row)) * Dd + h * 64 + lc * 8;
            cp16(sk + off,        kh + g);
            cp16(sk + 8192 + off, vh + g);
        }
        cp_commit();
    };
    load_kv(0, 0);
    load_kv(1, 1);
    {
        for (int idx = tid; idx < 3576; idx += 128) {
            int row = idx >> 3, lc = idx & 7;
            uint32_t off = row * 128 + ((lc ^ (row & 7)) * 16);
            cp16(sb + FA_BAND + off, rh + (size_t)(i0 + row) * Dd + h * 64 + lc * 8);
        }
        #pragma unroll
        for (int t4 = 0; t4 < 4; t4++) {
            int idx = tid * 4 + t4;
            int row = idx >> 3, lc = idx & 7;
            uint32_t off = row * 128 + ((lc ^ (row & 7)) * 16);
            size_t g = ((size_t)(b * Ss + i0 + row)) * Dd + h * 64 + lc * 8;
            cp16(sb + FA_QU + off, qu + g);
            cp16(sb + FA_QV + off, qv + g);
        }
        cp_commit();
    }
    cp_wait0();
    __syncthreads();

    uint32_t qa[4][4], va[4][4];
    #pragma unroll
    for (int k16 = 0; k16 < 4; k16++) {
        int rA = wm + (lane & 15);
        int kcA = 2 * k16 + ((lane >> 4) & 1);
        ldmA(qa[k16], sb + FA_QU + rA * 128 + ((kcA ^ (rA & 7)) * 16));
        ldmA(va[k16], sb + FA_QV + rA * 128 + ((kcA ^ (rA & 7)) * 16));
    }

    for (int c = 0; c < 7; c++) {
        float tacc[8][4];
        #pragma unroll
        for (int nt = 0; nt < 8; nt++)
            #pragma unroll
            for (int q = 0; q < 4; q++) tacc[nt][q] = 0.f;
        #pragma unroll
        for (int k16 = 0; k16 < 4; k16++) {
            #pragma unroll
            for (int nt = 0; nt < 8; nt++) {
                uint32_t b2[2];
                int r  = c * 64 + nt * 8 + (lane & 7);
                int kc = 2 * k16 + ((lane >> 3) & 1);
                ldmB(b2, sb + FA_BAND + r * 128 + ((kc ^ (r & 7)) * 16));
                mmaF16(tacc[nt], va[k16], b2);
            }
        }
        __syncthreads();
        int di0 = wm + (lane >> 2);
        int di1 = di0 + 8;
        #pragma unroll
        for (int nt = 0; nt < 8; nt++) {
            int tc = c * 64 + nt * 8 + (lane & 3) * 2;
            stsh(sb + FA_BAND + tc * 128       + (((di0 >> 3) ^ (tc & 7)) * 16)       + (di0 & 7) * 2, tacc[nt][0]);
            stsh(sb + FA_BAND + (tc + 1) * 128 + (((di0 >> 3) ^ ((tc + 1) & 7)) * 16) + (di0 & 7) * 2, tacc[nt][1]);
            stsh(sb + FA_BAND + tc * 128       + (((di1 >> 3) ^ (tc & 7)) * 16)       + (di1 & 7) * 2, tacc[nt][2]);
            stsh(sb + FA_BAND + (tc + 1) * 128 + (((di1 >> 3) ^ ((tc + 1) & 7)) * 16) + (di1 & 7) * 2, tacc[nt][3]);
        }
        __syncthreads();
    }

    float m0 = -1e30f, m1 = -1e30f, l0 = 0.f, l1 = 0.f;
    float accO[8][4];
    #pragma unroll
    for (int nf = 0; nf < 8; nf++)
        #pragma unroll
        for (int q = 0; q < 4; q++) accO[nf][q] = 0.f;

    int di0 = wm + (lane >> 2);
    int di1 = di0 + 8;

    for (int jt = 0; jt < 6; jt++) {
        if (jt > 0) {
            if (jt < 5) cp_wait1(); else cp_wait0();
            __syncthreads();
        }
        uint32_t sk = sb + FA_KV + (jt & 1) * 16384;
        uint32_t sv = sk + 8192;

        float s[8][4];
        #pragma unroll
        for (int nt = 0; nt < 8; nt++)
            #pragma unroll
            for (int q = 0; q < 4; q++) s[nt][q] = 0.f;
        #pragma unroll
        for (int k16 = 0; k16 < 4; k16++) {
            #pragma unroll
            for (int nt = 0; nt < 8; nt++) {
                uint32_t b2[2];
                int r  = nt * 8 + (lane & 7);
                int kc = 2 * k16 + ((lane >> 3) & 1);
                ldmB(b2, sk + r * 128 + ((kc ^ (r & 7)) * 16));
                mmaF16(s[nt], qa[k16], b2);
            }
        }
        #pragma unroll
        for (int nt = 0; nt < 8; nt++) {
            int dj = jt * 64 + nt * 8 + (lane & 3) * 2;
            int t0 = di0 - dj + 383;
            int t1 = t0 + 8;
            s[nt][0] += ldsh(sb + FA_BAND + t0 * 128       + (((di0 >> 3) ^ (t0 & 7)) * 16)       + (di0 & 7) * 2);
            s[nt][1] += ldsh(sb + FA_BAND + (t0 - 1) * 128 + (((di0 >> 3) ^ ((t0 - 1) & 7)) * 16) + (di0 & 7) * 2);
            s[nt][2] += ldsh(sb + FA_BAND + t1 * 128       + (((di1 >> 3) ^ (t1 & 7)) * 16)       + (di1 & 7) * 2);
            s[nt][3] += ldsh(sb + FA_BAND + (t1 - 1) * 128 + (((di1 >> 3) ^ ((t1 - 1) & 7)) * 16) + (di1 & 7) * 2);
        }

        float mx0 = -1e30f, mx1 = -1e30f;
        #pragma unroll
        for (int nt = 0; nt < 8; nt++) {
            mx0 = fmaxf(mx0, fmaxf(s[nt][0], s[nt][1]));
            mx1 = fmaxf(mx1, fmaxf(s[nt][2], s[nt][3]));
        }
        mx0 = fmaxf(mx0, __shfl_xor_sync(~0u, mx0, 1));
        mx0 = fmaxf(mx0, __shfl_xor_sync(~0u, mx0, 2));
        mx1 = fmaxf(mx1, __shfl_xor_sync(~0u, mx1, 1));
        mx1 = fmaxf(mx1, __shfl_xor_sync(~0u, mx1, 2));
        float m0n = fmaxf(m0, mx0), m1n = fmaxf(m1, mx1);
        float c0 = __expf(m0 - m0n), c1 = __expf(m1 - m1n);
        m0 = m0n; m1 = m1n;

        float rs0 = 0.f, rs1 = 0.f;
        #pragma unroll
        for (int nt = 0; nt < 8; nt++) {
            s[nt][0] = __expf(s[nt][0] - m0); s[nt][1] = __expf(s[nt][1] - m0);
            s[nt][2] = __expf(s[nt][2] - m1); s[nt][3] = __expf(s[nt][3] - m1);
            rs0 += s[nt][0] + s[nt][1];
            rs1 += s[nt][2] + s[nt][3];
        }
        rs0 += __shfl_xor_sync(~0u, rs0, 1); rs0 += __shfl_xor_sync(~0u, rs0, 2);
        rs1 += __shfl_xor_sync(~0u, rs1, 1); rs1 += __shfl_xor_sync(~0u, rs1, 2);
        l0 = l0 * c0 + rs0;
        l1 = l1 * c1 + rs1;
        #pragma unroll
        for (int nf = 0; nf < 8; nf++) {
            accO[nf][0] *= c0; accO[nf][1] *= c0;
            accO[nf][2] *= c1; accO[nf][3] *= c1;
        }

        uint32_t pa_[4][4];
        #pragma unroll
        for (int kc = 0; kc < 4; kc++) {
            __half2 h0 = __halves2half2(__float2half_rn(s[2*kc][0]),   __float2half_rn(s[2*kc][1]));
            __half2 h1 = __halves2half2(__float2half_rn(s[2*kc][2]),   __float2half_rn(s[2*kc][3]));
            __half2 h2 = __halves2half2(__float2half_rn(s[2*kc+1][0]), __float2half_rn(s[2*kc+1][1]));
            __half2 h3 = __halves2half2(__float2half_rn(s[2*kc+1][2]), __float2half_rn(s[2*kc+1][3]));
            pa_[kc][0] = *(uint32_t*)&h0; pa_[kc][1] = *(uint32_t*)&h1;
            pa_[kc][2] = *(uint32_t*)&h2; pa_[kc][3] = *(uint32_t*)&h3;
        }
        #pragma unroll
        for (int kc = 0; kc < 4; kc++) {
            #pragma unroll
            for (int nf2 = 0; nf2 < 4; nf2++) {
                uint32_t bb[4];
                int krow = kc * 16 + (lane & 15);
                int ncol = nf2 * 16 + ((lane >> 4) * 8);
                ldmT4(bb, sv + krow * 128 + (((ncol >> 3) ^ (krow & 7)) * 16));
                mmaF16(accO[nf2 * 2],     pa_[kc], bb);
                mmaF16(accO[nf2 * 2 + 1], pa_[kc], bb + 2);
            }
        }
        __syncthreads();
        if (jt + 2 < 6) load_kv(jt & 1, jt + 2);
    }

    float inv0 = 1.f / l0, inv1 = 1.f / l1;
    #pragma unroll
    for (int nf = 0; nf < 8; nf++) {
        int col = nf * 8 + (lane & 3) * 2;
        size_t o0 = ((size_t)(b * Ss + i0 + di0)) * Dd + h * 64 + col;
        size_t o1 = ((size_t)(b * Ss + i0 + di1)) * Dd + h * 64 + col;
        *(__half2*)(outh + o0) =
            __halves2half2(__float2half_rn(accO[nf][0] * inv0), __float2half_rn(accO[nf][1] * inv0));
        *(__half2*)(outh + o1) =
            __halves2half2(__float2half_rn(accO[nf][2] * inv1), __float2half_rn(accO[nf][3] * inv1));
    }
}

// ======================= vectorized conversions ============================
// 4 elements per thread
__global__ void conv_f16v(const float* __restrict__ in, __half* __restrict__ out,
                          int Mreal, int K)
{
    size_t idx = ((size_t)blockIdx.x * 256 + threadIdx.x) * 4;
    int rowi = (int)(idx / K);
    float4 v;
    if (rowi < Mreal) v = *(const float4*)(in + idx);
    else              v = make_float4(0.f, 0.f, 0.f, 0.f);
    __half2* o = (__half2*)(out + idx);
    o[0] = __halves2half2(__float2half_rn(v.x), __float2half_rn(v.y));
    o[1] = __halves2half2(__float2half_rn(v.z), __float2half_rn(v.w));
}

// transpose W[K][N] -> out[N][K] fp16, tile 32(k) x 128(n), vectorized
__device__ __forceinline__ void wt_body(const float* W, __half* O, int K, int N)
{
    __shared__ float t[32][129];
    int k0 = blockIdx.x * 32, n0 = blockIdx.y * 128;
    int tid = threadIdx.x;
    int rowl = tid >> 5;            // 0..7
    int c4   = (tid & 31) * 4;      // 0..124
    #pragma unroll
    for (int i = 0; i < 4; i++) {
        int row = rowl + i * 8;
        float4 v = *(const float4*)(W + (size_t)(k0 + row) * N + n0 + c4);
        t[row][c4] = v.x; t[row][c4 + 1] = v.y; t[row][c4 + 2] = v.z; t[row][c4 + 3] = v.w;
    }
    __syncthreads();
    int a  = tid & 15;              // k half2 index
    int nb = tid >> 4;              // 0..15
    #pragma unroll
    for (int p = 0; p < 8; p++) {
        int nn = nb + p * 16;
        *(__half2*)(O + (size_t)(n0 + nn) * K + k0 + 2 * a) =
            __halves2half2(__float2half_rn(t[2 * a][nn]), __float2half_rn(t[2 * a + 1][nn]));
    }
}

__global__ void wt5_f16(const float* __restrict__ W0, const float* __restrict__ W1,
                        const float* __restrict__ W2, const float* __restrict__ W3,
                        const float* __restrict__ W4,
                        __half* __restrict__ O0, __half* __restrict__ O1,
                        __half* __restrict__ O2, __half* __restrict__ O3,
                        __half* __restrict__ O4)
{
    const float* W; __half* O;
    switch (blockIdx.z) {
        case 0: W = W0; O = O0; break;
        case 1: W = W1; O = O1; break;
        case 2: W = W2; O = O2; break;
        case 3: W = W3; O = O3; break;
        default: W = W4; O = O4; break;
    }
    wt_body(W, O, Dd, Dd);
}

__global__ void wt_f16(const float* __restrict__ W, __half* __restrict__ out,
                       int K, int N)
{
    wt_body(W, out, K, N);
}

// ======================= LayerNorm(a+b) ====================================
template<bool H16OUT>
__global__ void add_ln_kernel(const float* __restrict__ a,
                              const float* __restrict__ bsrc,
                              const float* __restrict__ g,
                              const float* __restrict__ be,
                              float* __restrict__ out,
                              __half* __restrict__ outh)
{
    size_t rowi = blockIdx.x;
    const float* pa = a + rowi * Dd;
    const float* pb = bsrc + rowi * Dd;
    int t = threadIdx.x;

    float x0 = pa[t] + pb[t];
    float x1 = pa[t + 256] + pb[t + 256];
    float x2 = pa[t + 512] + pb[t + 512];

    float s  = x0 + x1 + x2;
    float s2 = x0 * x0 + x1 * x1 + x2 * x2;
    #pragma unroll
    for (int o = 16; o > 0; o >>= 1) {
        s  += __shfl_xor_sync(~0u, s, o);
        s2 += __shfl_xor_sync(~0u, s2, o);
    }
    __shared__ float r1[8], r2s[8];
    if ((t & 31) == 0) { r1[t >> 5] = s; r2s[t >> 5] = s2; }
    __syncthreads();
    if (t < 32) {
        float a1 = (t < 8) ? r1[t] : 0.f;
        float a2 = (t < 8) ? r2s[t] : 0.f;
        #pragma unroll
        for (int o = 4; o > 0; o >>= 1) {
            a1 += __shfl_xor_sync(~0u, a1, o);
            a2 += __shfl_xor_sync(~0u, a2, o);
        }
        if (t == 0) { r1[0] = a1; r2s[0] = a2; }
    }
    __syncthreads();
    float mean = r1[0] * (1.f / 768.f);
    float var  = r2s[0] * (1.f / 768.f) - mean * mean;
    float inv  = rsqrtf(var + 1e-5f);

    float y0 = (x0 - mean) * inv * g[t]       + be[t];
    float y1 = (x1 - mean) * inv * g[t + 256] + be[t + 256];
    float y2 = (x2 - mean) * inv * g[t + 512] + be[t + 512];

    float* po = out + rowi * Dd;
    po[t] = y0; po[t + 256] = y1; po[t + 512] = y2;
    if (H16OUT) {
        __half* ph = outh + rowi * Dd;
        ph[t]       = __float2half_rn(y0);
        ph[t + 256] = __float2half_rn(y1);
        ph[t + 512] = __float2half_rn(y2);
    }
}

// ======================= launch ============================================
extern "C" void kernel_launch(void* const* d_in, const int* in_sizes, int n_in,
                              void* d_out, int out_size)
{
    const float* x    = (const float*)d_in[0];
    const float* pe   = (const float*)d_in[1];
    const float* Wq   = (const float*)d_in[2];
    const float* Wk   = (const float*)d_in[3];
    const float* Wv   = (const float*)d_in[4];
    const float* Wr   = (const float*)d_in[5];
    const float* u    = (const float*)d_in[6];
    const float* v    = (const float*)d_in[7];
    const float* Wo   = (const float*)d_in[8];
    const float* ln1g = (const float*)d_in[9];
    const float* ln1b = (const float*)d_in[10];
    const float* ln2g = (const float*)d_in[11];
    const float* ln2b = (const float*)d_in[12];
    const float* W1   = (const float*)d_in[13];
    const float* b1   = (const float*)d_in[14];
    const float* W2   = (const float*)d_in[15];
    const float* b2   = (const float*)d_in[16];
    float* out = (float*)d_out;

    float *go, *gx1, *gf2;
    __half *gxh, *gpeh, *gqu, *gqv, *gkh, *gvh, *grh, *gattnh, *gx1h, *gffh;
    __half *gwqt, *gwkt, *gwvt, *gwrt, *gwot, *gw1t, *gw2t;
    cudaGetSymbolAddress((void**)&go, g_o);
    cudaGetSymbolAddress((void**)&gx1, g_x1);   cudaGetSymbolAddress((void**)&gf2, g_f2);
    cudaGetSymbolAddress((void**)&gxh, g_xh);   cudaGetSymbolAddress((void**)&gpeh, g_peh);
    cudaGetSymbolAddress((void**)&gqu, g_qu);   cudaGetSymbolAddress((void**)&gqv, g_qv);
    cudaGetSymbolAddress((void**)&gkh, g_kh);   cudaGetSymbolAddress((void**)&gvh, g_vh);
    cudaGetSymbolAddress((void**)&grh, g_rh);
    cudaGetSymbolAddress((void**)&gattnh, g_attnh);
    cudaGetSymbolAddress((void**)&gx1h, g_x1h); cudaGetSymbolAddress((void**)&gffh, g_ffh);
    cudaGetSymbolAddress((void**)&gwqt, g_wqt); cudaGetSymbolAddress((void**)&gwkt, g_wkt);
    cudaGetSymbolAddress((void**)&gwvt, g_wvt); cudaGetSymbolAddress((void**)&gwrt, g_wrt);
    cudaGetSymbolAddress((void**)&gwot, g_wot);
    cudaGetSymbolAddress((void**)&gw1t, g_w1t); cudaGetSymbolAddress((void**)&gw2t, g_w2t);

    cudaFuncSetAttribute(proj_gemm,    cudaFuncAttributeMaxDynamicSharedMemorySize, SMEM_SZ);
    cudaFuncSetAttribute(hmma_gemm<0>, cudaFuncAttributeMaxDynamicSharedMemorySize, SMEM_SZ);
    cudaFuncSetAttribute(hmma_gemm<3>, cudaFuncAttributeMaxDynamicSharedMemorySize, SMEM_SZ);
    cudaFuncSetAttribute(hmma_gemm<4>, cudaFuncAttributeMaxDynamicSharedMemorySize, SMEM_SZ);
    cudaFuncSetAttribute(flash_attn,   cudaFuncAttributeMaxDynamicSharedMemorySize, FA_SMEM);

    // conversions (vectorized)
    conv_f16v<<<(MM * Dd) / 1024, 256>>>(x, gxh, MM, Dd);
    conv_f16v<<<(768 * Dd) / 1024, 256>>>(pe, gpeh, RROWS, Dd);
    wt5_f16<<<dim3(24, 6, 5), 256>>>(Wq, Wk, Wv, Wr, Wo, gwqt, gwkt, gwvt, gwrt, gwot);
    wt_f16<<<dim3(24, 24), 256>>>(W1, gw1t, Dd, FFf);
    wt_f16<<<dim3(96, 6), 256>>>(W2, gw2t, FFf, Dd);

    // batched projections (QKV + r) in one launch
    proj_gemm<<<dim3(6, 48, 4), 256, SMEM_SZ>>>(gxh, gpeh, gwqt, gwkt, gwvt, gwrt,
                                                gqu, gqv, gkh, gvh, grh, u, v);

    // fused attention
    flash_attn<<<dim3(6, Hh, Bb), 128, FA_SMEM>>>(gqu, gqv, gkh, gvh, grh, gattnh);

    hmma_gemm<0><<<dim3(6, 48), 256, SMEM_SZ>>>(gattnh, gwot, go, nullptr, nullptr, MM, Dd, Dd);

    add_ln_kernel<true><<<MM, 256>>>(x, go, ln1g, ln1b, gx1, gx1h);

    // FFN (fp16, fp32 accum)
    hmma_gemm<3><<<dim3(24, 48), 256, SMEM_SZ>>>(gx1h, gw1t, nullptr, gffh, b1, MM, FFf, Dd);
    hmma_gemm<4><<<dim3(6, 48), 256, SMEM_SZ>>>(gffh, gw2t, gf2, nullptr, b2, MM, Dd, FFf);

    add_ln_kernel<false><<<MM, 256>>>(gx1, gf2, ln2g, ln2b, out, nullptr);

    (void)in_sizes; (void)n_in; (void)out_size;
}

// round 17
// speedup vs baseline: 9.8063x; 1.0075x over previous
#include <cuda_runtime.h>
#include <cuda_fp16.h>
#include <cstdint>

#define Bb 16
#define Ss 384
#define Dd 768
#define Hh 12
#define FFf 3072
#define MM (Bb*Ss)          // 6144
#define RROWS (2*Ss-1)      // 767

// ---------------- scratch ----------------
__device__ float g_o [MM*Dd];
__device__ float g_x1[MM*Dd];
__device__ float g_f2[MM*Dd];

__device__ __half g_xh  [(size_t)MM*Dd];
__device__ __half g_peh [(size_t)768*Dd];
__device__ __half g_qu  [(size_t)MM*Dd];
__device__ __half g_qv  [(size_t)MM*Dd];
__device__ __half g_kh  [(size_t)MM*Dd];
__device__ __half g_vh  [(size_t)MM*Dd];
__device__ __half g_rh  [(size_t)768*Dd];
__device__ __half g_attnh[(size_t)MM*Dd];
__device__ __half g_x1h [(size_t)MM*Dd];
__device__ __half g_ffh [(size_t)MM*FFf];
__device__ __half g_wqt [(size_t)Dd*Dd];
__device__ __half g_wkt [(size_t)Dd*Dd];
__device__ __half g_wvt [(size_t)Dd*Dd];
__device__ __half g_wrt [(size_t)Dd*Dd];
__device__ __half g_wot [(size_t)Dd*Dd];
__device__ __half g_w1t [(size_t)FFf*Dd];
__device__ __half g_w2t [(size_t)Dd*FFf];

// ---------------- PTX helpers ----------------
__device__ __forceinline__ uint32_t smem_u32(const void* p) {
    return (uint32_t)__cvta_generic_to_shared(p);
}
__device__ __forceinline__ void cp16(uint32_t dst, const void* src) {
    asm volatile("cp.async.cg.shared.global [%0], [%1], 16;\n"
                 :: "r"(dst), "l"(__cvta_generic_to_global(src)));
}
__device__ __forceinline__ void cp_commit() { asm volatile("cp.async.commit_group;\n" ::: "memory"); }
__device__ __forceinline__ void cp_wait1()  { asm volatile("cp.async.wait_group 1;\n" ::: "memory"); }
__device__ __forceinline__ void cp_wait0()  { asm volatile("cp.async.wait_group 0;\n" ::: "memory"); }

__device__ __forceinline__ void ldmA(uint32_t* a, uint32_t addr) {
    asm volatile("ldmatrix.sync.aligned.m8n8.x4.shared.b16 {%0,%1,%2,%3}, [%4];"
                 : "=r"(a[0]), "=r"(a[1]), "=r"(a[2]), "=r"(a[3]) : "r"(addr));
}
__device__ __forceinline__ void ldmB(uint32_t* b, uint32_t addr) {
    asm volatile("ldmatrix.sync.aligned.m8n8.x2.shared.b16 {%0,%1}, [%2];"
                 : "=r"(b[0]), "=r"(b[1]) : "r"(addr));
}
__device__ __forceinline__ void ldmB4(uint32_t* b, uint32_t addr) {
    asm volatile("ldmatrix.sync.aligned.m8n8.x4.shared.b16 {%0,%1,%2,%3}, [%4];"
                 : "=r"(b[0]), "=r"(b[1]), "=r"(b[2]), "=r"(b[3]) : "r"(addr));
}
__device__ __forceinline__ void ldmT4(uint32_t* b, uint32_t addr) {
    asm volatile("ldmatrix.sync.aligned.m8n8.x4.trans.shared.b16 {%0,%1,%2,%3}, [%4];"
                 : "=r"(b[0]), "=r"(b[1]), "=r"(b[2]), "=r"(b[3]) : "r"(addr));
}
__device__ __forceinline__ void mmaF16(float* d, const uint32_t* a, const uint32_t* b) {
    asm volatile("mma.sync.aligned.m16n8k16.row.col.f32.f16.f16.f32 "
                 "{%0,%1,%2,%3}, {%4,%5,%6,%7}, {%8,%9}, {%0,%1,%2,%3};"
                 : "+f"(d[0]), "+f"(d[1]), "+f"(d[2]), "+f"(d[3])
                 : "r"(a[0]), "r"(a[1]), "r"(a[2]), "r"(a[3]), "r"(b[0]), "r"(b[1]));
}
__device__ __forceinline__ void stsh(uint32_t addr, float v) {
    unsigned short h = __half_as_ushort(__float2half_rn(v));
    asm volatile("st.shared.u16 [%0], %1;" :: "r"(addr), "h"(h));
}
__device__ __forceinline__ float ldsh(uint32_t addr) {
    unsigned short h;
    asm volatile("ld.shared.u16 %0, [%1];" : "=h"(h) : "r"(addr));
    return __half2float(__ushort_as_half(h));
}

#define SMEM_SZ 98304

// ======================= GEMM mainloop: 128 threads, 64x64 warp tiles =======
// C = A(M x K) * Bt(N x K)^T ; acc[4][8][4] per thread (warp tile 64x64).
__device__ __forceinline__ void gemm_core(uint32_t sb, const __half* A, const __half* Bt,
                                          int m0, int n0, int K, int tid, int wid, int lane,
                                          float acc[4][8][4])
{
    int NC = K >> 6;
    int wm = (wid >> 1) * 64;
    int wn = (wid & 1) * 64;
    const int lr = tid >> 3;        // 0..15
    const int lc = tid & 7;

    auto load_stage = [&](int st, int cc) {
        uint32_t sa = sb + st * 32768;
        const __half* pa = A  + (size_t)(m0 + lr) * K + cc * 64 + lc * 8;
        const __half* pb = Bt + (size_t)(n0 + lr) * K + cc * 64 + lc * 8;
        #pragma unroll
        for (int i = 0; i < 8; i++) {
            int row = lr + i * 16;
            uint32_t off = row * 128 + ((lc ^ (row & 7)) * 16);
            cp16(sa + off,         pa);
            cp16(sa + 16384 + off, pb);
            pa += (size_t)16 * K;
            pb += (size_t)16 * K;
        }
        cp_commit();
    };

    load_stage(0, 0);
    load_stage(1, 1);

    for (int cc = 0; cc < NC; cc++) {
        if (cc + 2 < NC) cp_wait1(); else cp_wait0();
        __syncthreads();
        if (cc + 2 < NC) load_stage((cc + 2) % 3, cc + 2);

        uint32_t sa  = sb + (cc % 3) * 32768;
        uint32_t sbb = sa + 16384;
        #pragma unroll
        for (int k16 = 0; k16 < 4; k16++) {
            uint32_t a[4][4], b[4][4];
            #pragma unroll
            for (int mt = 0; mt < 4; mt++) {
                int r  = wm + mt * 16 + (lane & 15);
                int kc = 2 * k16 + ((lane >> 4) & 1);
                ldmA(a[mt], sa + r * 128 + ((kc ^ (r & 7)) * 16));
            }
            #pragma unroll
            for (int nt2 = 0; nt2 < 4; nt2++) {
                // x4: lanes 0-7 (n8a,kc0), 8-15 (n8a,kc1), 16-23 (n8b,kc0), 24-31 (n8b,kc1)
                int g  = lane >> 3;
                int r  = wn + nt2 * 16 + ((g >> 1) * 8) + (lane & 7);
                int kc = 2 * k16 + (g & 1);
                ldmB4(b[nt2], sbb + r * 128 + ((kc ^ (r & 7)) * 16));
            }
            #pragma unroll
            for (int mt = 0; mt < 4; mt++)
                #pragma unroll
                for (int nt2 = 0; nt2 < 4; nt2++) {
                    mmaF16(acc[mt][2 * nt2],     a[mt], b[nt2]);
                    mmaF16(acc[mt][2 * nt2 + 1], a[mt], b[nt2] + 2);
                }
        }
    }
    __syncthreads();
}

__device__ __forceinline__ void acc_to_tile(char* smem, int wid, int lane, float acc[4][8][4])
{
    float* tile = (float*)smem;
    int wm = (wid >> 1) * 64;
    int wn = (wid & 1) * 64;
    #pragma unroll
    for (int mt = 0; mt < 4; mt++) {
        #pragma unroll
        for (int nt = 0; nt < 8; nt++) {
            int r0  = wm + mt * 16 + (lane >> 2);
            int col = wn + nt * 8 + (lane & 3) * 2;
            tile[r0 * 132 + col]           = acc[mt][nt][0];
            tile[r0 * 132 + col + 1]       = acc[mt][nt][1];
            tile[(r0 + 8) * 132 + col]     = acc[mt][nt][2];
            tile[(r0 + 8) * 132 + col + 1] = acc[mt][nt][3];
        }
    }
    __syncthreads();
}

// ======================= batched projection GEMM ============================
// z=0: xh@Wq -> qu=h((c+u)/8), qv=h((c+v)/8);  z=1: xh@Wk -> kh;
// z=2: xh@Wv -> vh;  z=3: peh@Wr -> rh (M=767)
__global__ void __launch_bounds__(128)
proj_gemm(const __half* __restrict__ xh, const __half* __restrict__ peh,
          const __half* __restrict__ wq, const __half* __restrict__ wk,
          const __half* __restrict__ wv, const __half* __restrict__ wr,
          __half* __restrict__ qu, __half* __restrict__ qv,
          __half* __restrict__ kh, __half* __restrict__ vh,
          __half* __restrict__ rh,
          const float* __restrict__ ub, const float* __restrict__ vb)
{
    extern __shared__ __align__(1024) char smem[];
    int z = blockIdx.z;
    int m0 = blockIdx.y * 128, n0 = blockIdx.x * 128;
    int Mreal = (z == 3) ? RROWS : MM;
    if (m0 >= Mreal) return;

    const __half* A  = (z == 3) ? peh : xh;
    const __half* Bt = (z == 0) ? wq : (z == 1) ? wk : (z == 2) ? wv : wr;

    uint32_t sb = smem_u32(smem);
    int tid = threadIdx.x;
    int wid = tid >> 5, lane = tid & 31;

    float acc[4][8][4];
    #pragma unroll
    for (int mt = 0; mt < 4; mt++)
        #pragma unroll
        for (int nt = 0; nt < 8; nt++)
            #pragma unroll
            for (int q = 0; q < 4; q++) acc[mt][nt][q] = 0.f;

    gemm_core(sb, A, Bt, m0, n0, Dd, tid, wid, lane, acc);
    acc_to_tile(smem, wid, lane, acc);

    float* tile = (float*)smem;
    #pragma unroll
    for (int j = 0; j < 32; j++) {
        int idx = tid + j * 128;
        int rr = idx >> 5, c4 = idx & 31;
        float4 v = *(const float4*)(tile + rr * 132 + c4 * 4);
        int grow = m0 + rr;
        int gcol = n0 + c4 * 4;
        if (grow >= Mreal) continue;
        if (z == 0) {
            float u0 = ub[gcol], u1 = ub[gcol + 1], u2 = ub[gcol + 2], u3 = ub[gcol + 3];
            float w0 = vb[gcol], w1 = vb[gcol + 1], w2 = vb[gcol + 2], w3 = vb[gcol + 3];
            __half2* pu = (__half2*)(qu + (size_t)grow * Dd + gcol);
            __half2* pv = (__half2*)(qv + (size_t)grow * Dd + gcol);
            pu[0] = __halves2half2(__float2half_rn((v.x + u0) * 0.125f), __float2half_rn((v.y + u1) * 0.125f));
            pu[1] = __halves2half2(__float2half_rn((v.z + u2) * 0.125f), __float2half_rn((v.w + u3) * 0.125f));
            pv[0] = __halves2half2(__float2half_rn((v.x + w0) * 0.125f), __float2half_rn((v.y + w1) * 0.125f));
            pv[1] = __halves2half2(__float2half_rn((v.z + w2) * 0.125f), __float2half_rn((v.w + w3) * 0.125f));
        } else {
            __half* dst = (z == 1) ? kh : (z == 2) ? vh : rh;
            __half2* p = (__half2*)(dst + (size_t)grow * Dd + gcol);
            p[0] = __halves2half2(__float2half_rn(v.x), __float2half_rn(v.y));
            p[1] = __halves2half2(__float2half_rn(v.z), __float2half_rn(v.w));
        }
    }
}

// ======================= fp16 HMMA GEMM (Wo / FFN) ==========================
// EPI 0: fp32 C    EPI 3: bias+relu -> half Cb    EPI 4: bias -> fp32 C
template<int EPI>
__global__ void __launch_bounds__(128)
hmma_gemm(const __half* __restrict__ A,
          const __half* __restrict__ Bt,
          float* __restrict__ C,
          __half* __restrict__ Cb,
          const float* __restrict__ bias,
          int Mreal, int N, int K)
{
    extern __shared__ __align__(1024) char smem[];
    uint32_t sb = smem_u32(smem);
    int tid = threadIdx.x;
    int wid = tid >> 5, lane = tid & 31;
    int n0 = blockIdx.x * 128, m0 = blockIdx.y * 128;

    float acc[4][8][4];
    #pragma unroll
    for (int mt = 0; mt < 4; mt++)
        #pragma unroll
        for (int nt = 0; nt < 8; nt++)
            #pragma unroll
            for (int q = 0; q < 4; q++) acc[mt][nt][q] = 0.f;

    gemm_core(sb, A, Bt, m0, n0, K, tid, wid, lane, acc);
    acc_to_tile(smem, wid, lane, acc);

    float* tile = (float*)smem;
    #pragma unroll
    for (int j = 0; j < 32; j++) {
        int idx = tid + j * 128;
        int rr = idx >> 5, c4 = idx & 31;
        float4 v = *(const float4*)(tile + rr * 132 + c4 * 4);
        int grow = m0 + rr;
        int gcol = n0 + c4 * 4;
        if (grow >= Mreal) continue;
        if (EPI == 0) {
            *(float4*)(C + (size_t)grow * N + gcol) = v;
        } else if (EPI == 3) {
            v.x = fmaxf(v.x + bias[gcol], 0.f);     v.y = fmaxf(v.y + bias[gcol + 1], 0.f);
            v.z = fmaxf(v.z + bias[gcol + 2], 0.f); v.w = fmaxf(v.w + bias[gcol + 3], 0.f);
            __half2* p = (__half2*)(Cb + (size_t)grow * N + gcol);
            p[0] = __halves2half2(__float2half_rn(v.x), __float2half_rn(v.y));
            p[1] = __halves2half2(__float2half_rn(v.z), __float2half_rn(v.w));
        } else {
            v.x += bias[gcol]; v.y += bias[gcol + 1];
            v.z += bias[gcol + 2]; v.w += bias[gcol + 3];
            *(float4*)(C + (size_t)grow * N + gcol) = v;
        }
    }
}

// ======================= fused flash attention ==============================
#define FA_BAND 0
#define FA_QU   57344
#define FA_QV   65536
#define FA_KV   73728
#define FA_SMEM 106496

__global__ void __launch_bounds__(128)
flash_attn(const __half* __restrict__ qu,
           const __half* __restrict__ qv,
           const __half* __restrict__ kh,
           const __half* __restrict__ vh,
           const __half* __restrict__ rh,
           __half* __restrict__ outh)
{
    extern __shared__ __align__(1024) char smem[];
    uint32_t sb = smem_u32(smem);
    int tid = threadIdx.x;
    int wid = tid >> 5, lane = tid & 31;
    int i0 = blockIdx.x * 64;
    int h = blockIdx.y, b = blockIdx.z;
    int wm = wid * 16;

    auto load_kv = [&](int st, int jt) {
        uint32_t sk = sb + FA_KV + st * 16384;
        #pragma unroll
        for (int t4 = 0; t4 < 4; t4++) {
            int idx = tid * 4 + t4;
            int row = idx >> 3, lc = idx & 7;
            uint32_t off = row * 128 + ((lc ^ (row & 7)) * 16);
            size_t g = ((size_t)(b * Ss + jt * 64 + row)) * Dd + h * 64 + lc * 8;
            cp16(sk + off,        kh + g);
            cp16(sk + 8192 + off, vh + g);
        }
        cp_commit();
    };
    load_kv(0, 0);
    load_kv(1, 1);
    {
        for (int idx = tid; idx < 3576; idx += 128) {
            int row = idx >> 3, lc = idx & 7;
            uint32_t off = row * 128 + ((lc ^ (row & 7)) * 16);
            cp16(sb + FA_BAND + off, rh + (size_t)(i0 + row) * Dd + h * 64 + lc * 8);
        }
        #pragma unroll
        for (int t4 = 0; t4 < 4; t4++) {
            int idx = tid * 4 + t4;
            int row = idx >> 3, lc = idx & 7;
            uint32_t off = row * 128 + ((lc ^ (row & 7)) * 16);
            size_t g = ((size_t)(b * Ss + i0 + row)) * Dd + h * 64 + lc * 8;
            cp16(sb + FA_QU + off, qu + g);
            cp16(sb + FA_QV + off, qv + g);
        }
        cp_commit();
    }
    cp_wait0();
    __syncthreads();

    uint32_t qa[4][4], va[4][4];
    #pragma unroll
    for (int k16 = 0; k16 < 4; k16++) {
        int rA = wm + (lane & 15);
        int kcA = 2 * k16 + ((lane >> 4) & 1);
        ldmA(qa[k16], sb + FA_QU + rA * 128 + ((kcA ^ (rA & 7)) * 16));
        ldmA(va[k16], sb + FA_QV + rA * 128 + ((kcA ^ (rA & 7)) * 16));
    }

    for (int c = 0; c < 7; c++) {
        float tacc[8][4];
        #pragma unroll
        for (int nt = 0; nt < 8; nt++)
            #pragma unroll
            for (int q = 0; q < 4; q++) tacc[nt][q] = 0.f;
        #pragma unroll
        for (int k16 = 0; k16 < 4; k16++) {
            #pragma unroll
            for (int nt = 0; nt < 8; nt++) {
                uint32_t b2[2];
                int r  = c * 64 + nt * 8 + (lane & 7);
                int kc = 2 * k16 + ((lane >> 3) & 1);
                ldmB(b2, sb + FA_BAND + r * 128 + ((kc ^ (r & 7)) * 16));
                mmaF16(tacc[nt], va[k16], b2);
            }
        }
        __syncthreads();
        int di0 = wm + (lane >> 2);
        int di1 = di0 + 8;
        #pragma unroll
        for (int nt = 0; nt < 8; nt++) {
            int tc = c * 64 + nt * 8 + (lane & 3) * 2;
            stsh(sb + FA_BAND + tc * 128       + (((di0 >> 3) ^ (tc & 7)) * 16)       + (di0 & 7) * 2, tacc[nt][0]);
            stsh(sb + FA_BAND + (tc + 1) * 128 + (((di0 >> 3) ^ ((tc + 1) & 7)) * 16) + (di0 & 7) * 2, tacc[nt][1]);
            stsh(sb + FA_BAND + tc * 128       + (((di1 >> 3) ^ (tc & 7)) * 16)       + (di1 & 7) * 2, tacc[nt][2]);
            stsh(sb + FA_BAND + (tc + 1) * 128 + (((di1 >> 3) ^ ((tc + 1) & 7)) * 16) + (di1 & 7) * 2, tacc[nt][3]);
        }
        __syncthreads();
    }

    float m0 = -1e30f, m1 = -1e30f, l0 = 0.f, l1 = 0.f;
    float accO[8][4];
    #pragma unroll
    for (int nf = 0; nf < 8; nf++)
        #pragma unroll
        for (int q = 0; q < 4; q++) accO[nf][q] = 0.f;

    int di0 = wm + (lane >> 2);
    int di1 = di0 + 8;

    for (int jt = 0; jt < 6; jt++) {
        if (jt > 0) {
            if (jt < 5) cp_wait1(); else cp_wait0();
            __syncthreads();
        }
        uint32_t sk = sb + FA_KV + (jt & 1) * 16384;
        uint32_t sv = sk + 8192;

        float s[8][4];
        #pragma unroll
        for (int nt = 0; nt < 8; nt++)
            #pragma unroll
            for (int q = 0; q < 4; q++) s[nt][q] = 0.f;
        #pragma unroll
        for (int k16 = 0; k16 < 4; k16++) {
            #pragma unroll
            for (int nt = 0; nt < 8; nt++) {
                uint32_t b2[2];
                int r  = nt * 8 + (lane & 7);
                int kc = 2 * k16 + ((lane >> 3) & 1);
                ldmB(b2, sk + r * 128 + ((kc ^ (r & 7)) * 16));
                mmaF16(s[nt], qa[k16], b2);
            }
        }
        #pragma unroll
        for (int nt = 0; nt < 8; nt++) {
            int dj = jt * 64 + nt * 8 + (lane & 3) * 2;
            int t0 = di0 - dj + 383;
            int t1 = t0 + 8;
            s[nt][0] += ldsh(sb + FA_BAND + t0 * 128       + (((di0 >> 3) ^ (t0 & 7)) * 16)       + (di0 & 7) * 2);
            s[nt][1] += ldsh(sb + FA_BAND + (t0 - 1) * 128 + (((di0 >> 3) ^ ((t0 - 1) & 7)) * 16) + (di0 & 7) * 2);
            s[nt][2] += ldsh(sb + FA_BAND + t1 * 128       + (((di1 >> 3) ^ (t1 & 7)) * 16)       + (di1 & 7) * 2);
            s[nt][3] += ldsh(sb + FA_BAND + (t1 - 1) * 128 + (((di1 >> 3) ^ ((t1 - 1) & 7)) * 16) + (di1 & 7) * 2);
        }

        float mx0 = -1e30f, mx1 = -1e30f;
        #pragma unroll
        for (int nt = 0; nt < 8; nt++) {
            mx0 = fmaxf(mx0, fmaxf(s[nt][0], s[nt][1]));
            mx1 = fmaxf(mx1, fmaxf(s[nt][2], s[nt][3]));
        }
        mx0 = fmaxf(mx0, __shfl_xor_sync(~0u, mx0, 1));
        mx0 = fmaxf(mx0, __shfl_xor_sync(~0u, mx0, 2));
        mx1 = fmaxf(mx1, __shfl_xor_sync(~0u, mx1, 1));
        mx1 = fmaxf(mx1, __shfl_xor_sync(~0u, mx1, 2));
        float m0n = fmaxf(m0, mx0), m1n = fmaxf(m1, mx1);
        float c0 = __expf(m0 - m0n), c1 = __expf(m1 - m1n);
        m0 = m0n; m1 = m1n;

        float rs0 = 0.f, rs1 = 0.f;
        #pragma unroll
        for (int nt = 0; nt < 8; nt++) {
            s[nt][0] = __expf(s[nt][0] - m0); s[nt][1] = __expf(s[nt][1] - m0);
            s[nt][2] = __expf(s[nt][2] - m1); s[nt][3] = __expf(s[nt][3] - m1);
            rs0 += s[nt][0] + s[nt][1];
            rs1 += s[nt][2] + s[nt][3];
        }
        rs0 += __shfl_xor_sync(~0u, rs0, 1); rs0 += __shfl_xor_sync(~0u, rs0, 2);
        rs1 += __shfl_xor_sync(~0u, rs1, 1); rs1 += __shfl_xor_sync(~0u, rs1, 2);
        l0 = l0 * c0 + rs0;
        l1 = l1 * c1 + rs1;
        #pragma unroll
        for (int nf = 0; nf < 8; nf++) {
            accO[nf][0] *= c0; accO[nf][1] *= c0;
            accO[nf][2] *= c1; accO[nf][3] *= c1;
        }

        uint32_t pa_[4][4];
        #pragma unroll
        for (int kc = 0; kc < 4; kc++) {
            __half2 h0 = __halves2half2(__float2half_rn(s[2*kc][0]),   __float2half_rn(s[2*kc][1]));
            __half2 h1 = __halves2half2(__float2half_rn(s[2*kc][2]),   __float2half_rn(s[2*kc][3]));
            __half2 h2 = __halves2half2(__float2half_rn(s[2*kc+1][0]), __float2half_rn(s[2*kc+1][1]));
            __half2 h3 = __halves2half2(__float2half_rn(s[2*kc+1][2]), __float2half_rn(s[2*kc+1][3]));
            pa_[kc][0] = *(uint32_t*)&h0; pa_[kc][1] = *(uint32_t*)&h1;
            pa_[kc][2] = *(uint32_t*)&h2; pa_[kc][3] = *(uint32_t*)&h3;
        }
        #pragma unroll
        for (int kc = 0; kc < 4; kc++) {
            #pragma unroll
            for (int nf2 = 0; nf2 < 4; nf2++) {
                uint32_t bb[4];
                int krow = kc * 16 + (lane & 15);
                int ncol = nf2 * 16 + ((lane >> 4) * 8);
                ldmT4(bb, sv + krow * 128 + (((ncol >> 3) ^ (krow & 7)) * 16));
                mmaF16(accO[nf2 * 2],     pa_[kc], bb);
                mmaF16(accO[nf2 * 2 + 1], pa_[kc], bb + 2);
            }
        }
        __syncthreads();
        if (jt + 2 < 6) load_kv(jt & 1, jt + 2);
    }

    float inv0 = 1.f / l0, inv1 = 1.f / l1;
    #pragma unroll
    for (int nf = 0; nf < 8; nf++) {
        int col = nf * 8 + (lane & 3) * 2;
        size_t o0 = ((size_t)(b * Ss + i0 + di0)) * Dd + h * 64 + col;
        size_t o1 = ((size_t)(b * Ss + i0 + di1)) * Dd + h * 64 + col;
        *(__half2*)(outh + o0) =
            __halves2half2(__float2half_rn(accO[nf][0] * inv0), __float2half_rn(accO[nf][1] * inv0));
        *(__half2*)(outh + o1) =
            __halves2half2(__float2half_rn(accO[nf][2] * inv1), __float2half_rn(accO[nf][3] * inv1));
    }
}

// ======================= vectorized conversions ============================
__global__ void conv_f16v(const float* __restrict__ in, __half* __restrict__ out,
                          int Mreal, int K)
{
    size_t idx = ((size_t)blockIdx.x * 256 + threadIdx.x) * 4;
    int rowi = (int)(idx / K);
    float4 v;
    if (rowi < Mreal) v = *(const float4*)(in + idx);
    else              v = make_float4(0.f, 0.f, 0.f, 0.f);
    __half2* o = (__half2*)(out + idx);
    o[0] = __halves2half2(__float2half_rn(v.x), __float2half_rn(v.y));
    o[1] = __halves2half2(__float2half_rn(v.z), __float2half_rn(v.w));
}

__device__ __forceinline__ void wt_body(const float* W, __half* O, int K, int N)
{
    __shared__ float t[32][129];
    int k0 = blockIdx.x * 32, n0 = blockIdx.y * 128;
    int tid = threadIdx.x;
    int rowl = tid >> 5;
    int c4   = (tid & 31) * 4;
    #pragma unroll
    for (int i = 0; i < 4; i++) {
        int row = rowl + i * 8;
        float4 v = *(const float4*)(W + (size_t)(k0 + row) * N + n0 + c4);
        t[row][c4] = v.x; t[row][c4 + 1] = v.y; t[row][c4 + 2] = v.z; t[row][c4 + 3] = v.w;
    }
    __syncthreads();
    int a  = tid & 15;
    int nb = tid >> 4;
    #pragma unroll
    for (int p = 0; p < 8; p++) {
        int nn = nb + p * 16;
        *(__half2*)(O + (size_t)(n0 + nn) * K + k0 + 2 * a) =
            __halves2half2(__float2half_rn(t[2 * a][nn]), __float2half_rn(t[2 * a + 1][nn]));
    }
}

__global__ void wt5_f16(const float* __restrict__ W0, const float* __restrict__ W1,
                        const float* __restrict__ W2, const float* __restrict__ W3,
                        const float* __restrict__ W4,
                        __half* __restrict__ O0, __half* __restrict__ O1,
                        __half* __restrict__ O2, __half* __restrict__ O3,
                        __half* __restrict__ O4)
{
    const float* W; __half* O;
    switch (blockIdx.z) {
        case 0: W = W0; O = O0; break;
        case 1: W = W1; O = O1; break;
        case 2: W = W2; O = O2; break;
        case 3: W = W3; O = O3; break;
        default: W = W4; O = O4; break;
    }
    wt_body(W, O, Dd, Dd);
}

__global__ void wt_f16(const float* __restrict__ W, __half* __restrict__ out,
                       int K, int N)
{
    wt_body(W, out, K, N);
}

// ======================= LayerNorm(a+b) ====================================
template<bool H16OUT>
__global__ void add_ln_kernel(const float* __restrict__ a,
                              const float* __restrict__ bsrc,
                              const float* __restrict__ g,
                              const float* __restrict__ be,
                              float* __restrict__ out,
                              __half* __restrict__ outh)
{
    size_t rowi = blockIdx.x;
    const float* pa = a + rowi * Dd;
    const float* pb = bsrc + rowi * Dd;
    int t = threadIdx.x;

    float x0 = pa[t] + pb[t];
    float x1 = pa[t + 256] + pb[t + 256];
    float x2 = pa[t + 512] + pb[t + 512];

    float s  = x0 + x1 + x2;
    float s2 = x0 * x0 + x1 * x1 + x2 * x2;
    #pragma unroll
    for (int o = 16; o > 0; o >>= 1) {
        s  += __shfl_xor_sync(~0u, s, o);
        s2 += __shfl_xor_sync(~0u, s2, o);
    }
    __shared__ float r1[8], r2s[8];
    if ((t & 31) == 0) { r1[t >> 5] = s; r2s[t >> 5] = s2; }
    __syncthreads();
    if (t < 32) {
        float a1 = (t < 8) ? r1[t] : 0.f;
        float a2 = (t < 8) ? r2s[t] : 0.f;
        #pragma unroll
        for (int o = 4; o > 0; o >>= 1) {
            a1 += __shfl_xor_sync(~0u, a1, o);
            a2 += __shfl_xor_sync(~0u, a2, o);
        }
        if (t == 0) { r1[0] = a1; r2s[0] = a2; }
    }
    __syncthreads();
    float mean = r1[0] * (1.f / 768.f);
    float var  = r2s[0] * (1.f / 768.f) - mean * mean;
    float inv  = rsqrtf(var + 1e-5f);

    float y0 = (x0 - mean) * inv * g[t]       + be[t];
    float y1 = (x1 - mean) * inv * g[t + 256] + be[t + 256];
    float y2 = (x2 - mean) * inv * g[t + 512] + be[t + 512];

    float* po = out + rowi * Dd;
    po[t] = y0; po[t + 256] = y1; po[t + 512] = y2;
    if (H16OUT) {
        __half* ph = outh + rowi * Dd;
        ph[t]       = __float2half_rn(y0);
        ph[t + 256] = __float2half_rn(y1);
        ph[t + 512] = __float2half_rn(y2);
    }
}

// ======================= launch ============================================
extern "C" void kernel_launch(void* const* d_in, const int* in_sizes, int n_in,
                              void* d_out, int out_size)
{
    const float* x    = (const float*)d_in[0];
    const float* pe   = (const float*)d_in[1];
    const float* Wq   = (const float*)d_in[2];
    const float* Wk   = (const float*)d_in[3];
    const float* Wv   = (const float*)d_in[4];
    const float* Wr   = (const float*)d_in[5];
    const float* u    = (const float*)d_in[6];
    const float* v    = (const float*)d_in[7];
    const float* Wo   = (const float*)d_in[8];
    const float* ln1g = (const float*)d_in[9];
    const float* ln1b = (const float*)d_in[10];
    const float* ln2g = (const float*)d_in[11];
    const float* ln2b = (const float*)d_in[12];
    const float* W1   = (const float*)d_in[13];
    const float* b1   = (const float*)d_in[14];
    const float* W2   = (const float*)d_in[15];
    const float* b2   = (const float*)d_in[16];
    float* out = (float*)d_out;

    float *go, *gx1, *gf2;
    __half *gxh, *gpeh, *gqu, *gqv, *gkh, *gvh, *grh, *gattnh, *gx1h, *gffh;
    __half *gwqt, *gwkt, *gwvt, *gwrt, *gwot, *gw1t, *gw2t;
    cudaGetSymbolAddress((void**)&go, g_o);
    cudaGetSymbolAddress((void**)&gx1, g_x1);   cudaGetSymbolAddress((void**)&gf2, g_f2);
    cudaGetSymbolAddress((void**)&gxh, g_xh);   cudaGetSymbolAddress((void**)&gpeh, g_peh);
    cudaGetSymbolAddress((void**)&gqu, g_qu);   cudaGetSymbolAddress((void**)&gqv, g_qv);
    cudaGetSymbolAddress((void**)&gkh, g_kh);   cudaGetSymbolAddress((void**)&gvh, g_vh);
    cudaGetSymbolAddress((void**)&grh, g_rh);
    cudaGetSymbolAddress((void**)&gattnh, g_attnh);
    cudaGetSymbolAddress((void**)&gx1h, g_x1h); cudaGetSymbolAddress((void**)&gffh, g_ffh);
    cudaGetSymbolAddress((void**)&gwqt, g_wqt); cudaGetSymbolAddress((void**)&gwkt, g_wkt);
    cudaGetSymbolAddress((void**)&gwvt, g_wvt); cudaGetSymbolAddress((void**)&gwrt, g_wrt);
    cudaGetSymbolAddress((void**)&gwot, g_wot);
    cudaGetSymbolAddress((void**)&gw1t, g_w1t); cudaGetSymbolAddress((void**)&gw2t, g_w2t);

    cudaFuncSetAttribute(proj_gemm,    cudaFuncAttributeMaxDynamicSharedMemorySize, SMEM_SZ);
    cudaFuncSetAttribute(hmma_gemm<0>, cudaFuncAttributeMaxDynamicSharedMemorySize, SMEM_SZ);
    cudaFuncSetAttribute(hmma_gemm<3>, cudaFuncAttributeMaxDynamicSharedMemorySize, SMEM_SZ);
    cudaFuncSetAttribute(hmma_gemm<4>, cudaFuncAttributeMaxDynamicSharedMemorySize, SMEM_SZ);
    cudaFuncSetAttribute(flash_attn,   cudaFuncAttributeMaxDynamicSharedMemorySize, FA_SMEM);

    // conversions (vectorized)
    conv_f16v<<<(MM * Dd) / 1024, 256>>>(x, gxh, MM, Dd);
    conv_f16v<<<(768 * Dd) / 1024, 256>>>(pe, gpeh, RROWS, Dd);
    wt5_f16<<<dim3(24, 6, 5), 256>>>(Wq, Wk, Wv, Wr, Wo, gwqt, gwkt, gwvt, gwrt, gwot);
    wt_f16<<<dim3(24, 24), 256>>>(W1, gw1t, Dd, FFf);
    wt_f16<<<dim3(96, 6), 256>>>(W2, gw2t, FFf, Dd);

    // batched projections (QKV + r) in one launch
    proj_gemm<<<dim3(6, 48, 4), 128, SMEM_SZ>>>(gxh, gpeh, gwqt, gwkt, gwvt, gwrt,
                                                gqu, gqv, gkh, gvh, grh, u, v);

    // fused attention
    flash_attn<<<dim3(6, Hh, Bb), 128, FA_SMEM>>>(gqu, gqv, gkh, gvh, grh, gattnh);

    hmma_gemm<0><<<dim3(6, 48), 128, SMEM_SZ>>>(gattnh, gwot, go, nullptr, nullptr, MM, Dd, Dd);

    add_ln_kernel<true><<<MM, 256>>>(x, go, ln1g, ln1b, gx1, gx1h);

    // FFN (fp16, fp32 accum)
    hmma_gemm<3><<<dim3(24, 48), 128, SMEM_SZ>>>(gx1h, gw1t, nullptr, gffh, b1, MM, FFf, Dd);
    hmma_gemm<4><<<dim3(6, 48), 128, SMEM_SZ>>>(gffh, gw2t, gf2, nullptr, b2, MM, Dd, FFf);

    add_ln_kernel<false><<<MM, 256>>>(gx1, gf2, ln2g, ln2b, out, nullptr);

    (void)in_sizes; (void)n_in; (void)out_size;
}